// round 1
// baseline (speedup 1.0000x reference)
#include <cuda_runtime.h>
#include <math.h>

// ---------------- problem constants ----------------
#define LSEQ   128
#define BATCH  8
#define CH     8
#define HID    256
#define NHEAD  8
#define DHEAD  32
#define FFD    1024
#define MAXPADC 15
#define NSEQ   1024          // BATCH * LSEQ

// ---------------- scratch (allocation-free) ----------------
__device__ float g_win[139264];                 // max B*E*pl*C
__device__ float g_tokens[278528];              // max B*E*H
__device__ float g_seq[1024 * 34 * 256];        // 8,912,896
__device__ float g_s2 [1024 * 34 * 256];        // 8,912,896
__device__ float g_ff [1024 * 34 * 1024];       // 35,651,584  (also aliases q/k/v)
__device__ float g_comb[1024 * 512];

static const int SEQBUF = 1024 * 34 * 256;

// ---------------- helpers ----------------
__device__ __forceinline__ float gelu_exact(float x) {
    return 0.5f * x * (1.0f + erff(x * 0.7071067811865476f));
}

// ---------------- window gather (x left-padded by 15 zeros) ----------------
__global__ void win_kernel(const float* __restrict__ x, float* __restrict__ win,
                           int E, int pl) {
    int plc = pl * CH;
    int tot = BATCH * E * plc;
    int idx = blockIdx.x * blockDim.x + threadIdx.x;
    if (idx >= tot) return;
    int r = idx % plc;
    int e = (idx / plc) % E;
    int b = idx / (plc * E);
    int p = r >> 3, c = r & 7;
    int i = e + p;  // index into padded length
    win[idx] = (i < MAXPADC) ? 0.0f : x[(b * LSEQ + (i - MAXPADC)) * CH + c];
}

// ---------------- seq build: tokens[j(t,k)] + pos[k] ----------------
__global__ void build_seq_kernel(const float* __restrict__ tokens,
                                 const float* __restrict__ pos,
                                 float* __restrict__ seq,
                                 int NMAX, int E, int pl, int st) {
    int tot = NSEQ * NMAX * HID;
    int idx = blockIdx.x * blockDim.x + threadIdx.x;
    if (idx >= tot) return;
    int h = idx & 255;
    int rest = idx >> 8;
    int k = rest % NMAX;
    int bt = rest / NMAX;
    int t = bt & (LSEQ - 1);
    int b = bt >> 7;
    int n = (t + MAXPADC - (pl - 1)) / st + 1;
    int ends = t + MAXPADC - (n - 1) * st + k * st;
    int j = ends - (pl - 1);
    j = j < 0 ? 0 : (j > E - 1 ? E - 1 : j);
    seq[idx] = tokens[(b * E + j) * HID + h] + pos[k * HID + h];
}

// ---------------- gather last valid patch into concat buffer ----------------
__global__ void gather_kernel(const float* __restrict__ seq, float* __restrict__ comb,
                              int NMAX, int pl, int st, int off) {
    int idx = blockIdx.x * blockDim.x + threadIdx.x;
    if (idx >= NSEQ * HID) return;
    int h = idx & 255;
    int bt = idx >> 8;
    int t = bt & (LSEQ - 1);
    int n = (t + MAXPADC - (pl - 1)) / st + 1;
    comb[bt * 512 + off + h] = seq[(bt * NMAX + (n - 1)) * HID + h];
}

// ---------------- layernorm over H=256 (one block per row, two-pass) ----------------
__global__ void ln_kernel(const float* __restrict__ in, const float* __restrict__ g,
                          const float* __restrict__ b, float* __restrict__ out) {
    __shared__ float red[256];
    int row = blockIdx.x, h = threadIdx.x;
    float v = in[row * 256 + h];
    red[h] = v; __syncthreads();
    #pragma unroll
    for (int s = 128; s > 0; s >>= 1) { if (h < s) red[h] += red[h + s]; __syncthreads(); }
    float mu = red[0] * (1.0f / 256.0f);
    __syncthreads();
    float d = v - mu;
    red[h] = d * d; __syncthreads();
    #pragma unroll
    for (int s = 128; s > 0; s >>= 1) { if (h < s) red[h] += red[h + s]; __syncthreads(); }
    float var = red[0] * (1.0f / 256.0f);
    out[row * 256 + h] = d * rsqrtf(var + 1e-5f) * g[h] + b[h];
}

// ---------------- tiled SGEMM: C[M,N] = A[M,K] @ W[K,N] (+bias, epilogue) ----------------
// EPI: 0 = bias store, 1 = bias+gelu store, 2 = bias + accumulate into C (residual)
// Requires: M%64==0, N%64==0, K%16==0 (holds for every call here).
template<int EPI>
__global__ void gemm_kernel(const float* __restrict__ A, const float* __restrict__ W,
                            const float* __restrict__ bias, float* __restrict__ C,
                            int M, int N, int K) {
    __shared__ float As[16][64];
    __shared__ float Bs[16][64];
    int tid = threadIdx.x;
    int bm = blockIdx.y * 64, bn = blockIdx.x * 64;
    int ty = tid >> 4, tx = tid & 15;

    int arow  = tid >> 2;
    int acol4 = (tid & 3) << 2;
    int brow  = tid >> 4;
    int bcol4 = (tid & 15) << 2;

    float acc[4][4];
    #pragma unroll
    for (int i = 0; i < 4; i++)
        #pragma unroll
        for (int j = 0; j < 4; j++) acc[i][j] = 0.0f;

    for (int k0 = 0; k0 < K; k0 += 16) {
        float4 av = *(const float4*)(A + (size_t)(bm + arow) * K + k0 + acol4);
        As[acol4 + 0][arow] = av.x;
        As[acol4 + 1][arow] = av.y;
        As[acol4 + 2][arow] = av.z;
        As[acol4 + 3][arow] = av.w;
        float4 bv = *(const float4*)(W + (size_t)(k0 + brow) * N + bn + bcol4);
        *(float4*)&Bs[brow][bcol4] = bv;
        __syncthreads();
        #pragma unroll
        for (int kk = 0; kk < 16; kk++) {
            float ar[4], br[4];
            #pragma unroll
            for (int i = 0; i < 4; i++) ar[i] = As[kk][ty * 4 + i];
            #pragma unroll
            for (int j = 0; j < 4; j++) br[j] = Bs[kk][tx * 4 + j];
            #pragma unroll
            for (int i = 0; i < 4; i++)
                #pragma unroll
                for (int j = 0; j < 4; j++) acc[i][j] += ar[i] * br[j];
        }
        __syncthreads();
    }

    #pragma unroll
    for (int i = 0; i < 4; i++) {
        int row = bm + ty * 4 + i;
        #pragma unroll
        for (int j = 0; j < 4; j++) {
            int col = bn + tx * 4 + j;
            float r = acc[i][j] + bias[col];
            size_t o = (size_t)row * N + col;
            if (EPI == 0) C[o] = r;
            else if (EPI == 1) C[o] = gelu_exact(r);
            else C[o] += r;
        }
    }
}

// ---------------- attention: one block per (sequence, head) ----------------
template<int NMAX>
__global__ void attn_kernel(const float* __restrict__ Q, const float* __restrict__ Kb,
                            const float* __restrict__ Vb, float* __restrict__ O,
                            int pl, int st) {
    __shared__ float Ks[NMAX][32];
    __shared__ float Vs[NMAX][32];
    int bt = blockIdx.x, head = blockIdx.y;
    int t = bt & (LSEQ - 1);
    int n = (t + MAXPADC - (pl - 1)) / st + 1;
    int base = bt * NMAX * HID + head * DHEAD;

    for (int i = threadIdx.x; i < NMAX * 32; i += blockDim.x) {
        int kk = i >> 5, d = i & 31;
        Ks[kk][d] = Kb[base + kk * HID + d];
        Vs[kk][d] = Vb[base + kk * HID + d];
    }
    __syncthreads();

    int tq = threadIdx.x;
    if (tq < NMAX) {
        float qr[32];
        #pragma unroll
        for (int d = 0; d < 32; d++) qr[d] = Q[base + tq * HID + d];
        float sc[NMAX];
        float mx = -1e30f;
        #pragma unroll
        for (int kk = 0; kk < NMAX; kk++) {
            float s = 0.0f;
            #pragma unroll
            for (int d = 0; d < 32; d++) s += qr[d] * Ks[kk][d];
            s *= 0.17677669529663687f;   // 1/sqrt(32)
            sc[kk] = (kk < n) ? s : -1e30f;
            mx = fmaxf(mx, sc[kk]);
        }
        float ssum = 0.0f;
        #pragma unroll
        for (int kk = 0; kk < NMAX; kk++) {
            float e = (kk < n) ? expf(sc[kk] - mx) : 0.0f;
            sc[kk] = e;
            ssum += e;
        }
        float inv = 1.0f / ssum;
        #pragma unroll
        for (int d = 0; d < 32; d++) {
            float o = 0.0f;
            #pragma unroll
            for (int kk = 0; kk < NMAX; kk++) o += sc[kk] * Vs[kk][d];
            O[base + tq * HID + d] = o * inv;
        }
    }
}

// ---------------- host side ----------------
static inline void gemm(const float* A, const float* W, const float* bias, float* C,
                        int M, int N, int K, int epi) {
    dim3 grid(N / 64, M / 64), block(256);
    if (epi == 0)      gemm_kernel<0><<<grid, block>>>(A, W, bias, C, M, N, K);
    else if (epi == 1) gemm_kernel<1><<<grid, block>>>(A, W, bias, C, M, N, K);
    else               gemm_kernel<2><<<grid, block>>>(A, W, bias, C, M, N, K);
}

extern "C" void kernel_launch(void* const* d_in, const int* in_sizes, int n_in,
                              void* d_out, int out_size) {
    const float* x       = (const float*)d_in[0];
    const float* w_proj[2] = { (const float*)d_in[1], (const float*)d_in[3] };
    const float* b_proj[2] = { (const float*)d_in[2], (const float*)d_in[4] };
    const float* pos[2]    = { (const float*)d_in[5], (const float*)d_in[6] };
    const float* ln1_g = (const float*)d_in[7];
    const float* ln1_b = (const float*)d_in[8];
    const float* wq = (const float*)d_in[9];
    const float* bq = (const float*)d_in[10];
    const float* wk = (const float*)d_in[11];
    const float* bk = (const float*)d_in[12];
    const float* wv = (const float*)d_in[13];
    const float* bv = (const float*)d_in[14];
    const float* wo = (const float*)d_in[15];
    const float* bo = (const float*)d_in[16];
    const float* ln2_g = (const float*)d_in[17];
    const float* ln2_b = (const float*)d_in[18];
    const float* w_ff1 = (const float*)d_in[19];
    const float* b_ff1 = (const float*)d_in[20];
    const float* w_ff2 = (const float*)d_in[21];
    const float* b_ff2 = (const float*)d_in[22];
    const float* ln_g = (const float*)d_in[23];
    const float* ln_b = (const float*)d_in[24];
    const float* w_fus1 = (const float*)d_in[25];
    const float* b_fus1 = (const float*)d_in[26];
    const float* w_fus2 = (const float*)d_in[27];
    const float* b_fus2 = (const float*)d_in[28];

    float *win, *tokens, *seq, *s2, *ff, *comb;
    cudaGetSymbolAddress((void**)&win,    g_win);
    cudaGetSymbolAddress((void**)&tokens, g_tokens);
    cudaGetSymbolAddress((void**)&seq,    g_seq);
    cudaGetSymbolAddress((void**)&s2,     g_s2);
    cudaGetSymbolAddress((void**)&ff,     g_ff);
    cudaGetSymbolAddress((void**)&comb,   g_comb);
    float* qb = ff;
    float* kb = ff + SEQBUF;
    float* vb = ff + 2 * SEQBUF;

    const int PL[2] = {8, 16}, ST[2] = {4, 8}, EE[2] = {136, 128}, NMX[2] = {34, 16};

    for (int s = 0; s < 2; s++) {
        int pl = PL[s], st = ST[s], E = EE[s], NMAX = NMX[s];
        int plc = pl * CH;
        int BE = BATCH * E;       // 1088 or 1024 (both %64==0)
        int M = NSEQ * NMAX;      // 34816 or 16384

        { int tot = BE * plc;
          win_kernel<<<(tot + 255) / 256, 256>>>(x, win, E, pl); }
        gemm(win, w_proj[s], b_proj[s], tokens, BE, HID, plc, 0);
        { int tot = M * HID;
          build_seq_kernel<<<(tot + 255) / 256, 256>>>(tokens, pos[s], seq, NMAX, E, pl, st); }

        for (int li = 0; li < 2; li++) {
            ln_kernel<<<M, 256>>>(seq, ln1_g + li * HID, ln1_b + li * HID, s2);
            gemm(s2, wq + li * HID * HID, bq + li * HID, qb, M, HID, HID, 0);
            gemm(s2, wk + li * HID * HID, bk + li * HID, kb, M, HID, HID, 0);
            gemm(s2, wv + li * HID * HID, bv + li * HID, vb, M, HID, HID, 0);
            dim3 ag(NSEQ, NHEAD);
            if (NMAX == 34) attn_kernel<34><<<ag, 64>>>(qb, kb, vb, s2, pl, st);
            else            attn_kernel<16><<<ag, 64>>>(qb, kb, vb, s2, pl, st);
            gemm(s2, wo + li * HID * HID, bo + li * HID, seq, M, HID, HID, 2);
            ln_kernel<<<M, 256>>>(seq, ln2_g + li * HID, ln2_b + li * HID, s2);
            gemm(s2, w_ff1 + li * HID * FFD, b_ff1 + li * FFD, ff, M, FFD, HID, 1);
            gemm(ff, w_ff2 + li * HID * FFD, b_ff2 + li * HID, seq, M, HID, FFD, 2);
        }
        { int tot = NSEQ * HID;
          gather_kernel<<<(tot + 255) / 256, 256>>>(seq, comb, NMAX, pl, st, s * HID); }
    }

    gemm(comb, w_fus1, b_fus1, s2, NSEQ, HID, 2 * HID, 1);
    gemm(s2, w_fus2, b_fus2, seq, NSEQ, HID, HID, 0);
    ln_kernel<<<NSEQ, 256>>>(seq, ln_g, ln_b, (float*)d_out);
}

// round 2
// speedup vs baseline: 2.6507x; 2.6507x over previous
#include <cuda_runtime.h>
#include <math.h>
#include <stdint.h>

// ---------------- problem constants ----------------
#define LSEQ   128
#define BATCH  8
#define CH     8
#define HID    256
#define NHEAD  8
#define DHEAD  32
#define FFD    1024
#define MAXPADC 15
#define NSEQ   1024          // BATCH * LSEQ

// ---------------- scratch (allocation-free) ----------------
__device__ float g_win[147456];                 // 1152 x 128 (padded)
__device__ float g_tokens[294912];              // 1152 x 256 (padded)
__device__ float g_seq[1024 * 34 * 256];
__device__ float g_s2 [1024 * 34 * 256];
__device__ float g_ff [1024 * 34 * 1024];       // also aliases q/k/v
__device__ float g_comb[1024 * 512];

static const int SEQBUF = 1024 * 34 * 256;

// ---------------- helpers ----------------
__device__ __forceinline__ float gelu_exact(float x) {
    return 0.5f * x * (1.0f + erff(x * 0.7071067811865476f));
}
__device__ __forceinline__ uint32_t f2tf(float f) {
    uint32_t u;
    asm("cvt.rna.tf32.f32 %0, %1;" : "=r"(u) : "f"(f));
    return u;
}
__device__ __forceinline__ void st_tf4(uint32_t* p, float4 v) {
    uint4 u;
    u.x = f2tf(v.x); u.y = f2tf(v.y); u.z = f2tf(v.z); u.w = f2tf(v.w);
    *(uint4*)p = u;
}
__device__ __forceinline__ void mma_tf32(float* c, const uint32_t* a,
                                         uint32_t b0, uint32_t b1) {
    asm volatile(
        "mma.sync.aligned.m16n8k8.row.col.f32.tf32.tf32.f32 "
        "{%0,%1,%2,%3}, {%4,%5,%6,%7}, {%8,%9}, {%0,%1,%2,%3};\n"
        : "+f"(c[0]), "+f"(c[1]), "+f"(c[2]), "+f"(c[3])
        : "r"(a[0]), "r"(a[1]), "r"(a[2]), "r"(a[3]), "r"(b0), "r"(b1));
}

// ---------------- window gather (x left-padded by 15 zeros) ----------------
__global__ void win_kernel(const float* __restrict__ x, float* __restrict__ win,
                           int E, int pl) {
    int plc = pl * CH;
    int tot = BATCH * E * plc;
    int idx = blockIdx.x * blockDim.x + threadIdx.x;
    if (idx >= tot) return;
    int r = idx % plc;
    int e = (idx / plc) % E;
    int b = idx / (plc * E);
    int p = r >> 3, c = r & 7;
    int i = e + p;
    win[idx] = (i < MAXPADC) ? 0.0f : x[(b * LSEQ + (i - MAXPADC)) * CH + c];
}

// ---------------- seq build: tokens[j(t,k)] + pos[k] ----------------
__global__ void build_seq_kernel(const float* __restrict__ tokens,
                                 const float* __restrict__ pos,
                                 float* __restrict__ seq,
                                 int NMAX, int E, int pl, int st) {
    int tot = NSEQ * NMAX * HID;
    int idx = blockIdx.x * blockDim.x + threadIdx.x;
    if (idx >= tot) return;
    int h = idx & 255;
    int rest = idx >> 8;
    int k = rest % NMAX;
    int bt = rest / NMAX;
    int t = bt & (LSEQ - 1);
    int b = bt >> 7;
    int n = (t + MAXPADC - (pl - 1)) / st + 1;
    int ends = t + MAXPADC - (n - 1) * st + k * st;
    int j = ends - (pl - 1);
    j = j < 0 ? 0 : (j > E - 1 ? E - 1 : j);
    seq[idx] = tokens[(b * E + j) * HID + h] + pos[k * HID + h];
}

// ---------------- gather last valid patch into concat buffer ----------------
__global__ void gather_kernel(const float* __restrict__ seq, float* __restrict__ comb,
                              int NMAX, int pl, int st, int off) {
    int idx = blockIdx.x * blockDim.x + threadIdx.x;
    if (idx >= NSEQ * HID) return;
    int h = idx & 255;
    int bt = idx >> 8;
    int t = bt & (LSEQ - 1);
    int n = (t + MAXPADC - (pl - 1)) / st + 1;
    comb[bt * 512 + off + h] = seq[(bt * NMAX + (n - 1)) * HID + h];
}

// ---------------- layernorm: one WARP per row of 256 ----------------
__global__ void ln_kernel(const float* __restrict__ in, const float* __restrict__ g,
                          const float* __restrict__ b, float* __restrict__ out) {
    int warp = threadIdx.x >> 5, lane = threadIdx.x & 31;
    size_t row = (size_t)blockIdx.x * 8 + warp;
    const float4* p = (const float4*)(in + row * 256);
    float4 v0 = p[lane], v1 = p[lane + 32];
    float s = v0.x + v0.y + v0.z + v0.w + v1.x + v1.y + v1.z + v1.w;
    #pragma unroll
    for (int o = 16; o > 0; o >>= 1) s += __shfl_xor_sync(0xffffffffu, s, o);
    float mu = s * (1.0f / 256.0f);
    float d0x = v0.x - mu, d0y = v0.y - mu, d0z = v0.z - mu, d0w = v0.w - mu;
    float d1x = v1.x - mu, d1y = v1.y - mu, d1z = v1.z - mu, d1w = v1.w - mu;
    float q = d0x*d0x + d0y*d0y + d0z*d0z + d0w*d0w
            + d1x*d1x + d1y*d1y + d1z*d1z + d1w*d1w;
    #pragma unroll
    for (int o = 16; o > 0; o >>= 1) q += __shfl_xor_sync(0xffffffffu, q, o);
    float r = rsqrtf(q * (1.0f / 256.0f) + 1e-5f);
    const float4* gp = (const float4*)g;
    const float4* bp = (const float4*)b;
    float4 g0 = gp[lane], g1 = gp[lane + 32];
    float4 b0 = bp[lane], b1 = bp[lane + 32];
    float4 o0, o1;
    o0.x = d0x * r * g0.x + b0.x; o0.y = d0y * r * g0.y + b0.y;
    o0.z = d0z * r * g0.z + b0.z; o0.w = d0w * r * g0.w + b0.w;
    o1.x = d1x * r * g1.x + b1.x; o1.y = d1y * r * g1.y + b1.y;
    o1.z = d1z * r * g1.z + b1.z; o1.w = d1w * r * g1.w + b1.w;
    float4* po = (float4*)(out + row * 256);
    po[lane] = o0; po[lane + 32] = o1;
}

// ---------------- tf32 tensor-core GEMM: C[M,N] = A[M,K] @ W[K,N] ----------------
// Block tile 128x128, BK=16, 8 warps (4x2), warp tile 32x64, double-buffered.
// Requires M%128==0 (padded), N%128==0, K%16==0.
// EPI: 0 = bias store, 1 = bias+gelu store, 2 = bias + accumulate (residual)
template<int EPI>
__global__ void __launch_bounds__(256) tgemm_kernel(
        const float* __restrict__ A, const float* __restrict__ W,
        const float* __restrict__ bias, float* __restrict__ C,
        int N, int K) {
    __shared__ uint32_t As[2][128 * 20];   // m-major, row stride 20 (pad)
    __shared__ uint32_t Bs[2][16 * 136];   // k-major, row stride 136 (pad)

    const int tid = threadIdx.x, lane = tid & 31, warp = tid >> 5;
    const int wm = (warp >> 1) << 5;       // warp M offset (0..96)
    const int wn = (warp & 1) << 6;        // warp N offset (0/64)
    const int bm = blockIdx.y << 7, bn = blockIdx.x << 7;

    float acc[2][8][4];
    #pragma unroll
    for (int mi = 0; mi < 2; mi++)
        #pragma unroll
        for (int j = 0; j < 8; j++)
            #pragma unroll
            for (int q = 0; q < 4; q++) acc[mi][j][q] = 0.0f;

    const float* Ap = A + (size_t)(bm + (tid >> 2)) * K + ((tid & 3) << 2);
    const float* Bp = W + (size_t)(tid >> 5) * N + bn + ((tid & 31) << 2);
    const size_t a64 = (size_t)64 * K;
    const size_t b8  = (size_t)8 * N;

    const int as0 = (tid >> 2) * 20 + ((tid & 3) << 2);
    const int as1 = as0 + 64 * 20;
    const int bs0 = (tid >> 5) * 136 + ((tid & 31) << 2);
    const int bs1 = bs0 + 8 * 136;

    float4 av0 = *(const float4*)Ap;
    float4 av1 = *(const float4*)(Ap + a64);
    float4 bv0 = *(const float4*)Bp;
    float4 bv1 = *(const float4*)(Bp + b8);
    st_tf4(&As[0][as0], av0); st_tf4(&As[0][as1], av1);
    st_tf4(&Bs[0][bs0], bv0); st_tf4(&Bs[0][bs1], bv1);
    __syncthreads();

    const int aoff = (wm + (lane >> 2)) * 20 + (lane & 3);
    const int boff = (lane & 3) * 136 + wn + (lane >> 2);

    int cur = 0;
    for (int k0 = 0; k0 < K; k0 += 16) {
        const bool nxt = (k0 + 16) < K;
        if (nxt) {
            Ap += 16; Bp += (size_t)16 * N;
            av0 = *(const float4*)Ap;
            av1 = *(const float4*)(Ap + a64);
            bv0 = *(const float4*)Bp;
            bv1 = *(const float4*)(Bp + b8);
        }
        const uint32_t* Ab = As[cur];
        const uint32_t* Bb = Bs[cur];
        #pragma unroll
        for (int kk = 0; kk < 2; kk++) {
            uint32_t a[2][4];
            #pragma unroll
            for (int mi = 0; mi < 2; mi++) {
                const uint32_t* p = Ab + aoff + mi * 320 + kk * 8;  // 16*20, k step
                a[mi][0] = p[0];
                a[mi][1] = p[160];          // +8 rows
                a[mi][2] = p[4];            // +4 cols
                a[mi][3] = p[164];
            }
            #pragma unroll
            for (int j = 0; j < 8; j++) {
                uint32_t b0 = Bb[boff + kk * 1088 + j * 8];        // 8*136
                uint32_t b1 = Bb[boff + kk * 1088 + j * 8 + 544];  // +4 k rows
                mma_tf32(acc[0][j], a[0], b0, b1);
                mma_tf32(acc[1][j], a[1], b0, b1);
            }
        }
        if (nxt) {
            int nb = cur ^ 1;
            st_tf4(&As[nb][as0], av0); st_tf4(&As[nb][as1], av1);
            st_tf4(&Bs[nb][bs0], bv0); st_tf4(&Bs[nb][bs1], bv1);
            __syncthreads();
            cur = nb;
        }
    }

    // epilogue
    #pragma unroll
    for (int mi = 0; mi < 2; mi++) {
        int r = bm + wm + mi * 16 + (lane >> 2);
        #pragma unroll
        for (int j = 0; j < 8; j++) {
            int c = bn + wn + j * 8 + ((lane & 3) << 1);
            float bf0 = bias[c], bf1 = bias[c + 1];
            float v0 = acc[mi][j][0] + bf0, v1 = acc[mi][j][1] + bf1;
            float v2 = acc[mi][j][2] + bf0, v3 = acc[mi][j][3] + bf1;
            float2* p0 = (float2*)(C + (size_t)r * N + c);
            float2* p1 = (float2*)(C + (size_t)(r + 8) * N + c);
            if (EPI == 0) {
                *p0 = make_float2(v0, v1);
                *p1 = make_float2(v2, v3);
            } else if (EPI == 1) {
                *p0 = make_float2(gelu_exact(v0), gelu_exact(v1));
                *p1 = make_float2(gelu_exact(v2), gelu_exact(v3));
            } else {
                float2 o0 = *p0, o1 = *p1;
                *p0 = make_float2(o0.x + v0, o0.y + v1);
                *p1 = make_float2(o1.x + v2, o1.y + v3);
            }
        }
    }
}

// ---------------- attention: one block per (sequence, head) ----------------
template<int NMAX>
__global__ void attn_kernel(const float* __restrict__ Q, const float* __restrict__ Kb,
                            const float* __restrict__ Vb, float* __restrict__ O,
                            int pl, int st) {
    __shared__ float Ks[NMAX][32];
    __shared__ float Vs[NMAX][32];
    int bt = blockIdx.x, head = blockIdx.y;
    int t = bt & (LSEQ - 1);
    int n = (t + MAXPADC - (pl - 1)) / st + 1;
    int base = bt * NMAX * HID + head * DHEAD;

    for (int i = threadIdx.x; i < NMAX * 32; i += blockDim.x) {
        int kk = i >> 5, d = i & 31;
        Ks[kk][d] = Kb[base + kk * HID + d];
        Vs[kk][d] = Vb[base + kk * HID + d];
    }
    __syncthreads();

    int tq = threadIdx.x;
    if (tq < NMAX) {
        float qr[32];
        #pragma unroll
        for (int d = 0; d < 32; d++) qr[d] = Q[base + tq * HID + d];
        float sc[NMAX];
        float mx = -1e30f;
        #pragma unroll
        for (int kk = 0; kk < NMAX; kk++) {
            float s = 0.0f;
            #pragma unroll
            for (int d = 0; d < 32; d++) s += qr[d] * Ks[kk][d];
            s *= 0.17677669529663687f;
            sc[kk] = (kk < n) ? s : -1e30f;
            mx = fmaxf(mx, sc[kk]);
        }
        float ssum = 0.0f;
        #pragma unroll
        for (int kk = 0; kk < NMAX; kk++) {
            float e = (kk < n) ? expf(sc[kk] - mx) : 0.0f;
            sc[kk] = e;
            ssum += e;
        }
        float inv = 1.0f / ssum;
        #pragma unroll
        for (int d = 0; d < 32; d++) {
            float o = 0.0f;
            #pragma unroll
            for (int kk = 0; kk < NMAX; kk++) o += sc[kk] * Vs[kk][d];
            O[base + tq * HID + d] = o * inv;
        }
    }
}

// ---------------- host side ----------------
static inline void gemm(const float* A, const float* W, const float* bias, float* C,
                        int Mp, int N, int K, int epi) {
    dim3 grid(N >> 7, Mp >> 7), block(256);
    if (epi == 0)      tgemm_kernel<0><<<grid, block>>>(A, W, bias, C, N, K);
    else if (epi == 1) tgemm_kernel<1><<<grid, block>>>(A, W, bias, C, N, K);
    else               tgemm_kernel<2><<<grid, block>>>(A, W, bias, C, N, K);
}

extern "C" void kernel_launch(void* const* d_in, const int* in_sizes, int n_in,
                              void* d_out, int out_size) {
    const float* x       = (const float*)d_in[0];
    const float* w_proj[2] = { (const float*)d_in[1], (const float*)d_in[3] };
    const float* b_proj[2] = { (const float*)d_in[2], (const float*)d_in[4] };
    const float* pos[2]    = { (const float*)d_in[5], (const float*)d_in[6] };
    const float* ln1_g = (const float*)d_in[7];
    const float* ln1_b = (const float*)d_in[8];
    const float* wq = (const float*)d_in[9];
    const float* bq = (const float*)d_in[10];
    const float* wk = (const float*)d_in[11];
    const float* bk = (const float*)d_in[12];
    const float* wv = (const float*)d_in[13];
    const float* bv = (const float*)d_in[14];
    const float* wo = (const float*)d_in[15];
    const float* bo = (const float*)d_in[16];
    const float* ln2_g = (const float*)d_in[17];
    const float* ln2_b = (const float*)d_in[18];
    const float* w_ff1 = (const float*)d_in[19];
    const float* b_ff1 = (const float*)d_in[20];
    const float* w_ff2 = (const float*)d_in[21];
    const float* b_ff2 = (const float*)d_in[22];
    const float* ln_g = (const float*)d_in[23];
    const float* ln_b = (const float*)d_in[24];
    const float* w_fus1 = (const float*)d_in[25];
    const float* b_fus1 = (const float*)d_in[26];
    const float* w_fus2 = (const float*)d_in[27];
    const float* b_fus2 = (const float*)d_in[28];

    float *win, *tokens, *seq, *s2, *ff, *comb;
    cudaGetSymbolAddress((void**)&win,    g_win);
    cudaGetSymbolAddress((void**)&tokens, g_tokens);
    cudaGetSymbolAddress((void**)&seq,    g_seq);
    cudaGetSymbolAddress((void**)&s2,     g_s2);
    cudaGetSymbolAddress((void**)&ff,     g_ff);
    cudaGetSymbolAddress((void**)&comb,   g_comb);
    float* qb = ff;
    float* kb = ff + SEQBUF;
    float* vb = ff + 2 * SEQBUF;

    const int PL[2] = {8, 16}, ST[2] = {4, 8}, EE[2] = {136, 128}, NMX[2] = {34, 16};
    const int MP[2] = {1152, 1024};   // proj M padded to /128

    for (int s = 0; s < 2; s++) {
        int pl = PL[s], st = ST[s], E = EE[s], NMAX = NMX[s];
        int plc = pl * CH;
        int BE = BATCH * E;
        int M = NSEQ * NMAX;      // 34816 or 16384, both %128==0

        { int tot = BE * plc;
          win_kernel<<<(tot + 255) / 256, 256>>>(x, win, E, pl); }
        gemm(win, w_proj[s], b_proj[s], tokens, MP[s], HID, plc, 0);
        { int tot = M * HID;
          build_seq_kernel<<<(tot + 255) / 256, 256>>>(tokens, pos[s], seq, NMAX, E, pl, st); }

        for (int li = 0; li < 2; li++) {
            ln_kernel<<<M / 8, 256>>>(seq, ln1_g + li * HID, ln1_b + li * HID, s2);
            gemm(s2, wq + li * HID * HID, bq + li * HID, qb, M, HID, HID, 0);
            gemm(s2, wk + li * HID * HID, bk + li * HID, kb, M, HID, HID, 0);
            gemm(s2, wv + li * HID * HID, bv + li * HID, vb, M, HID, HID, 0);
            dim3 ag(NSEQ, NHEAD);
            if (NMAX == 34) attn_kernel<34><<<ag, 64>>>(qb, kb, vb, s2, pl, st);
            else            attn_kernel<16><<<ag, 64>>>(qb, kb, vb, s2, pl, st);
            gemm(s2, wo + li * HID * HID, bo + li * HID, seq, M, HID, HID, 2);
            ln_kernel<<<M / 8, 256>>>(seq, ln2_g + li * HID, ln2_b + li * HID, s2);
            gemm(s2, w_ff1 + li * HID * FFD, b_ff1 + li * FFD, ff, M, FFD, HID, 1);
            gemm(ff, w_ff2 + li * HID * FFD, b_ff2 + li * HID, seq, M, HID, FFD, 2);
        }
        { int tot = NSEQ * HID;
          gather_kernel<<<(tot + 255) / 256, 256>>>(seq, comb, NMAX, pl, st, s * HID); }
    }

    gemm(comb, w_fus1, b_fus1, s2, NSEQ, HID, 2 * HID, 1);
    gemm(s2, w_fus2, b_fus2, seq, NSEQ, HID, HID, 0);
    ln_kernel<<<NSEQ / 8, 256>>>(seq, ln_g, ln_b, (float*)d_out);
}

// round 4
// speedup vs baseline: 2.9740x; 1.1220x over previous
#include <cuda_runtime.h>
#include <math.h>
#include <stdint.h>

// ---------------- problem constants ----------------
#define LSEQ   128
#define BATCH  8
#define CH     8
#define HID    256
#define NHEAD  8
#define DHEAD  32
#define FFD    1024
#define MAXPADC 15
#define NSEQ   1024          // BATCH * LSEQ

// ---------------- scratch (allocation-free) ----------------
__device__ float g_win[147456];                 // 1152 x 128 (padded)
__device__ float g_tokens[294912];              // 1152 x 256 (padded)
__device__ float g_seq[1024 * 34 * 256];
__device__ float g_s2 [1024 * 34 * 256];
__device__ float g_ff [1024 * 34 * 1024];       // also aliases q/k/v
__device__ float g_comb[1024 * 512];
__device__ float g_wt[1818624];                 // pre-transposed tf32-rounded weights

static const int SEQBUF = 1024 * 34 * 256;

// ---------------- helpers ----------------
__device__ __forceinline__ float gelu_exact(float x) {
    return 0.5f * x * (1.0f + erff(x * 0.7071067811865476f));
}
__device__ __forceinline__ uint32_t f2tf(float f) {
    uint32_t u;
    asm("cvt.rna.tf32.f32 %0, %1;" : "=r"(u) : "f"(f));
    return u;
}
__device__ __forceinline__ float rtf(float f) {    // round value to tf32, keep fp32 bits
    return __uint_as_float(f2tf(f));
}
__device__ __forceinline__ uint32_t smem_u32(const void* p) {
    uint32_t a;
    asm("{ .reg .u64 t; cvta.to.shared.u64 t, %1; cvt.u32.u64 %0, t; }" : "=r"(a) : "l"(p));
    return a;
}
__device__ __forceinline__ void cp16(uint32_t dst, const void* src) {
    asm volatile("cp.async.cg.shared.global [%0], [%1], 16;" :: "r"(dst), "l"(src));
}
__device__ __forceinline__ void cp_commit() {
    asm volatile("cp.async.commit_group;" ::: "memory");
}
template<int N>
__device__ __forceinline__ void cp_wait() {
    asm volatile("cp.async.wait_group %0;" :: "n"(N) : "memory");
}
__device__ __forceinline__ void mma_tf32(float* c, const uint32_t* a,
                                         uint32_t b0, uint32_t b1) {
    asm volatile(
        "mma.sync.aligned.m16n8k8.row.col.f32.tf32.tf32.f32 "
        "{%0,%1,%2,%3}, {%4,%5,%6,%7}, {%8,%9}, {%0,%1,%2,%3};\n"
        : "+f"(c[0]), "+f"(c[1]), "+f"(c[2]), "+f"(c[3])
        : "r"(a[0]), "r"(a[1]), "r"(a[2]), "r"(a[3]), "r"(b0), "r"(b1));
}

// ---------------- weight transpose + tf32 round: W[K,N] -> WT[N,K] ----------------
__global__ void wt_kernel(const float* __restrict__ W, float* __restrict__ WT,
                          int K, int N) {
    __shared__ float t[32][33];
    int kb = blockIdx.y * 32, nb = blockIdx.x * 32;
    int tx = threadIdx.x & 31, ty = threadIdx.x >> 5;
    #pragma unroll
    for (int i = 0; i < 32; i += 8)
        t[ty + i][tx] = W[(size_t)(kb + ty + i) * N + nb + tx];
    __syncthreads();
    #pragma unroll
    for (int i = 0; i < 32; i += 8)
        WT[(size_t)(nb + ty + i) * K + kb + tx] = rtf(t[tx][ty + i]);
}

// ---------------- window gather (rounded to tf32) ----------------
__global__ void win_kernel(const float* __restrict__ x, float* __restrict__ win,
                           int E, int pl) {
    int plc = pl * CH;
    int tot = BATCH * E * plc;
    int idx = blockIdx.x * blockDim.x + threadIdx.x;
    if (idx >= tot) return;
    int r = idx % plc;
    int e = (idx / plc) % E;
    int b = idx / (plc * E);
    int p = r >> 3, c = r & 7;
    int i = e + p;
    win[idx] = (i < MAXPADC) ? 0.0f : rtf(x[(b * LSEQ + (i - MAXPADC)) * CH + c]);
}

// ---------------- seq build ----------------
__global__ void build_seq_kernel(const float* __restrict__ tokens,
                                 const float* __restrict__ pos,
                                 float* __restrict__ seq,
                                 int NMAX, int E, int pl, int st) {
    int tot = NSEQ * NMAX * HID;
    int idx = blockIdx.x * blockDim.x + threadIdx.x;
    if (idx >= tot) return;
    int h = idx & 255;
    int rest = idx >> 8;
    int k = rest % NMAX;
    int bt = rest / NMAX;
    int t = bt & (LSEQ - 1);
    int b = bt >> 7;
    int n = (t + MAXPADC - (pl - 1)) / st + 1;
    int ends = t + MAXPADC - (n - 1) * st + k * st;
    int j = ends - (pl - 1);
    j = j < 0 ? 0 : (j > E - 1 ? E - 1 : j);
    seq[idx] = tokens[(b * E + j) * HID + h] + pos[k * HID + h];
}

// ---------------- gather last valid patch (rounded) ----------------
__global__ void gather_kernel(const float* __restrict__ seq, float* __restrict__ comb,
                              int NMAX, int pl, int st, int off) {
    int idx = blockIdx.x * blockDim.x + threadIdx.x;
    if (idx >= NSEQ * HID) return;
    int h = idx & 255;
    int bt = idx >> 8;
    int t = bt & (LSEQ - 1);
    int n = (t + MAXPADC - (pl - 1)) / st + 1;
    comb[bt * 512 + off + h] = rtf(seq[(bt * NMAX + (n - 1)) * HID + h]);
}

// ---------------- layernorm: one WARP per row of 256 ----------------
template<bool ROUND>
__global__ void ln_kernel(const float* __restrict__ in, const float* __restrict__ g,
                          const float* __restrict__ b, float* __restrict__ out) {
    int warp = threadIdx.x >> 5, lane = threadIdx.x & 31;
    size_t row = (size_t)blockIdx.x * 8 + warp;
    const float4* p = (const float4*)(in + row * 256);
    float4 v0 = p[lane], v1 = p[lane + 32];
    float s = v0.x + v0.y + v0.z + v0.w + v1.x + v1.y + v1.z + v1.w;
    #pragma unroll
    for (int o = 16; o > 0; o >>= 1) s += __shfl_xor_sync(0xffffffffu, s, o);
    float mu = s * (1.0f / 256.0f);
    float d0x = v0.x - mu, d0y = v0.y - mu, d0z = v0.z - mu, d0w = v0.w - mu;
    float d1x = v1.x - mu, d1y = v1.y - mu, d1z = v1.z - mu, d1w = v1.w - mu;
    float q = d0x*d0x + d0y*d0y + d0z*d0z + d0w*d0w
            + d1x*d1x + d1y*d1y + d1z*d1z + d1w*d1w;
    #pragma unroll
    for (int o = 16; o > 0; o >>= 1) q += __shfl_xor_sync(0xffffffffu, q, o);
    float r = rsqrtf(q * (1.0f / 256.0f) + 1e-5f);
    const float4* gp = (const float4*)g;
    const float4* bp = (const float4*)b;
    float4 g0 = gp[lane], g1 = gp[lane + 32];
    float4 b0 = bp[lane], b1 = bp[lane + 32];
    float4 o0, o1;
    o0.x = d0x * r * g0.x + b0.x; o0.y = d0y * r * g0.y + b0.y;
    o0.z = d0z * r * g0.z + b0.z; o0.w = d0w * r * g0.w + b0.w;
    o1.x = d1x * r * g1.x + b1.x; o1.y = d1y * r * g1.y + b1.y;
    o1.z = d1z * r * g1.z + b1.z; o1.w = d1w * r * g1.w + b1.w;
    if (ROUND) {
        o0.x = rtf(o0.x); o0.y = rtf(o0.y); o0.z = rtf(o0.z); o0.w = rtf(o0.w);
        o1.x = rtf(o1.x); o1.y = rtf(o1.y); o1.z = rtf(o1.z); o1.w = rtf(o1.w);
    }
    float4* po = (float4*)(out + row * 256);
    po[lane] = o0; po[lane + 32] = o1;
}

// ---------------- tf32 mma.sync GEMM, cp.async 3-stage pipeline ----------------
// C[M,N] = A[M,K] @ WT[N,K]^T (+bias, epilogue)
// BM=128, BN=256, BK=32, 8 warps, warp tile 64x64 (mi=4, j=8).
// A fp32 pre-rounded to tf32 values; WT tf32-rounded fp32 bits.
// M%128==0, N%256==0, K%32==0.
// Stage layout (floats): A[128][32] at 0, B[256][32] at 4096; stage stride 12288.
// 16B-granular swizzle: seg' = seg ^ (row & 7).
#define GSTAGE 12288
#define GSMEM  (3 * GSTAGE * 4)
template<int EPI>
__global__ void __launch_bounds__(256, 1) tgemm_kernel(
        const float* __restrict__ A, const float* __restrict__ BT,
        const float* __restrict__ bias, float* __restrict__ C,
        int N, int K) {
    extern __shared__ float sm[];
    const uint32_t sb = smem_u32(sm);
    const int tid = threadIdx.x, lane = tid & 31, warp = tid >> 5;
    const int bm = blockIdx.y << 7, bn = blockIdx.x << 8;
    const int wm = (warp & 1) << 6, wn = (warp >> 1) << 6;
    const int nc = K >> 5;

    // copy-side indices
    const int crow = tid >> 3, cseg = tid & 7;
    const float* Ag = A  + (size_t)(bm + crow) * K + (cseg << 2);
    const float* Bg = BT + (size_t)(bn + crow) * K + (cseg << 2);
    const int xsw = (cseg ^ (crow & 7)) << 2;     // swizzled word offset within row

    float acc[4][8][4];
    #pragma unroll
    for (int mi = 0; mi < 4; mi++)
        #pragma unroll
        for (int j = 0; j < 8; j++)
            #pragma unroll
            for (int q = 0; q < 4; q++) acc[mi][j][q] = 0.0f;

    // prologue: issue stages 0,1
    #pragma unroll
    for (int s = 0; s < 2; s++) {
        if (s < nc) {
            const int koff = s << 5;
            const uint32_t stg = sb + (uint32_t)(s * GSTAGE) * 4u;
            #pragma unroll
            for (int i = 0; i < 4; i++)
                cp16(stg + (uint32_t)(((crow + i * 32) << 5) + xsw) * 4u,
                     Ag + (size_t)(i * 32) * K + koff);
            #pragma unroll
            for (int i = 0; i < 8; i++)
                cp16(stg + (uint32_t)(16384) + (uint32_t)(((crow + i * 32) << 5) + xsw) * 4u,
                     Bg + (size_t)(i * 32) * K + koff);
        }
        cp_commit();
    }

    const int r_lo = lane >> 2, wv = lane & 3;

    for (int c = 0; c < nc; c++) {
        cp_wait<1>();
        __syncthreads();

        // issue chunk c+2
        if (c + 2 < nc) {
            const int koff = (c + 2) << 5;
            const uint32_t stg = sb + (uint32_t)(((c + 2) % 3) * GSTAGE) * 4u;
            #pragma unroll
            for (int i = 0; i < 4; i++)
                cp16(stg + (uint32_t)(((crow + i * 32) << 5) + xsw) * 4u,
                     Ag + (size_t)(i * 32) * K + koff);
            #pragma unroll
            for (int i = 0; i < 8; i++)
                cp16(stg + (uint32_t)(16384) + (uint32_t)(((crow + i * 32) << 5) + xsw) * 4u,
                     Bg + (size_t)(i * 32) * K + koff);
        }
        cp_commit();

        // compute chunk c
        const float* st  = sm + (c % 3) * GSTAGE;
        const float* stb = st + 4096;
        #pragma unroll
        for (int kk = 0; kk < 4; kk++) {
            const int s0 = (((2 * kk)     ^ r_lo) << 2) + wv;
            const int s1 = (((2 * kk + 1) ^ r_lo) << 2) + wv;
            uint32_t a[4][4];
            #pragma unroll
            for (int mi = 0; mi < 4; mi++) {
                const int base = (wm + mi * 16 + r_lo) << 5;
                a[mi][0] = __float_as_uint(st[base + s0]);
                a[mi][1] = __float_as_uint(st[base + 256 + s0]);
                a[mi][2] = __float_as_uint(st[base + s1]);
                a[mi][3] = __float_as_uint(st[base + 256 + s1]);
            }
            uint32_t bf[8][2];
            #pragma unroll
            for (int j = 0; j < 8; j++) {
                const int nb = (wn + j * 8 + r_lo) << 5;
                bf[j][0] = __float_as_uint(stb[nb + s0]);
                bf[j][1] = __float_as_uint(stb[nb + s1]);
            }
            #pragma unroll
            for (int j = 0; j < 8; j++)
                #pragma unroll
                for (int mi = 0; mi < 4; mi++)
                    mma_tf32(acc[mi][j], a[mi], bf[j][0], bf[j][1]);
        }
        __syncthreads();
    }

    // epilogue
    #pragma unroll
    for (int mi = 0; mi < 4; mi++) {
        const int r = bm + wm + mi * 16 + r_lo;
        #pragma unroll
        for (int j = 0; j < 8; j++) {
            const int cl = bn + wn + j * 8 + wv * 2;
            float bf0 = bias[cl], bf1 = bias[cl + 1];
            float v0 = acc[mi][j][0] + bf0, v1 = acc[mi][j][1] + bf1;
            float v2 = acc[mi][j][2] + bf0, v3 = acc[mi][j][3] + bf1;
            float2* p0 = (float2*)(C + (size_t)r * N + cl);
            float2* p1 = (float2*)(C + (size_t)(r + 8) * N + cl);
            if (EPI == 0) {
                *p0 = make_float2(v0, v1);
                *p1 = make_float2(v2, v3);
            } else if (EPI == 1) {
                *p0 = make_float2(rtf(gelu_exact(v0)), rtf(gelu_exact(v1)));
                *p1 = make_float2(rtf(gelu_exact(v2)), rtf(gelu_exact(v3)));
            } else {
                float2 o0 = *p0, o1 = *p1;
                *p0 = make_float2(o0.x + v0, o0.y + v1);
                *p1 = make_float2(o1.x + v2, o1.y + v3);
            }
        }
    }
}

// ---------------- attention: one block per (sequence, head) ----------------
template<int NMAX>
__global__ void attn_kernel(const float* __restrict__ Q, const float* __restrict__ Kb,
                            const float* __restrict__ Vb, float* __restrict__ O,
                            int pl, int st) {
    __shared__ float Ks[NMAX][32];
    __shared__ float Vs[NMAX][32];
    int bt = blockIdx.x, head = blockIdx.y;
    int t = bt & (LSEQ - 1);
    int n = (t + MAXPADC - (pl - 1)) / st + 1;
    int base = bt * NMAX * HID + head * DHEAD;

    for (int i = threadIdx.x; i < NMAX * 32; i += blockDim.x) {
        int kk = i >> 5, d = i & 31;
        Ks[kk][d] = Kb[base + kk * HID + d];
        Vs[kk][d] = Vb[base + kk * HID + d];
    }
    __syncthreads();

    int tq = threadIdx.x;
    if (tq < NMAX) {
        float qr[32];
        #pragma unroll
        for (int d = 0; d < 32; d++) qr[d] = Q[base + tq * HID + d];
        float sc[NMAX];
        float mx = -1e30f;
        #pragma unroll
        for (int kk = 0; kk < NMAX; kk++) {
            float s = 0.0f;
            #pragma unroll
            for (int d = 0; d < 32; d++) s += qr[d] * Ks[kk][d];
            s *= 0.17677669529663687f;
            sc[kk] = (kk < n) ? s : -1e30f;
            mx = fmaxf(mx, sc[kk]);
        }
        float ssum = 0.0f;
        #pragma unroll
        for (int kk = 0; kk < NMAX; kk++) {
            float e = (kk < n) ? expf(sc[kk] - mx) : 0.0f;
            sc[kk] = e;
            ssum += e;
        }
        float inv = 1.0f / ssum;
        #pragma unroll
        for (int d = 0; d < 32; d++) {
            float o = 0.0f;
            #pragma unroll
            for (int kk = 0; kk < NMAX; kk++) o += sc[kk] * Vs[kk][d];
            O[base + tq * HID + d] = rtf(o * inv);
        }
    }
}

// ---------------- host side ----------------
static inline void gemm(const float* A, const float* WT, const float* bias, float* C,
                        int Mp, int N, int K, int epi) {
    dim3 grid(N >> 8, Mp >> 7), block(256);
    if (epi == 0)      tgemm_kernel<0><<<grid, block, GSMEM>>>(A, WT, bias, C, N, K);
    else if (epi == 1) tgemm_kernel<1><<<grid, block, GSMEM>>>(A, WT, bias, C, N, K);
    else               tgemm_kernel<2><<<grid, block, GSMEM>>>(A, WT, bias, C, N, K);
}
static inline void wtr(const float* W, float* WT, int K, int N) {
    wt_kernel<<<dim3(N / 32, K / 32), 256>>>(W, WT, K, N);
}

extern "C" void kernel_launch(void* const* d_in, const int* in_sizes, int n_in,
                              void* d_out, int out_size) {
    cudaFuncSetAttribute(tgemm_kernel<0>, cudaFuncAttributeMaxDynamicSharedMemorySize, GSMEM);
    cudaFuncSetAttribute(tgemm_kernel<1>, cudaFuncAttributeMaxDynamicSharedMemorySize, GSMEM);
    cudaFuncSetAttribute(tgemm_kernel<2>, cudaFuncAttributeMaxDynamicSharedMemorySize, GSMEM);

    const float* x       = (const float*)d_in[0];
    const float* w_proj[2] = { (const float*)d_in[1], (const float*)d_in[3] };
    const float* b_proj[2] = { (const float*)d_in[2], (const float*)d_in[4] };
    const float* pos[2]    = { (const float*)d_in[5], (const float*)d_in[6] };
    const float* ln1_g = (const float*)d_in[7];
    const float* ln1_b = (const float*)d_in[8];
    const float* wq = (const float*)d_in[9];
    const float* bq = (const float*)d_in[10];
    const float* wk = (const float*)d_in[11];
    const float* bk = (const float*)d_in[12];
    const float* wv = (const float*)d_in[13];
    const float* bv = (const float*)d_in[14];
    const float* wo = (const float*)d_in[15];
    const float* bo = (const float*)d_in[16];
    const float* ln2_g = (const float*)d_in[17];
    const float* ln2_b = (const float*)d_in[18];
    const float* w_ff1 = (const float*)d_in[19];
    const float* b_ff1 = (const float*)d_in[20];
    const float* w_ff2 = (const float*)d_in[21];
    const float* b_ff2 = (const float*)d_in[22];
    const float* ln_g = (const float*)d_in[23];
    const float* ln_b = (const float*)d_in[24];
    const float* w_fus1 = (const float*)d_in[25];
    const float* b_fus1 = (const float*)d_in[26];
    const float* w_fus2 = (const float*)d_in[27];
    const float* b_fus2 = (const float*)d_in[28];

    float *win, *tokens, *seq, *s2, *ff, *comb, *wt;
    cudaGetSymbolAddress((void**)&win,    g_win);
    cudaGetSymbolAddress((void**)&tokens, g_tokens);
    cudaGetSymbolAddress((void**)&seq,    g_seq);
    cudaGetSymbolAddress((void**)&s2,     g_s2);
    cudaGetSymbolAddress((void**)&ff,     g_ff);
    cudaGetSymbolAddress((void**)&comb,   g_comb);
    cudaGetSymbolAddress((void**)&wt,     g_wt);
    float* qb = ff;
    float* kb = ff + SEQBUF;
    float* vb = ff + 2 * SEQBUF;

    // ---- transposed tf32 weight layout in g_wt ----
    float* wt_proj0 = wt;                         // 256 x 64
    float* wt_proj1 = wt + 16384;                 // 256 x 128
    float* wt_q     = wt + 49152;                 // 2 x (256 x 256)
    float* wt_k     = wt + 180224;
    float* wt_v     = wt + 311296;
    float* wt_o     = wt + 442368;
    float* wt_ff1   = wt + 573440;                // 2 x (1024 x 256)
    float* wt_ff2   = wt + 1097728;               // 2 x (256 x 1024)
    float* wt_fus1  = wt + 1622016;               // 256 x 512
    float* wt_fus2  = wt + 1753088;               // 256 x 256

    wtr(w_proj[0], wt_proj0, 64, 256);
    wtr(w_proj[1], wt_proj1, 128, 256);
    for (int li = 0; li < 2; li++) {
        wtr(wq + li * 65536, wt_q + li * 65536, 256, 256);
        wtr(wk + li * 65536, wt_k + li * 65536, 256, 256);
        wtr(wv + li * 65536, wt_v + li * 65536, 256, 256);
        wtr(wo + li * 65536, wt_o + li * 65536, 256, 256);
        wtr(w_ff1 + li * 262144, wt_ff1 + li * 262144, 256, 1024);
        wtr(w_ff2 + li * 262144, wt_ff2 + li * 262144, 1024, 256);
    }
    wtr(w_fus1, wt_fus1, 512, 256);
    wtr(w_fus2, wt_fus2, 256, 256);

    const int PL[2] = {8, 16}, ST[2] = {4, 8}, EE[2] = {136, 128}, NMX[2] = {34, 16};
    const int MP[2] = {1152, 1024};

    for (int s = 0; s < 2; s++) {
        int pl = PL[s], st = ST[s], E = EE[s], NMAX = NMX[s];
        int plc = pl * CH;
        int BE = BATCH * E;
        int M = NSEQ * NMAX;   // 34816 / 16384

        { int tot = BE * plc;
          win_kernel<<<(tot + 255) / 256, 256>>>(x, win, E, pl); }
        gemm(win, s == 0 ? wt_proj0 : wt_proj1, b_proj[s], tokens, MP[s], HID, plc, 0);
        { int tot = M * HID;
          build_seq_kernel<<<(tot + 255) / 256, 256>>>(tokens, pos[s], seq, NMAX, E, pl, st); }

        for (int li = 0; li < 2; li++) {
            ln_kernel<true><<<M / 8, 256>>>(seq, ln1_g + li * HID, ln1_b + li * HID, s2);
            gemm(s2, wt_q + li * 65536, bq + li * HID, qb, M, HID, HID, 0);
            gemm(s2, wt_k + li * 65536, bk + li * HID, kb, M, HID, HID, 0);
            gemm(s2, wt_v + li * 65536, bv + li * HID, vb, M, HID, HID, 0);
            dim3 ag(NSEQ, NHEAD);
            if (NMAX == 34) attn_kernel<34><<<ag, 64>>>(qb, kb, vb, s2, pl, st);
            else            attn_kernel<16><<<ag, 64>>>(qb, kb, vb, s2, pl, st);
            gemm(s2, wt_o + li * 65536, bo + li * HID, seq, M, HID, HID, 2);
            ln_kernel<true><<<M / 8, 256>>>(seq, ln2_g + li * HID, ln2_b + li * HID, s2);
            gemm(s2, wt_ff1 + li * 262144, b_ff1 + li * FFD, ff, M, FFD, HID, 1);
            gemm(ff, wt_ff2 + li * 262144, b_ff2 + li * HID, seq, M, HID, FFD, 2);
        }
        { int tot = NSEQ * HID;
          gather_kernel<<<(tot + 255) / 256, 256>>>(seq, comb, NMAX, pl, st, s * HID); }
    }

    gemm(comb, wt_fus1, b_fus1, s2, NSEQ, HID, 2 * HID, 1);
    gemm(s2, wt_fus2, b_fus2, seq, NSEQ, HID, HID, 0);
    ln_kernel<false><<<NSEQ / 8, 256>>>(seq, ln_g, ln_b, (float*)d_out);
}

// round 6
// speedup vs baseline: 3.8670x; 1.3003x over previous
#include <cuda_runtime.h>
#include <cuda_fp16.h>
#include <math.h>
#include <stdint.h>

// ---------------- problem constants ----------------
#define LSEQ   128
#define BATCH  8
#define CH     8
#define HID    256
#define NHEAD  8
#define DHEAD  32
#define FFD    1024
#define MAXPADC 15
#define NSEQ   1024          // BATCH * LSEQ

// ---------------- scratch (allocation-free) ----------------
__device__ __half  g_winh[147456];              // 1152 x 128 (padded), half
__device__ float   g_tokens[294912];            // 1152 x 256
__device__ float   g_seq[1024 * 34 * 256];      // residual stream fp32
__device__ float   g_qkv[1024 * 34 * 768];      // fused qkv output fp32
__device__ __half  g_s2h[1024 * 34 * 256];      // LN / attn outputs, half
__device__ __half  g_ffh[1024 * 34 * 1024];     // ff1 gelu output, half
__device__ __half  g_combh[1024 * 512];
__device__ __half  g_wth[1818624];              // pre-transposed half weights
__device__ float   g_bqkv[1536];                // packed qkv bias, 2 layers x 768

// ---------------- helpers ----------------
__device__ __forceinline__ float gelu_exact(float x) {
    return 0.5f * x * (1.0f + erff(x * 0.7071067811865476f));
}
__device__ __forceinline__ uint32_t smem_u32(const void* p) {
    uint32_t a;
    asm("{ .reg .u64 t; cvta.to.shared.u64 t, %1; cvt.u32.u64 %0, t; }" : "=r"(a) : "l"(p));
    return a;
}
__device__ __forceinline__ void cp16(uint32_t dst, const void* src) {
    asm volatile("cp.async.cg.shared.global [%0], [%1], 16;" :: "r"(dst), "l"(src));
}
__device__ __forceinline__ void cp_commit() {
    asm volatile("cp.async.commit_group;" ::: "memory");
}
template<int N>
__device__ __forceinline__ void cp_wait() {
    asm volatile("cp.async.wait_group %0;" :: "n"(N) : "memory");
}
__device__ __forceinline__ void mma_f16(float* c, const uint32_t* a,
                                        uint32_t b0, uint32_t b1) {
    asm volatile(
        "mma.sync.aligned.m16n8k16.row.col.f32.f16.f16.f32 "
        "{%0,%1,%2,%3}, {%4,%5,%6,%7}, {%8,%9}, {%0,%1,%2,%3};\n"
        : "+f"(c[0]), "+f"(c[1]), "+f"(c[2]), "+f"(c[3])
        : "r"(a[0]), "r"(a[1]), "r"(a[2]), "r"(a[3]), "r"(b0), "r"(b1));
}
// swizzled half-offset within a [rows][32-half] tile
__device__ __forceinline__ int swofs(int r, int h) {
    return r * 32 + ((((h >> 3) ^ ((r >> 1) & 3)) << 3)) + (h & 7);
}

// ---------------- weight transpose + half convert: W[K,N] -> WT[N,K] ----------------
__global__ void wt_kernel(const float* __restrict__ W, __half* __restrict__ WT,
                          int K, int N) {
    __shared__ float t[32][33];
    int kb = blockIdx.y * 32, nb = blockIdx.x * 32;
    int tx = threadIdx.x & 31, ty = threadIdx.x >> 5;
    #pragma unroll
    for (int i = 0; i < 32; i += 8)
        t[ty + i][tx] = W[(size_t)(kb + ty + i) * N + nb + tx];
    __syncthreads();
    #pragma unroll
    for (int i = 0; i < 32; i += 8)
        WT[(size_t)(nb + ty + i) * K + kb + tx] = __float2half_rn(t[tx][ty + i]);
}

// ---------------- window gather (half) ----------------
__global__ void win_kernel(const float* __restrict__ x, __half* __restrict__ win,
                           int E, int pl) {
    int plc = pl * CH;
    int tot = BATCH * E * plc;
    int idx = blockIdx.x * blockDim.x + threadIdx.x;
    if (idx >= tot) return;
    int r = idx % plc;
    int e = (idx / plc) % E;
    int b = idx / (plc * E);
    int p = r >> 3, c = r & 7;
    int i = e + p;
    win[idx] = __float2half_rn((i < MAXPADC) ? 0.0f : x[(b * LSEQ + (i - MAXPADC)) * CH + c]);
}

// ---------------- seq build (fp32) ----------------
__global__ void build_seq_kernel(const float* __restrict__ tokens,
                                 const float* __restrict__ pos,
                                 float* __restrict__ seq,
                                 int NMAX, int E, int pl, int st) {
    int tot = NSEQ * NMAX * HID;
    int idx = blockIdx.x * blockDim.x + threadIdx.x;
    if (idx >= tot) return;
    int h = idx & 255;
    int rest = idx >> 8;
    int k = rest % NMAX;
    int bt = rest / NMAX;
    int t = bt & (LSEQ - 1);
    int b = bt >> 7;
    int n = (t + MAXPADC - (pl - 1)) / st + 1;
    int ends = t + MAXPADC - (n - 1) * st + k * st;
    int j = ends - (pl - 1);
    j = j < 0 ? 0 : (j > E - 1 ? E - 1 : j);
    seq[idx] = tokens[(b * E + j) * HID + h] + pos[k * HID + h];
}

// ---------------- gather last valid patch (half) ----------------
__global__ void gather_kernel(const float* __restrict__ seq, __half* __restrict__ comb,
                              int NMAX, int pl, int st, int off) {
    int idx = blockIdx.x * blockDim.x + threadIdx.x;
    if (idx >= NSEQ * HID) return;
    int h = idx & 255;
    int bt = idx >> 8;
    int t = bt & (LSEQ - 1);
    int n = (t + MAXPADC - (pl - 1)) / st + 1;
    comb[bt * 512 + off + h] = __float2half_rn(seq[(bt * NMAX + (n - 1)) * HID + h]);
}

// ---------------- layernorm: one WARP per row of 256, templated output ----------------
template<typename OT>
__global__ void ln_kernel(const float* __restrict__ in, const float* __restrict__ g,
                          const float* __restrict__ b, OT* __restrict__ out) {
    int warp = threadIdx.x >> 5, lane = threadIdx.x & 31;
    size_t row = (size_t)blockIdx.x * 8 + warp;
    const float4* p = (const float4*)(in + row * 256);
    float4 v0 = p[lane], v1 = p[lane + 32];
    float s = v0.x + v0.y + v0.z + v0.w + v1.x + v1.y + v1.z + v1.w;
    #pragma unroll
    for (int o = 16; o > 0; o >>= 1) s += __shfl_xor_sync(0xffffffffu, s, o);
    float mu = s * (1.0f / 256.0f);
    float d0x = v0.x - mu, d0y = v0.y - mu, d0z = v0.z - mu, d0w = v0.w - mu;
    float d1x = v1.x - mu, d1y = v1.y - mu, d1z = v1.z - mu, d1w = v1.w - mu;
    float q = d0x*d0x + d0y*d0y + d0z*d0z + d0w*d0w
            + d1x*d1x + d1y*d1y + d1z*d1z + d1w*d1w;
    #pragma unroll
    for (int o = 16; o > 0; o >>= 1) q += __shfl_xor_sync(0xffffffffu, q, o);
    float r = rsqrtf(q * (1.0f / 256.0f) + 1e-5f);
    const float4* gp = (const float4*)g;
    const float4* bp = (const float4*)b;
    float4 g0 = gp[lane], g1 = gp[lane + 32];
    float4 b0 = bp[lane], b1 = bp[lane + 32];
    float o0x = d0x * r * g0.x + b0.x, o0y = d0y * r * g0.y + b0.y;
    float o0z = d0z * r * g0.z + b0.z, o0w = d0w * r * g0.w + b0.w;
    float o1x = d1x * r * g1.x + b1.x, o1y = d1y * r * g1.y + b1.y;
    float o1z = d1z * r * g1.z + b1.z, o1w = d1w * r * g1.w + b1.w;
    if (sizeof(OT) == 2) {
        __half* oh = (__half*)out + row * 256;
        __half2 h0[2] = { __floats2half2_rn(o0x, o0y), __floats2half2_rn(o0z, o0w) };
        __half2 h1[2] = { __floats2half2_rn(o1x, o1y), __floats2half2_rn(o1z, o1w) };
        *(uint2*)(oh + lane * 4)       = *(uint2*)h0;
        *(uint2*)(oh + 128 + lane * 4) = *(uint2*)h1;
    } else {
        float* of = (float*)out + row * 256;
        *(float4*)(of + lane * 4)       = make_float4(o0x, o0y, o0z, o0w);
        *(float4*)(of + 128 + lane * 4) = make_float4(o1x, o1y, o1z, o1w);
    }
}

// ---------------- fp16 mma.sync GEMM, cp.async 3-stage pipeline ----------------
// C[M,N] = A[M,K] @ WT[N,K]^T (+bias, epilogue)
// BM=128, BN=256, BK=32 (halves), 8 warps, warp tile 64x64.
// A half [M,K]; WT half [N,K]. M%128==0, N%256==0, K%32==0.
// Stage (halves): A[128*32] at 0, B[256*32] at 4096; stage stride 12288 halves.
// EPI: 0 = bias store fp32, 1 = bias+gelu store half, 2 = bias + accumulate fp32
#define HSTAGE 12288
#define HSMEM  (3 * HSTAGE * 2)
template<int EPI>
__global__ void __launch_bounds__(256, 1) hgemm_kernel(
        const __half* __restrict__ A, const __half* __restrict__ BT,
        const float* __restrict__ bias, void* __restrict__ Cv,
        int N, int K) {
    extern __shared__ __half sm[];
    const uint32_t sb = smem_u32(sm);
    const int tid = threadIdx.x, lane = tid & 31, warp = tid >> 5;
    const int bm = blockIdx.y << 7, bn = blockIdx.x << 8;
    const int wm = (warp & 1) << 6, wn = (warp >> 1) << 6;
    const int nc = K >> 5;

    float acc[4][8][4];
    #pragma unroll
    for (int mi = 0; mi < 4; mi++)
        #pragma unroll
        for (int j = 0; j < 8; j++)
            #pragma unroll
            for (int q = 0; q < 4; q++) acc[mi][j][q] = 0.0f;

    // copy-side: A segs 512 (2/thread), B segs 1024 (4/thread); seg = 16B = 8 halves
    const int sA0 = tid, sA1 = tid + 256;
    auto issue = [&](int c) {
        const int koff = c << 5;
        const uint32_t stg = sb + (uint32_t)((c % 3) * HSTAGE) * 2u;
        #pragma unroll
        for (int i = 0; i < 2; i++) {
            int seg = (i == 0) ? sA0 : sA1;
            int row = seg >> 2, sc = seg & 3;
            uint32_t dst = stg + (uint32_t)(row * 32 + ((sc ^ ((row >> 1) & 3)) << 3)) * 2u;
            cp16(dst, A + (size_t)(bm + row) * K + koff + sc * 8);
        }
        #pragma unroll
        for (int i = 0; i < 4; i++) {
            int seg = tid + i * 256;
            int row = seg >> 2, sc = seg & 3;
            uint32_t dst = stg + (uint32_t)(4096 + row * 32 + ((sc ^ ((row >> 1) & 3)) << 3)) * 2u;
            cp16(dst, BT + (size_t)(bn + row) * K + koff + sc * 8);
        }
    };

    #pragma unroll
    for (int s = 0; s < 2; s++) {
        if (s < nc) issue(s);
        cp_commit();
    }

    const int r_lo = lane >> 2, wv = lane & 3;

    for (int c = 0; c < nc; c++) {
        cp_wait<1>();
        __syncthreads();
        if (c + 2 < nc) issue(c + 2);
        cp_commit();

        const __half* st  = sm + (c % 3) * HSTAGE;
        const __half* stb = st + 4096;
        #pragma unroll
        for (int kk = 0; kk < 2; kk++) {
            const int h0 = kk * 16 + 2 * wv;
            uint32_t a[4][4];
            #pragma unroll
            for (int mi = 0; mi < 4; mi++) {
                const int ra = wm + mi * 16 + r_lo;
                a[mi][0] = *(const uint32_t*)(st + swofs(ra,     h0));
                a[mi][1] = *(const uint32_t*)(st + swofs(ra + 8, h0));
                a[mi][2] = *(const uint32_t*)(st + swofs(ra,     h0 + 8));
                a[mi][3] = *(const uint32_t*)(st + swofs(ra + 8, h0 + 8));
            }
            uint32_t bf[8][2];
            #pragma unroll
            for (int j = 0; j < 8; j++) {
                const int rb = wn + j * 8 + r_lo;
                bf[j][0] = *(const uint32_t*)(stb + swofs(rb, h0));
                bf[j][1] = *(const uint32_t*)(stb + swofs(rb, h0 + 8));
            }
            #pragma unroll
            for (int j = 0; j < 8; j++)
                #pragma unroll
                for (int mi = 0; mi < 4; mi++)
                    mma_f16(acc[mi][j], a[mi], bf[j][0], bf[j][1]);
        }
        __syncthreads();
    }

    // epilogue
    #pragma unroll
    for (int mi = 0; mi < 4; mi++) {
        const int r = bm + wm + mi * 16 + r_lo;
        #pragma unroll
        for (int j = 0; j < 8; j++) {
            const int cl = bn + wn + j * 8 + wv * 2;
            float bf0 = bias[cl], bf1 = bias[cl + 1];
            float v0 = acc[mi][j][0] + bf0, v1 = acc[mi][j][1] + bf1;
            float v2 = acc[mi][j][2] + bf0, v3 = acc[mi][j][3] + bf1;
            if (EPI == 0) {
                float* C = (float*)Cv;
                *(float2*)(C + (size_t)r * N + cl)       = make_float2(v0, v1);
                *(float2*)(C + (size_t)(r + 8) * N + cl) = make_float2(v2, v3);
            } else if (EPI == 1) {
                __half* C = (__half*)Cv;
                *(__half2*)(C + (size_t)r * N + cl) =
                    __floats2half2_rn(gelu_exact(v0), gelu_exact(v1));
                *(__half2*)(C + (size_t)(r + 8) * N + cl) =
                    __floats2half2_rn(gelu_exact(v2), gelu_exact(v3));
            } else {
                float* C = (float*)Cv;
                float2* p0 = (float2*)(C + (size_t)r * N + cl);
                float2* p1 = (float2*)(C + (size_t)(r + 8) * N + cl);
                float2 o0 = *p0, o1 = *p1;
                *p0 = make_float2(o0.x + v0, o0.y + v1);
                *p1 = make_float2(o1.x + v2, o1.y + v3);
            }
        }
    }
}

// ---------------- attention: one block per (sequence, head) ----------------
// qkv fp32 [M, 768]: q at col 0, k at 256, v at 512. Output half [M, 256].
template<int NMAX>
__global__ void attn_kernel(const float* __restrict__ QKV, __half* __restrict__ O,
                            int pl, int st) {
    __shared__ float Ks[NMAX][32];
    __shared__ float Vs[NMAX][32];
    int bt = blockIdx.x, head = blockIdx.y;
    int t = bt & (LSEQ - 1);
    int n = (t + MAXPADC - (pl - 1)) / st + 1;
    size_t base = (size_t)bt * NMAX * 768 + head * DHEAD;

    for (int i = threadIdx.x; i < NMAX * 32; i += blockDim.x) {
        int kk = i >> 5, d = i & 31;
        Ks[kk][d] = QKV[base + (size_t)kk * 768 + 256 + d];
        Vs[kk][d] = QKV[base + (size_t)kk * 768 + 512 + d];
    }
    __syncthreads();

    int tq = threadIdx.x;
    if (tq < NMAX) {
        float qr[32];
        #pragma unroll
        for (int d = 0; d < 32; d++) qr[d] = QKV[base + (size_t)tq * 768 + d];
        float sc[NMAX];
        float mx = -1e30f;
        #pragma unroll
        for (int kk = 0; kk < NMAX; kk++) {
            float s = 0.0f;
            #pragma unroll
            for (int d = 0; d < 32; d++) s += qr[d] * Ks[kk][d];
            s *= 0.17677669529663687f;
            sc[kk] = (kk < n) ? s : -1e30f;
            mx = fmaxf(mx, sc[kk]);
        }
        float ssum = 0.0f;
        #pragma unroll
        for (int kk = 0; kk < NMAX; kk++) {
            float e = (kk < n) ? expf(sc[kk] - mx) : 0.0f;
            sc[kk] = e;
            ssum += e;
        }
        float inv = 1.0f / ssum;
        __half* op = O + (size_t)(bt * NMAX + tq) * HID + head * DHEAD;
        #pragma unroll
        for (int d = 0; d < 32; d += 2) {
            float o0 = 0.0f, o1 = 0.0f;
            #pragma unroll
            for (int kk = 0; kk < NMAX; kk++) {
                o0 += sc[kk] * Vs[kk][d];
                o1 += sc[kk] * Vs[kk][d + 1];
            }
            *(__half2*)(op + d) = __floats2half2_rn(o0 * inv, o1 * inv);
        }
    }
}

// ---------------- host side ----------------
static inline void gemm(const __half* A, const __half* WT, const float* bias, void* C,
                        int Mp, int N, int K, int epi) {
    dim3 grid(N >> 8, Mp >> 7), block(256);
    if (epi == 0)      hgemm_kernel<0><<<grid, block, HSMEM>>>(A, WT, bias, C, N, K);
    else if (epi == 1) hgemm_kernel<1><<<grid, block, HSMEM>>>(A, WT, bias, C, N, K);
    else               hgemm_kernel<2><<<grid, block, HSMEM>>>(A, WT, bias, C, N, K);
}
static inline void wtr(const float* W, __half* WT, int K, int N) {
    wt_kernel<<<dim3(N / 32, K / 32), 256>>>(W, WT, K, N);
}

extern "C" void kernel_launch(void* const* d_in, const int* in_sizes, int n_in,
                              void* d_out, int out_size) {
    cudaFuncSetAttribute(hgemm_kernel<0>, cudaFuncAttributeMaxDynamicSharedMemorySize, HSMEM);
    cudaFuncSetAttribute(hgemm_kernel<1>, cudaFuncAttributeMaxDynamicSharedMemorySize, HSMEM);
    cudaFuncSetAttribute(hgemm_kernel<2>, cudaFuncAttributeMaxDynamicSharedMemorySize, HSMEM);

    const float* x       = (const float*)d_in[0];
    const float* w_proj[2] = { (const float*)d_in[1], (const float*)d_in[3] };
    const float* b_proj[2] = { (const float*)d_in[2], (const float*)d_in[4] };
    const float* pos[2]    = { (const float*)d_in[5], (const float*)d_in[6] };
    const float* ln1_g = (const float*)d_in[7];
    const float* ln1_b = (const float*)d_in[8];
    const float* wq = (const float*)d_in[9];
    const float* bq = (const float*)d_in[10];
    const float* wk = (const float*)d_in[11];
    const float* bk = (const float*)d_in[12];
    const float* wv = (const float*)d_in[13];
    const float* bv = (const float*)d_in[14];
    const float* wo = (const float*)d_in[15];
    const float* bo = (const float*)d_in[16];
    const float* ln2_g = (const float*)d_in[17];
    const float* ln2_b = (const float*)d_in[18];
    const float* w_ff1 = (const float*)d_in[19];
    const float* b_ff1 = (const float*)d_in[20];
    const float* w_ff2 = (const float*)d_in[21];
    const float* b_ff2 = (const float*)d_in[22];
    const float* ln_g = (const float*)d_in[23];
    const float* ln_b = (const float*)d_in[24];
    const float* w_fus1 = (const float*)d_in[25];
    const float* b_fus1 = (const float*)d_in[26];
    const float* w_fus2 = (const float*)d_in[27];
    const float* b_fus2 = (const float*)d_in[28];

    __half *winh, *s2h, *ffh, *combh, *wth;
    float *tokens, *seq, *qkv, *bqkv;
    cudaGetSymbolAddress((void**)&winh,   g_winh);
    cudaGetSymbolAddress((void**)&tokens, g_tokens);
    cudaGetSymbolAddress((void**)&seq,    g_seq);
    cudaGetSymbolAddress((void**)&qkv,    g_qkv);
    cudaGetSymbolAddress((void**)&s2h,    g_s2h);
    cudaGetSymbolAddress((void**)&ffh,    g_ffh);
    cudaGetSymbolAddress((void**)&combh,  g_combh);
    cudaGetSymbolAddress((void**)&wth,    g_wth);
    cudaGetSymbolAddress((void**)&bqkv,   g_bqkv);

    // ---- transposed half weight layout in g_wth ----
    __half* wt_proj0 = wth;                      // 256 x 64
    __half* wt_proj1 = wth + 16384;              // 256 x 128
    __half* wt_qkv   = wth + 49152;              // 2 x (768 x 256)
    __half* wt_o     = wth + 442368;             // 2 x (256 x 256)
    __half* wt_ff1   = wth + 573440;             // 2 x (1024 x 256)
    __half* wt_ff2   = wth + 1097728;            // 2 x (256 x 1024)
    __half* wt_fus1  = wth + 1622016;            // 256 x 512
    __half* wt_fus2  = wth + 1753088;            // 256 x 256

    wtr(w_proj[0], wt_proj0, 64, 256);
    wtr(w_proj[1], wt_proj1, 128, 256);
    for (int li = 0; li < 2; li++) {
        wtr(wq + li * 65536, wt_qkv + li * 196608,          256, 256);
        wtr(wk + li * 65536, wt_qkv + li * 196608 + 65536,  256, 256);
        wtr(wv + li * 65536, wt_qkv + li * 196608 + 131072, 256, 256);
        wtr(wo + li * 65536, wt_o + li * 65536, 256, 256);
        wtr(w_ff1 + li * 262144, wt_ff1 + li * 262144, 256, 1024);
        wtr(w_ff2 + li * 262144, wt_ff2 + li * 262144, 1024, 256);
        cudaMemcpyAsync(bqkv + li * 768,       bq + li * 256, 1024, cudaMemcpyDeviceToDevice);
        cudaMemcpyAsync(bqkv + li * 768 + 256, bk + li * 256, 1024, cudaMemcpyDeviceToDevice);
        cudaMemcpyAsync(bqkv + li * 768 + 512, bv + li * 256, 1024, cudaMemcpyDeviceToDevice);
    }
    wtr(w_fus1, wt_fus1, 512, 256);
    wtr(w_fus2, wt_fus2, 256, 256);

    const int PL[2] = {8, 16}, ST[2] = {4, 8}, EE[2] = {136, 128}, NMX[2] = {34, 16};
    const int MP[2] = {1152, 1024};

    for (int s = 0; s < 2; s++) {
        int pl = PL[s], st = ST[s], E = EE[s], NMAX = NMX[s];
        int plc = pl * CH;
        int BE = BATCH * E;
        int M = NSEQ * NMAX;   // 34816 / 16384

        { int tot = BE * plc;
          win_kernel<<<(tot + 255) / 256, 256>>>(x, winh, E, pl); }
        gemm(winh, s == 0 ? wt_proj0 : wt_proj1, b_proj[s], tokens, MP[s], HID, plc, 0);
        { int tot = M * HID;
          build_seq_kernel<<<(tot + 255) / 256, 256>>>(tokens, pos[s], seq, NMAX, E, pl, st); }

        for (int li = 0; li < 2; li++) {
            ln_kernel<__half><<<M / 8, 256>>>(seq, ln1_g + li * HID, ln1_b + li * HID, s2h);
            gemm(s2h, wt_qkv + li * 196608, bqkv + li * 768, qkv, M, 768, HID, 0);
            dim3 ag(NSEQ, NHEAD);
            if (NMAX == 34) attn_kernel<34><<<ag, 64>>>(qkv, s2h, pl, st);
            else            attn_kernel<16><<<ag, 64>>>(qkv, s2h, pl, st);
            gemm(s2h, wt_o + li * 65536, bo + li * HID, seq, M, HID, HID, 2);
            ln_kernel<__half><<<M / 8, 256>>>(seq, ln2_g + li * HID, ln2_b + li * HID, s2h);
            gemm(s2h, wt_ff1 + li * 262144, b_ff1 + li * FFD, ffh, M, FFD, HID, 1);
            gemm(ffh, wt_ff2 + li * 262144, b_ff2 + li * HID, seq, M, HID, FFD, 2);
        }
        { int tot = NSEQ * HID;
          gather_kernel<<<(tot + 255) / 256, 256>>>(seq, combh, NMAX, pl, st, s * HID); }
    }

    gemm(combh, wt_fus1, b_fus1, s2h, NSEQ, HID, 2 * HID, 1);
    gemm(s2h, wt_fus2, b_fus2, seq, NSEQ, HID, HID, 0);
    ln_kernel<float><<<NSEQ / 8, 256>>>(seq, ln_g, ln_b, (float*)d_out);
}

// round 7
// speedup vs baseline: 5.9371x; 1.5353x over previous
#include <cuda_runtime.h>
#include <cuda_fp16.h>
#include <math.h>
#include <stdint.h>

// ---------------- problem constants ----------------
#define LSEQ   128
#define BATCH  8
#define CH     8
#define HID    256
#define NHEAD  8
#define DHEAD  32
#define FFD    1024
#define MAXPADC 15
#define NSEQ   1024          // BATCH * LSEQ

// compacted row counts: MB = rows per batch element, MC = total rows
#define MB0 2368
#define MB1 1088
#define MC0 18944            // 148 * 128
#define MC1 8704             // 68 * 128

// ---------------- scratch (allocation-free) ----------------
__device__ __half  g_winh[147456];              // 1152 x 128 (padded), half
__device__ float   g_tokens[294912];            // 1152 x 256
__device__ float   g_seq[MC0 * 256];            // residual stream fp32 (compacted)
__device__ float   g_qkv[MC0 * 768];            // fused qkv output fp32
__device__ __half  g_s2h[MC0 * 256];            // LN / attn outputs, half
__device__ __half  g_ffh[MC0 * 1024];           // ff1 gelu output, half
__device__ __half  g_combh[1024 * 512];
__device__ __half  g_wth[1818624];              // pre-transposed half weights
__device__ float   g_bqkv[1536];                // packed qkv bias, 2 layers x 768

// ---------------- helpers ----------------
__device__ __forceinline__ float gelu_exact(float x) {
    return 0.5f * x * (1.0f + erff(x * 0.7071067811865476f));
}
__device__ __forceinline__ uint32_t smem_u32(const void* p) {
    uint32_t a;
    asm("{ .reg .u64 t; cvta.to.shared.u64 t, %1; cvt.u32.u64 %0, t; }" : "=r"(a) : "l"(p));
    return a;
}
__device__ __forceinline__ void cp16(uint32_t dst, const void* src) {
    asm volatile("cp.async.cg.shared.global [%0], [%1], 16;" :: "r"(dst), "l"(src));
}
__device__ __forceinline__ void cp_commit() {
    asm volatile("cp.async.commit_group;" ::: "memory");
}
template<int N>
__device__ __forceinline__ void cp_wait() {
    asm volatile("cp.async.wait_group %0;" :: "n"(N) : "memory");
}
__device__ __forceinline__ void mma_f16(float* c, const uint32_t* a,
                                        uint32_t b0, uint32_t b1) {
    asm volatile(
        "mma.sync.aligned.m16n8k16.row.col.f32.f16.f16.f32 "
        "{%0,%1,%2,%3}, {%4,%5,%6,%7}, {%8,%9}, {%0,%1,%2,%3};\n"
        : "+f"(c[0]), "+f"(c[1]), "+f"(c[2]), "+f"(c[3])
        : "r"(a[0]), "r"(a[1]), "r"(a[2]), "r"(a[3]), "r"(b0), "r"(b1));
}
// swizzled half-offset within a [rows][32-half] tile
__device__ __forceinline__ int swofs(int r, int h) {
    return r * 32 + ((((h >> 3) ^ ((r >> 1) & 3)) << 3)) + (h & 7);
}
// valid patches for timestep t, and prefix-sum offsets (closed form)
template<int SCALE>
__device__ __forceinline__ int nfun(int t) {
    return SCALE == 0 ? ((t + 8) >> 2) + 1 : (t >> 3) + 1;
}
template<int SCALE>
__device__ __forceinline__ int Sfun(int t) {
    if (SCALE == 0) {        // sum_{u<t} ((u+8)/4 + 1) = t + G(t+8) - 4
        int m = t + 8, q = m >> 2, r = m & 3;
        return t + 2 * q * (q - 1) + r * q - 4;
    } else {                 // sum_{u<t} (u/8 + 1) = t + H(t)
        int q = t >> 3, r = t & 7;
        return t + 4 * q * (q - 1) + r * q;
    }
}

// ---------------- weight transpose + half convert: W[K,N] -> WT[N,K] ----------------
__global__ void wt_kernel(const float* __restrict__ W, __half* __restrict__ WT,
                          int K, int N) {
    __shared__ float t[32][33];
    int kb = blockIdx.y * 32, nb = blockIdx.x * 32;
    int tx = threadIdx.x & 31, ty = threadIdx.x >> 5;
    #pragma unroll
    for (int i = 0; i < 32; i += 8)
        t[ty + i][tx] = W[(size_t)(kb + ty + i) * N + nb + tx];
    __syncthreads();
    #pragma unroll
    for (int i = 0; i < 32; i += 8)
        WT[(size_t)(nb + ty + i) * K + kb + tx] = __float2half_rn(t[tx][ty + i]);
}

// ---------------- window gather (half) ----------------
__global__ void win_kernel(const float* __restrict__ x, __half* __restrict__ win,
                           int E, int pl) {
    int plc = pl * CH;
    int tot = BATCH * E * plc;
    int idx = blockIdx.x * blockDim.x + threadIdx.x;
    if (idx >= tot) return;
    int r = idx % plc;
    int e = (idx / plc) % E;
    int b = idx / (plc * E);
    int p = r >> 3, c = r & 7;
    int i = e + p;
    win[idx] = __float2half_rn((i < MAXPADC) ? 0.0f : x[(b * LSEQ + (i - MAXPADC)) * CH + c]);
}

// ---------------- seq build (fp32, compacted) ----------------
template<int SCALE>
__global__ void build_seq_kernel(const float* __restrict__ tokens,
                                 const float* __restrict__ pos,
                                 float* __restrict__ seq,
                                 int NMAX, int E, int pl, int st, int MBc) {
    int tot = NSEQ * NMAX * HID;
    int idx = blockIdx.x * blockDim.x + threadIdx.x;
    if (idx >= tot) return;
    int h = idx & 255;
    int rest = idx >> 8;
    int k = rest % NMAX;
    int bt = rest / NMAX;
    int t = bt & (LSEQ - 1);
    int b = bt >> 7;
    int n = nfun<SCALE>(t);
    if (k >= n) return;
    int ends = t + MAXPADC - (n - 1) * st + k * st;
    int j = ends - (pl - 1);
    j = j < 0 ? 0 : (j > E - 1 ? E - 1 : j);
    int m = b * MBc + Sfun<SCALE>(t) + k;
    seq[(size_t)m * HID + h] = tokens[(b * E + j) * HID + h] + pos[k * HID + h];
}

// ---------------- gather last valid patch (half, compacted) ----------------
template<int SCALE>
__global__ void gather_kernel(const float* __restrict__ seq, __half* __restrict__ comb,
                              int off, int MBc) {
    int idx = blockIdx.x * blockDim.x + threadIdx.x;
    if (idx >= NSEQ * HID) return;
    int h = idx & 255;
    int bt = idx >> 8;
    int t = bt & (LSEQ - 1);
    int b = bt >> 7;
    int n = nfun<SCALE>(t);
    int m = b * MBc + Sfun<SCALE>(t) + n - 1;
    comb[bt * 512 + off + h] = __float2half_rn(seq[(size_t)m * HID + h]);
}

// ---------------- layernorm: one WARP per row of 256, templated output ----------------
template<typename OT>
__global__ void ln_kernel(const float* __restrict__ in, const float* __restrict__ g,
                          const float* __restrict__ b, OT* __restrict__ out) {
    int warp = threadIdx.x >> 5, lane = threadIdx.x & 31;
    size_t row = (size_t)blockIdx.x * 8 + warp;
    const float4* p = (const float4*)(in + row * 256);
    float4 v0 = p[lane], v1 = p[lane + 32];
    float s = v0.x + v0.y + v0.z + v0.w + v1.x + v1.y + v1.z + v1.w;
    #pragma unroll
    for (int o = 16; o > 0; o >>= 1) s += __shfl_xor_sync(0xffffffffu, s, o);
    float mu = s * (1.0f / 256.0f);
    float d0x = v0.x - mu, d0y = v0.y - mu, d0z = v0.z - mu, d0w = v0.w - mu;
    float d1x = v1.x - mu, d1y = v1.y - mu, d1z = v1.z - mu, d1w = v1.w - mu;
    float q = d0x*d0x + d0y*d0y + d0z*d0z + d0w*d0w
            + d1x*d1x + d1y*d1y + d1z*d1z + d1w*d1w;
    #pragma unroll
    for (int o = 16; o > 0; o >>= 1) q += __shfl_xor_sync(0xffffffffu, q, o);
    float r = rsqrtf(q * (1.0f / 256.0f) + 1e-5f);
    const float4* gp = (const float4*)g;
    const float4* bp = (const float4*)b;
    float4 g0 = gp[lane], g1 = gp[lane + 32];
    float4 b0 = bp[lane], b1 = bp[lane + 32];
    float o0x = d0x * r * g0.x + b0.x, o0y = d0y * r * g0.y + b0.y;
    float o0z = d0z * r * g0.z + b0.z, o0w = d0w * r * g0.w + b0.w;
    float o1x = d1x * r * g1.x + b1.x, o1y = d1y * r * g1.y + b1.y;
    float o1z = d1z * r * g1.z + b1.z, o1w = d1w * r * g1.w + b1.w;
    if (sizeof(OT) == 2) {
        __half* oh = (__half*)out + row * 256;
        __half2 h0[2] = { __floats2half2_rn(o0x, o0y), __floats2half2_rn(o0z, o0w) };
        __half2 h1[2] = { __floats2half2_rn(o1x, o1y), __floats2half2_rn(o1z, o1w) };
        *(uint2*)(oh + lane * 4)       = *(uint2*)h0;
        *(uint2*)(oh + 128 + lane * 4) = *(uint2*)h1;
    } else {
        float* of = (float*)out + row * 256;
        *(float4*)(of + lane * 4)       = make_float4(o0x, o0y, o0z, o0w);
        *(float4*)(of + 128 + lane * 4) = make_float4(o1x, o1y, o1z, o1w);
    }
}

// ---------------- fp16 mma.sync GEMM, cp.async 3-stage pipeline ----------------
#define HSTAGE 12288
#define HSMEM  (3 * HSTAGE * 2)
template<int EPI>
__global__ void __launch_bounds__(256, 1) hgemm_kernel(
        const __half* __restrict__ A, const __half* __restrict__ BT,
        const float* __restrict__ bias, void* __restrict__ Cv,
        int N, int K) {
    extern __shared__ __half sm[];
    const uint32_t sb = smem_u32(sm);
    const int tid = threadIdx.x, lane = tid & 31, warp = tid >> 5;
    const int bm = blockIdx.y << 7, bn = blockIdx.x << 8;
    const int wm = (warp & 1) << 6, wn = (warp >> 1) << 6;
    const int nc = K >> 5;

    float acc[4][8][4];
    #pragma unroll
    for (int mi = 0; mi < 4; mi++)
        #pragma unroll
        for (int j = 0; j < 8; j++)
            #pragma unroll
            for (int q = 0; q < 4; q++) acc[mi][j][q] = 0.0f;

    const int sA0 = tid, sA1 = tid + 256;
    auto issue = [&](int c) {
        const int koff = c << 5;
        const uint32_t stg = sb + (uint32_t)((c % 3) * HSTAGE) * 2u;
        #pragma unroll
        for (int i = 0; i < 2; i++) {
            int seg = (i == 0) ? sA0 : sA1;
            int row = seg >> 2, sc = seg & 3;
            uint32_t dst = stg + (uint32_t)(row * 32 + ((sc ^ ((row >> 1) & 3)) << 3)) * 2u;
            cp16(dst, A + (size_t)(bm + row) * K + koff + sc * 8);
        }
        #pragma unroll
        for (int i = 0; i < 4; i++) {
            int seg = tid + i * 256;
            int row = seg >> 2, sc = seg & 3;
            uint32_t dst = stg + (uint32_t)(4096 + row * 32 + ((sc ^ ((row >> 1) & 3)) << 3)) * 2u;
            cp16(dst, BT + (size_t)(bn + row) * K + koff + sc * 8);
        }
    };

    #pragma unroll
    for (int s = 0; s < 2; s++) {
        if (s < nc) issue(s);
        cp_commit();
    }

    const int r_lo = lane >> 2, wv = lane & 3;

    for (int c = 0; c < nc; c++) {
        cp_wait<1>();
        __syncthreads();
        if (c + 2 < nc) issue(c + 2);
        cp_commit();

        const __half* st  = sm + (c % 3) * HSTAGE;
        const __half* stb = st + 4096;
        #pragma unroll
        for (int kk = 0; kk < 2; kk++) {
            const int h0 = kk * 16 + 2 * wv;
            uint32_t a[4][4];
            #pragma unroll
            for (int mi = 0; mi < 4; mi++) {
                const int ra = wm + mi * 16 + r_lo;
                a[mi][0] = *(const uint32_t*)(st + swofs(ra,     h0));
                a[mi][1] = *(const uint32_t*)(st + swofs(ra + 8, h0));
                a[mi][2] = *(const uint32_t*)(st + swofs(ra,     h0 + 8));
                a[mi][3] = *(const uint32_t*)(st + swofs(ra + 8, h0 + 8));
            }
            uint32_t bf[8][2];
            #pragma unroll
            for (int j = 0; j < 8; j++) {
                const int rb = wn + j * 8 + r_lo;
                bf[j][0] = *(const uint32_t*)(stb + swofs(rb, h0));
                bf[j][1] = *(const uint32_t*)(stb + swofs(rb, h0 + 8));
            }
            #pragma unroll
            for (int j = 0; j < 8; j++)
                #pragma unroll
                for (int mi = 0; mi < 4; mi++)
                    mma_f16(acc[mi][j], a[mi], bf[j][0], bf[j][1]);
        }
        __syncthreads();
    }

    #pragma unroll
    for (int mi = 0; mi < 4; mi++) {
        const int r = bm + wm + mi * 16 + r_lo;
        #pragma unroll
        for (int j = 0; j < 8; j++) {
            const int cl = bn + wn + j * 8 + wv * 2;
            float bf0 = bias[cl], bf1 = bias[cl + 1];
            float v0 = acc[mi][j][0] + bf0, v1 = acc[mi][j][1] + bf1;
            float v2 = acc[mi][j][2] + bf0, v3 = acc[mi][j][3] + bf1;
            if (EPI == 0) {
                float* C = (float*)Cv;
                *(float2*)(C + (size_t)r * N + cl)       = make_float2(v0, v1);
                *(float2*)(C + (size_t)(r + 8) * N + cl) = make_float2(v2, v3);
            } else if (EPI == 1) {
                __half* C = (__half*)Cv;
                *(__half2*)(C + (size_t)r * N + cl) =
                    __floats2half2_rn(gelu_exact(v0), gelu_exact(v1));
                *(__half2*)(C + (size_t)(r + 8) * N + cl) =
                    __floats2half2_rn(gelu_exact(v2), gelu_exact(v3));
            } else {
                float* C = (float*)Cv;
                float2* p0 = (float2*)(C + (size_t)r * N + cl);
                float2* p1 = (float2*)(C + (size_t)(r + 8) * N + cl);
                float2 o0 = *p0, o1 = *p1;
                *p0 = make_float2(o0.x + v0, o0.y + v1);
                *p1 = make_float2(o1.x + v2, o1.y + v3);
            }
        }
    }
}

// ---------------- attention (compacted): one block per (b,t,head) ----------------
// qkv fp32 [M, 768]: q at 0, k at 256, v at 512. Output half [M, 256].
template<int SCALE, int NMAX>
__global__ void attn_kernel(const float* __restrict__ QKV, __half* __restrict__ O,
                            int MBc) {
    __shared__ float Ks[NMAX][32];
    __shared__ float Vs[NMAX][32];
    int bt = blockIdx.x, head = blockIdx.y;
    int t = bt & (LSEQ - 1);
    int b = bt >> 7;
    int n = nfun<SCALE>(t);
    int rb = b * MBc + Sfun<SCALE>(t);
    size_t base = (size_t)rb * 768 + head * DHEAD;

    for (int i = threadIdx.x; i < NMAX * 32; i += blockDim.x) {
        int kk = i >> 5, d = i & 31;
        float kv = 0.0f, vv = 0.0f;
        if (kk < n) {
            kv = QKV[base + (size_t)kk * 768 + 256 + d];
            vv = QKV[base + (size_t)kk * 768 + 512 + d];
        }
        Ks[kk][d] = kv;
        Vs[kk][d] = vv;
    }
    __syncthreads();

    int tq = threadIdx.x;
    if (tq < n) {
        float qr[32];
        #pragma unroll
        for (int d = 0; d < 32; d++) qr[d] = QKV[base + (size_t)tq * 768 + d];
        float sc[NMAX];
        float mx = -1e30f;
        #pragma unroll
        for (int kk = 0; kk < NMAX; kk++) {
            float s = 0.0f;
            #pragma unroll
            for (int d = 0; d < 32; d++) s += qr[d] * Ks[kk][d];
            s *= 0.17677669529663687f;
            sc[kk] = (kk < n) ? s : -1e30f;
            mx = fmaxf(mx, sc[kk]);
        }
        float ssum = 0.0f;
        #pragma unroll
        for (int kk = 0; kk < NMAX; kk++) {
            float e = (kk < n) ? expf(sc[kk] - mx) : 0.0f;
            sc[kk] = e;
            ssum += e;
        }
        float inv = 1.0f / ssum;
        __half* op = O + (size_t)(rb + tq) * HID + head * DHEAD;
        #pragma unroll
        for (int d = 0; d < 32; d += 2) {
            float o0 = 0.0f, o1 = 0.0f;
            #pragma unroll
            for (int kk = 0; kk < NMAX; kk++) {
                o0 += sc[kk] * Vs[kk][d];
                o1 += sc[kk] * Vs[kk][d + 1];
            }
            *(__half2*)(op + d) = __floats2half2_rn(o0 * inv, o1 * inv);
        }
    }
}

// ---------------- host side ----------------
static inline void gemm(const __half* A, const __half* WT, const float* bias, void* C,
                        int Mp, int N, int K, int epi) {
    dim3 grid(N >> 8, Mp >> 7), block(256);
    if (epi == 0)      hgemm_kernel<0><<<grid, block, HSMEM>>>(A, WT, bias, C, N, K);
    else if (epi == 1) hgemm_kernel<1><<<grid, block, HSMEM>>>(A, WT, bias, C, N, K);
    else               hgemm_kernel<2><<<grid, block, HSMEM>>>(A, WT, bias, C, N, K);
}
static inline void wtr(const float* W, __half* WT, int K, int N) {
    wt_kernel<<<dim3(N / 32, K / 32), 256>>>(W, WT, K, N);
}

extern "C" void kernel_launch(void* const* d_in, const int* in_sizes, int n_in,
                              void* d_out, int out_size) {
    cudaFuncSetAttribute(hgemm_kernel<0>, cudaFuncAttributeMaxDynamicSharedMemorySize, HSMEM);
    cudaFuncSetAttribute(hgemm_kernel<1>, cudaFuncAttributeMaxDynamicSharedMemorySize, HSMEM);
    cudaFuncSetAttribute(hgemm_kernel<2>, cudaFuncAttributeMaxDynamicSharedMemorySize, HSMEM);

    const float* x       = (const float*)d_in[0];
    const float* w_proj[2] = { (const float*)d_in[1], (const float*)d_in[3] };
    const float* b_proj[2] = { (const float*)d_in[2], (const float*)d_in[4] };
    const float* pos[2]    = { (const float*)d_in[5], (const float*)d_in[6] };
    const float* ln1_g = (const float*)d_in[7];
    const float* ln1_b = (const float*)d_in[8];
    const float* wq = (const float*)d_in[9];
    const float* bq = (const float*)d_in[10];
    const float* wk = (const float*)d_in[11];
    const float* bk = (const float*)d_in[12];
    const float* wv = (const float*)d_in[13];
    const float* bv = (const float*)d_in[14];
    const float* wo = (const float*)d_in[15];
    const float* bo = (const float*)d_in[16];
    const float* ln2_g = (const float*)d_in[17];
    const float* ln2_b = (const float*)d_in[18];
    const float* w_ff1 = (const float*)d_in[19];
    const float* b_ff1 = (const float*)d_in[20];
    const float* w_ff2 = (const float*)d_in[21];
    const float* b_ff2 = (const float*)d_in[22];
    const float* ln_g = (const float*)d_in[23];
    const float* ln_b = (const float*)d_in[24];
    const float* w_fus1 = (const float*)d_in[25];
    const float* b_fus1 = (const float*)d_in[26];
    const float* w_fus2 = (const float*)d_in[27];
    const float* b_fus2 = (const float*)d_in[28];

    __half *winh, *s2h, *ffh, *combh, *wth;
    float *tokens, *seq, *qkv, *bqkv;
    cudaGetSymbolAddress((void**)&winh,   g_winh);
    cudaGetSymbolAddress((void**)&tokens, g_tokens);
    cudaGetSymbolAddress((void**)&seq,    g_seq);
    cudaGetSymbolAddress((void**)&qkv,    g_qkv);
    cudaGetSymbolAddress((void**)&s2h,    g_s2h);
    cudaGetSymbolAddress((void**)&ffh,    g_ffh);
    cudaGetSymbolAddress((void**)&combh,  g_combh);
    cudaGetSymbolAddress((void**)&wth,    g_wth);
    cudaGetSymbolAddress((void**)&bqkv,   g_bqkv);

    // ---- transposed half weight layout in g_wth ----
    __half* wt_proj0 = wth;                      // 256 x 64
    __half* wt_proj1 = wth + 16384;              // 256 x 128
    __half* wt_qkv   = wth + 49152;              // 2 x (768 x 256)
    __half* wt_o     = wth + 442368;             // 2 x (256 x 256)
    __half* wt_ff1   = wth + 573440;             // 2 x (1024 x 256)
    __half* wt_ff2   = wth + 1097728;            // 2 x (256 x 1024)
    __half* wt_fus1  = wth + 1622016;            // 256 x 512
    __half* wt_fus2  = wth + 1753088;            // 256 x 256

    wtr(w_proj[0], wt_proj0, 64, 256);
    wtr(w_proj[1], wt_proj1, 128, 256);
    for (int li = 0; li < 2; li++) {
        wtr(wq + li * 65536, wt_qkv + li * 196608,          256, 256);
        wtr(wk + li * 65536, wt_qkv + li * 196608 + 65536,  256, 256);
        wtr(wv + li * 65536, wt_qkv + li * 196608 + 131072, 256, 256);
        wtr(wo + li * 65536, wt_o + li * 65536, 256, 256);
        wtr(w_ff1 + li * 262144, wt_ff1 + li * 262144, 256, 1024);
        wtr(w_ff2 + li * 262144, wt_ff2 + li * 262144, 1024, 256);
        cudaMemcpyAsync(bqkv + li * 768,       bq + li * 256, 1024, cudaMemcpyDeviceToDevice);
        cudaMemcpyAsync(bqkv + li * 768 + 256, bk + li * 256, 1024, cudaMemcpyDeviceToDevice);
        cudaMemcpyAsync(bqkv + li * 768 + 512, bv + li * 256, 1024, cudaMemcpyDeviceToDevice);
    }
    wtr(w_fus1, wt_fus1, 512, 256);
    wtr(w_fus2, wt_fus2, 256, 256);

    const int PL[2] = {8, 16}, ST[2] = {4, 8}, EE[2] = {136, 128}, NMX[2] = {34, 16};
    const int MP[2] = {1152, 1024};
    const int MCC[2] = {MC0, MC1}, MBB[2] = {MB0, MB1};

    for (int s = 0; s < 2; s++) {
        int pl = PL[s], st = ST[s], E = EE[s], NMAX = NMX[s];
        int plc = pl * CH;
        int BE = BATCH * E;
        int M = MCC[s], MBc = MBB[s];

        { int tot = BE * plc;
          win_kernel<<<(tot + 255) / 256, 256>>>(x, winh, E, pl); }
        gemm(winh, s == 0 ? wt_proj0 : wt_proj1, b_proj[s], tokens, MP[s], HID, plc, 0);
        { int tot = NSEQ * NMAX * HID;
          int blocks = (tot + 255) / 256;
          if (s == 0) build_seq_kernel<0><<<blocks, 256>>>(tokens, pos[s], seq, NMAX, E, pl, st, MBc);
          else        build_seq_kernel<1><<<blocks, 256>>>(tokens, pos[s], seq, NMAX, E, pl, st, MBc);
        }

        for (int li = 0; li < 2; li++) {
            ln_kernel<__half><<<M / 8, 256>>>(seq, ln1_g + li * HID, ln1_b + li * HID, s2h);
            gemm(s2h, wt_qkv + li * 196608, bqkv + li * 768, qkv, M, 768, HID, 0);
            dim3 ag(NSEQ, NHEAD);
            if (s == 0) attn_kernel<0, 34><<<ag, 64>>>(qkv, s2h, MBc);
            else        attn_kernel<1, 16><<<ag, 64>>>(qkv, s2h, MBc);
            gemm(s2h, wt_o + li * 65536, bo + li * HID, seq, M, HID, HID, 2);
            ln_kernel<__half><<<M / 8, 256>>>(seq, ln2_g + li * HID, ln2_b + li * HID, s2h);
            gemm(s2h, wt_ff1 + li * 262144, b_ff1 + li * FFD, ffh, M, FFD, HID, 1);
            gemm(ffh, wt_ff2 + li * 262144, b_ff2 + li * HID, seq, M, HID, FFD, 2);
        }
        { int tot = NSEQ * HID;
          int blocks = (tot + 255) / 256;
          if (s == 0) gather_kernel<0><<<blocks, 256>>>(seq, combh, 0, MBc);
          else        gather_kernel<1><<<blocks, 256>>>(seq, combh, 256, MBc);
        }
    }

    gemm(combh, wt_fus1, b_fus1, s2h, NSEQ, HID, 2 * HID, 1);
    gemm(s2h, wt_fus2, b_fus2, seq, NSEQ, HID, HID, 0);
    ln_kernel<float><<<NSEQ / 8, 256>>>(seq, ln_g, ln_b, (float*)d_out);
}

// round 9
// speedup vs baseline: 6.4607x; 1.0882x over previous
#include <cuda_runtime.h>
#include <cuda_fp16.h>
#include <math.h>
#include <stdint.h>

// ---------------- problem constants ----------------
#define LSEQ   128
#define BATCH  8
#define CH     8
#define HID    256
#define NHEAD  8
#define DHEAD  32
#define FFD    1024
#define MAXPADC 15
#define NSEQ   1024          // BATCH * LSEQ

// compacted row counts
#define MB0 2368
#define MB1 1088
#define MC0 18944            // 148 * 128
#define MC1 8704             // 68 * 128

// ---------------- scratch (allocation-free) ----------------
__device__ __half  g_winh[147456];
__device__ float   g_tokens[294912];
__device__ float   g_seq[MC0 * 256];
__device__ float   g_qkv[MC0 * 768];
__device__ __half  g_s2h[MC0 * 256];
__device__ __half  g_ffh[MC0 * 1024];
__device__ __half  g_combh[1024 * 512];
__device__ __half  g_wth[1818624];
__device__ float   g_bqkv[1536];

// ---------------- helpers ----------------
__device__ __forceinline__ float gelu_exact(float x) {
    return 0.5f * x * (1.0f + erff(x * 0.7071067811865476f));
}
__device__ __forceinline__ uint32_t smem_u32(const void* p) {
    uint32_t a;
    asm("{ .reg .u64 t; cvta.to.shared.u64 t, %1; cvt.u32.u64 %0, t; }" : "=r"(a) : "l"(p));
    return a;
}
__device__ __forceinline__ void cp16(uint32_t dst, const void* src) {
    asm volatile("cp.async.cg.shared.global [%0], [%1], 16;" :: "r"(dst), "l"(src));
}
__device__ __forceinline__ void cp_commit() {
    asm volatile("cp.async.commit_group;" ::: "memory");
}
template<int N>
__device__ __forceinline__ void cp_wait() {
    asm volatile("cp.async.wait_group %0;" :: "n"(N) : "memory");
}
__device__ __forceinline__ void mma_f16(float* c, const uint32_t* a,
                                        uint32_t b0, uint32_t b1) {
    asm volatile(
        "mma.sync.aligned.m16n8k16.row.col.f32.f16.f16.f32 "
        "{%0,%1,%2,%3}, {%4,%5,%6,%7}, {%8,%9}, {%0,%1,%2,%3};\n"
        : "+f"(c[0]), "+f"(c[1]), "+f"(c[2]), "+f"(c[3])
        : "r"(a[0]), "r"(a[1]), "r"(a[2]), "r"(a[3]), "r"(b0), "r"(b1));
}
__device__ __forceinline__ void ldsm4(uint32_t& r0, uint32_t& r1, uint32_t& r2,
                                      uint32_t& r3, uint32_t addr) {
    asm volatile("ldmatrix.sync.aligned.m8n8.x4.shared.b16 {%0,%1,%2,%3}, [%4];"
                 : "=r"(r0), "=r"(r1), "=r"(r2), "=r"(r3) : "r"(addr));
}
// valid patches / prefix offsets (closed form)
template<int SCALE>
__device__ __forceinline__ int nfun(int t) {
    return SCALE == 0 ? ((t + 8) >> 2) + 1 : (t >> 3) + 1;
}
template<int SCALE>
__device__ __forceinline__ int Sfun(int t) {
    if (SCALE == 0) {
        int m = t + 8, q = m >> 2, r = m & 3;
        return t + 2 * q * (q - 1) + r * q - 4;
    } else {
        int q = t >> 3, r = t & 7;
        return t + 4 * q * (q - 1) + r * q;
    }
}

// ---------------- fused weight transpose + half convert ----------------
#define NJOBS 16
struct WtJobs {
    const float* src[NJOBS];
    __half*      dst[NJOBS];
    int K[NJOBS], N[NJOBS], t0[NJOBS];
};
__global__ void wt_fused(WtJobs jobs, int njobs) {
    __shared__ float t[32][33];
    int tile = blockIdx.x;
    int ji = 0;
    #pragma unroll 1
    while (ji + 1 < njobs && tile >= jobs.t0[ji + 1]) ji++;
    int lt = tile - jobs.t0[ji];
    int K = jobs.K[ji], N = jobs.N[ji];
    int tn = N >> 5;
    int nb = (lt % tn) * 32, kb = (lt / tn) * 32;
    const float* W = jobs.src[ji];
    __half* WT = jobs.dst[ji];
    int tx = threadIdx.x & 31, ty = threadIdx.x >> 5;
    #pragma unroll
    for (int i = 0; i < 32; i += 8)
        t[ty + i][tx] = W[(size_t)(kb + ty + i) * N + nb + tx];
    __syncthreads();
    #pragma unroll
    for (int i = 0; i < 32; i += 8)
        WT[(size_t)(nb + ty + i) * K + kb + tx] = __float2half_rn(t[tx][ty + i]);
}

// ---------------- window gather (half) ----------------
__global__ void win_kernel(const float* __restrict__ x, __half* __restrict__ win,
                           int E, int pl) {
    int plc = pl * CH;
    int tot = BATCH * E * plc;
    int idx = blockIdx.x * blockDim.x + threadIdx.x;
    if (idx >= tot) return;
    int r = idx % plc;
    int e = (idx / plc) % E;
    int b = idx / (plc * E);
    int p = r >> 3, c = r & 7;
    int i = e + p;
    win[idx] = __float2half_rn((i < MAXPADC) ? 0.0f : x[(b * LSEQ + (i - MAXPADC)) * CH + c]);
}

// ---------------- seq build + fused LN1: one warp per valid row ----------------
template<int SCALE>
__global__ void build_seq_ln(const float* __restrict__ tokens,
                             const float* __restrict__ pos,
                             const float* __restrict__ lg, const float* __restrict__ lb,
                             float* __restrict__ seq, __half* __restrict__ s2h,
                             int NMAX, int E, int pl, int st, int MBc) {
    int wid = threadIdx.x >> 5, lane = threadIdx.x & 31;
    int wg = blockIdx.x * 8 + wid;
    if (wg >= NSEQ * NMAX) return;
    int k = wg % NMAX, bt = wg / NMAX;
    int t = bt & (LSEQ - 1), b = bt >> 7;
    int n = nfun<SCALE>(t);
    if (k >= n) return;
    int ends = t + MAXPADC - (n - 1) * st + k * st;
    int j = ends - (pl - 1);
    j = j < 0 ? 0 : (j > E - 1 ? E - 1 : j);
    int m = b * MBc + Sfun<SCALE>(t) + k;

    const float4* tp = (const float4*)(tokens + (size_t)(b * E + j) * 256) + lane * 2;
    const float4* pp = (const float4*)(pos + k * 256) + lane * 2;
    float4 t0 = tp[0], t1 = tp[1], p0 = pp[0], p1 = pp[1];
    float v[8] = { t0.x + p0.x, t0.y + p0.y, t0.z + p0.z, t0.w + p0.w,
                   t1.x + p1.x, t1.y + p1.y, t1.z + p1.z, t1.w + p1.w };
    float s = 0.0f, q = 0.0f;
    #pragma unroll
    for (int i = 0; i < 8; i++) { s += v[i]; q += v[i] * v[i]; }
    #pragma unroll
    for (int o = 16; o > 0; o >>= 1) {
        s += __shfl_xor_sync(0xffffffffu, s, o);
        q += __shfl_xor_sync(0xffffffffu, q, o);
    }
    float mu = s * (1.0f / 256.0f);
    float var = q * (1.0f / 256.0f) - mu * mu;
    float rinv = rsqrtf(var + 1e-5f);

    float4* sp = (float4*)(seq + (size_t)m * 256) + lane * 2;
    sp[0] = make_float4(v[0], v[1], v[2], v[3]);
    sp[1] = make_float4(v[4], v[5], v[6], v[7]);

    const float4* gp = (const float4*)(lg) + lane * 2;
    const float4* bp = (const float4*)(lb) + lane * 2;
    float4 g0 = gp[0], g1 = gp[1], bb0 = bp[0], bb1 = bp[1];
    __half2 h[4];
    h[0] = __floats2half2_rn((v[0]-mu)*rinv*g0.x+bb0.x, (v[1]-mu)*rinv*g0.y+bb0.y);
    h[1] = __floats2half2_rn((v[2]-mu)*rinv*g0.z+bb0.z, (v[3]-mu)*rinv*g0.w+bb0.w);
    h[2] = __floats2half2_rn((v[4]-mu)*rinv*g1.x+bb1.x, (v[5]-mu)*rinv*g1.y+bb1.y);
    h[3] = __floats2half2_rn((v[6]-mu)*rinv*g1.z+bb1.z, (v[7]-mu)*rinv*g1.w+bb1.w);
    *(uint4*)(s2h + (size_t)m * 256 + lane * 8) = *(uint4*)h;
}

// ---------------- gather last valid patch (half, compacted) ----------------
template<int SCALE>
__global__ void gather_kernel(const float* __restrict__ seq, __half* __restrict__ comb,
                              int off, int MBc) {
    int idx = blockIdx.x * blockDim.x + threadIdx.x;
    if (idx >= NSEQ * HID) return;
    int h = idx & 255;
    int bt = idx >> 8;
    int t = bt & (LSEQ - 1);
    int b = bt >> 7;
    int n = nfun<SCALE>(t);
    int m = b * MBc + Sfun<SCALE>(t) + n - 1;
    comb[bt * 512 + off + h] = __float2half_rn(seq[(size_t)m * HID + h]);
}

// ---------------- final layernorm: warp per row, fp32 out ----------------
__global__ void ln_final(const float* __restrict__ in, const float* __restrict__ g,
                         const float* __restrict__ b, float* __restrict__ out) {
    int warp = threadIdx.x >> 5, lane = threadIdx.x & 31;
    size_t row = (size_t)blockIdx.x * 8 + warp;
    const float4* p = (const float4*)(in + row * 256);
    float4 v0 = p[lane], v1 = p[lane + 32];
    float s = v0.x + v0.y + v0.z + v0.w + v1.x + v1.y + v1.z + v1.w;
    #pragma unroll
    for (int o = 16; o > 0; o >>= 1) s += __shfl_xor_sync(0xffffffffu, s, o);
    float mu = s * (1.0f / 256.0f);
    float d0x = v0.x - mu, d0y = v0.y - mu, d0z = v0.z - mu, d0w = v0.w - mu;
    float d1x = v1.x - mu, d1y = v1.y - mu, d1z = v1.z - mu, d1w = v1.w - mu;
    float q = d0x*d0x + d0y*d0y + d0z*d0z + d0w*d0w
            + d1x*d1x + d1y*d1y + d1z*d1z + d1w*d1w;
    #pragma unroll
    for (int o = 16; o > 0; o >>= 1) q += __shfl_xor_sync(0xffffffffu, q, o);
    float r = rsqrtf(q * (1.0f / 256.0f) + 1e-5f);
    const float4* gp = (const float4*)g;
    const float4* bp = (const float4*)b;
    float4 g0 = gp[lane], g1 = gp[lane + 32];
    float4 b0 = bp[lane], b1 = bp[lane + 32];
    float4* po = (float4*)(out + row * 256);
    po[lane]      = make_float4(d0x*r*g0.x+b0.x, d0y*r*g0.y+b0.y, d0z*r*g0.z+b0.z, d0w*r*g0.w+b0.w);
    po[lane + 32] = make_float4(d1x*r*g1.x+b1.x, d1y*r*g1.y+b1.y, d1z*r*g1.z+b1.z, d1w*r*g1.w+b1.w);
}

// ---------------- fp16 mma.sync GEMM, cp.async 3-stage, ldmatrix ----------------
// EPI: 0 bias->fp32; 1 bias+gelu->half; 2 bias+residual->fp32;
//      3 bias+residual->fp32 + fused LN -> half (requires N==256, grid.x==1)
#define HSTAGE 12288
#define HSMEM  (3 * HSTAGE * 2)
template<int EPI>
__global__ void __launch_bounds__(256, 1) hgemm_kernel(
        const __half* __restrict__ A, const __half* __restrict__ BT,
        const float* __restrict__ bias, void* __restrict__ Cv,
        int N, int K,
        const float* __restrict__ lng, const float* __restrict__ lnb,
        __half* __restrict__ lnout) {
    extern __shared__ __half sm[];
    const uint32_t sb = smem_u32(sm);
    const int tid = threadIdx.x, lane = tid & 31, warp = tid >> 5;
    const int bm = blockIdx.y << 7, bn = blockIdx.x << 8;
    const int wm = (warp & 1) << 6, wn = (warp >> 1) << 6;
    const int nc = K >> 5;

    float acc[4][8][4];
    #pragma unroll
    for (int mi = 0; mi < 4; mi++)
        #pragma unroll
        for (int j = 0; j < 8; j++)
            #pragma unroll
            for (int q = 0; q < 4; q++) acc[mi][j][q] = 0.0f;

    const int sA0 = tid, sA1 = tid + 256;
    auto issue = [&](int c) {
        const int koff = c << 5;
        const uint32_t stg = sb + (uint32_t)((c % 3) * HSTAGE) * 2u;
        #pragma unroll
        for (int i = 0; i < 2; i++) {
            int seg = (i == 0) ? sA0 : sA1;
            int row = seg >> 2, sc = seg & 3;
            uint32_t dst = stg + (uint32_t)(row * 32 + ((sc ^ ((row >> 1) & 3)) << 3)) * 2u;
            cp16(dst, A + (size_t)(bm + row) * K + koff + sc * 8);
        }
        #pragma unroll
        for (int i = 0; i < 4; i++) {
            int seg = tid + i * 256;
            int row = seg >> 2, sc = seg & 3;
            uint32_t dst = stg + (uint32_t)(4096 + row * 32 + ((sc ^ ((row >> 1) & 3)) << 3)) * 2u;
            cp16(dst, BT + (size_t)(bn + row) * K + koff + sc * 8);
        }
    };

    #pragma unroll
    for (int s = 0; s < 2; s++) {
        if (s < nc) issue(s);
        cp_commit();
    }

    const int r_lo = lane >> 2, wv = lane & 3;
    // ldmatrix lane geometry
    const int arow = wm + (lane & 15);
    const int asel = (lane >> 4) & 1;
    int brow[4], bsel[4];
    {
        int i = lane >> 3;
        #pragma unroll
        for (int g = 0; g < 4; g++) {
            brow[g] = wn + ((g << 1) + (i >> 1)) * 8 + (lane & 7);
            bsel[g] = i & 1;
        }
    }

    for (int c = 0; c < nc; c++) {
        cp_wait<1>();
        __syncthreads();
        if (c + 2 < nc) issue(c + 2);
        cp_commit();

        const uint32_t stA = sb + (uint32_t)((c % 3) * HSTAGE) * 2u;
        const uint32_t stB = stA + 8192u;
        #pragma unroll
        for (int kk = 0; kk < 2; kk++) {
            uint32_t a[4][4];
            #pragma unroll
            for (int mi = 0; mi < 4; mi++) {
                int r = arow + mi * 16;
                uint32_t ad = stA + (uint32_t)(r * 64 + ((((kk << 1) | asel) ^ ((r >> 1) & 3)) << 4));
                ldsm4(a[mi][0], a[mi][1], a[mi][2], a[mi][3], ad);
            }
            uint32_t bf[8][2];
            #pragma unroll
            for (int g = 0; g < 4; g++) {
                int r = brow[g];
                uint32_t bd = stB + (uint32_t)(r * 64 + ((((kk << 1) | bsel[g]) ^ ((r >> 1) & 3)) << 4));
                ldsm4(bf[2*g][0], bf[2*g][1], bf[2*g+1][0], bf[2*g+1][1], bd);
            }
            #pragma unroll
            for (int j = 0; j < 8; j++)
                #pragma unroll
                for (int mi = 0; mi < 4; mi++)
                    mma_f16(acc[mi][j], a[mi], bf[j][0], bf[j][1]);
        }
        __syncthreads();
    }

    if (EPI == 3) {
        // residual add + store seq; keep values in acc
        float* C = (float*)Cv;
        #pragma unroll
        for (int mi = 0; mi < 4; mi++) {
            const int r = bm + wm + mi * 16 + r_lo;
            #pragma unroll
            for (int j = 0; j < 8; j++) {
                const int cl = wn + j * 8 + wv * 2;
                float bf0 = bias[cl], bf1 = bias[cl + 1];
                float2* p0 = (float2*)(C + (size_t)r * 256 + cl);
                float2* p1 = (float2*)(C + (size_t)(r + 8) * 256 + cl);
                float2 o0 = *p0, o1 = *p1;
                acc[mi][j][0] += bf0 + o0.x; acc[mi][j][1] += bf1 + o0.y;
                acc[mi][j][2] += bf0 + o1.x; acc[mi][j][3] += bf1 + o1.y;
                *p0 = make_float2(acc[mi][j][0], acc[mi][j][1]);
                *p1 = make_float2(acc[mi][j][2], acc[mi][j][3]);
            }
        }
        // per-row LN stats: quad shfl then cross-warp via smem
        float2* red = (float2*)sm;          // [128][4]
        float sums[8], sqs[8];
        #pragma unroll
        for (int mi = 0; mi < 4; mi++) {
            #pragma unroll
            for (int rr = 0; rr < 2; rr++) {
                float s = 0.0f, q = 0.0f;
                #pragma unroll
                for (int j = 0; j < 8; j++) {
                    float v0 = acc[mi][j][rr * 2], v1 = acc[mi][j][rr * 2 + 1];
                    s += v0 + v1; q += v0 * v0 + v1 * v1;
                }
                s += __shfl_xor_sync(0xffffffffu, s, 1);
                s += __shfl_xor_sync(0xffffffffu, s, 2);
                q += __shfl_xor_sync(0xffffffffu, q, 1);
                q += __shfl_xor_sync(0xffffffffu, q, 2);
                sums[mi * 2 + rr] = s; sqs[mi * 2 + rr] = q;
            }
        }
        const int wn_i = warp >> 1;
        if (wv == 0) {
            #pragma unroll
            for (int idx = 0; idx < 8; idx++) {
                int rl = wm + (idx >> 1) * 16 + r_lo + (idx & 1) * 8;
                red[rl * 4 + wn_i] = make_float2(sums[idx], sqs[idx]);
            }
        }
        __syncthreads();
        float mus[8], rinvs[8];
        #pragma unroll
        for (int idx = 0; idx < 8; idx++) {
            int rl = wm + (idx >> 1) * 16 + r_lo + (idx & 1) * 8;
            float S = 0.0f, Q = 0.0f;
            #pragma unroll
            for (int w = 0; w < 4; w++) {
                float2 e = red[rl * 4 + w];
                S += e.x; Q += e.y;
            }
            float mu = S * (1.0f / 256.0f);
            mus[idx] = mu;
            rinvs[idx] = rsqrtf(Q * (1.0f / 256.0f) - mu * mu + 1e-5f);
        }
        #pragma unroll
        for (int mi = 0; mi < 4; mi++) {
            const int r = bm + wm + mi * 16 + r_lo;
            #pragma unroll
            for (int j = 0; j < 8; j++) {
                const int cl = wn + j * 8 + wv * 2;
                float gg0 = lng[cl], gg1 = lng[cl + 1];
                float bb0 = lnb[cl], bb1 = lnb[cl + 1];
                float mu0 = mus[mi * 2], ri0 = rinvs[mi * 2];
                float mu1 = mus[mi * 2 + 1], ri1 = rinvs[mi * 2 + 1];
                *(__half2*)(lnout + (size_t)r * 256 + cl) =
                    __floats2half2_rn((acc[mi][j][0] - mu0) * ri0 * gg0 + bb0,
                                      (acc[mi][j][1] - mu0) * ri0 * gg1 + bb1);
                *(__half2*)(lnout + (size_t)(r + 8) * 256 + cl) =
                    __floats2half2_rn((acc[mi][j][2] - mu1) * ri1 * gg0 + bb0,
                                      (acc[mi][j][3] - mu1) * ri1 * gg1 + bb1);
            }
        }
        return;
    }

    #pragma unroll
    for (int mi = 0; mi < 4; mi++) {
        const int r = bm + wm + mi * 16 + r_lo;
        #pragma unroll
        for (int j = 0; j < 8; j++) {
            const int cl = bn + wn + j * 8 + wv * 2;
            float bf0 = bias[cl], bf1 = bias[cl + 1];
            float v0 = acc[mi][j][0] + bf0, v1 = acc[mi][j][1] + bf1;
            float v2 = acc[mi][j][2] + bf0, v3 = acc[mi][j][3] + bf1;
            if (EPI == 0) {
                float* C = (float*)Cv;
                *(float2*)(C + (size_t)r * N + cl)       = make_float2(v0, v1);
                *(float2*)(C + (size_t)(r + 8) * N + cl) = make_float2(v2, v3);
            } else if (EPI == 1) {
                __half* C = (__half*)Cv;
                *(__half2*)(C + (size_t)r * N + cl) =
                    __floats2half2_rn(gelu_exact(v0), gelu_exact(v1));
                *(__half2*)(C + (size_t)(r + 8) * N + cl) =
                    __floats2half2_rn(gelu_exact(v2), gelu_exact(v3));
            } else {
                float* C = (float*)Cv;
                float2* p0 = (float2*)(C + (size_t)r * N + cl);
                float2* p1 = (float2*)(C + (size_t)(r + 8) * N + cl);
                float2 o0 = *p0, o1 = *p1;
                *p0 = make_float2(o0.x + v0, o0.y + v1);
                *p1 = make_float2(o1.x + v2, o1.y + v3);
            }
        }
    }
}

// ---------------- attention (compacted) ----------------
template<int SCALE, int NMAX>
__global__ void attn_kernel(const float* __restrict__ QKV, __half* __restrict__ O,
                            int MBc) {
    __shared__ float Ks[NMAX][32];
    __shared__ float Vs[NMAX][32];
    int bt = blockIdx.x, head = blockIdx.y;
    int t = bt & (LSEQ - 1);
    int b = bt >> 7;
    int n = nfun<SCALE>(t);
    int rb = b * MBc + Sfun<SCALE>(t);
    size_t base = (size_t)rb * 768 + head * DHEAD;

    for (int i = threadIdx.x; i < NMAX * 32; i += blockDim.x) {
        int kk = i >> 5, d = i & 31;
        float kv = 0.0f, vv = 0.0f;
        if (kk < n) {
            kv = QKV[base + (size_t)kk * 768 + 256 + d];
            vv = QKV[base + (size_t)kk * 768 + 512 + d];
        }
        Ks[kk][d] = kv;
        Vs[kk][d] = vv;
    }
    __syncthreads();

    int tq = threadIdx.x;
    if (tq < n) {
        float qr[32];
        #pragma unroll
        for (int d = 0; d < 32; d++) qr[d] = QKV[base + (size_t)tq * 768 + d];
        float sc[NMAX];
        float mx = -1e30f;
        #pragma unroll
        for (int kk = 0; kk < NMAX; kk++) {
            float s = 0.0f;
            #pragma unroll
            for (int d = 0; d < 32; d++) s += qr[d] * Ks[kk][d];
            s *= 0.17677669529663687f;
            sc[kk] = (kk < n) ? s : -1e30f;
            mx = fmaxf(mx, sc[kk]);
        }
        float ssum = 0.0f;
        #pragma unroll
        for (int kk = 0; kk < NMAX; kk++) {
            float e = (kk < n) ? expf(sc[kk] - mx) : 0.0f;
            sc[kk] = e;
            ssum += e;
        }
        float inv = 1.0f / ssum;
        __half* op = O + (size_t)(rb + tq) * HID + head * DHEAD;
        #pragma unroll
        for (int d = 0; d < 32; d += 2) {
            float o0 = 0.0f, o1 = 0.0f;
            #pragma unroll
            for (int kk = 0; kk < NMAX; kk++) {
                o0 += sc[kk] * Vs[kk][d];
                o1 += sc[kk] * Vs[kk][d + 1];
            }
            *(__half2*)(op + d) = __floats2half2_rn(o0 * inv, o1 * inv);
        }
    }
}

// ---------------- host side ----------------
static inline void gemm(const __half* A, const __half* WT, const float* bias, void* C,
                        int Mp, int N, int K, int epi,
                        const float* lng = nullptr, const float* lnb = nullptr,
                        __half* lnout = nullptr) {
    dim3 grid(N >> 8, Mp >> 7), block(256);
    if (epi == 0)      hgemm_kernel<0><<<grid, block, HSMEM>>>(A, WT, bias, C, N, K, lng, lnb, lnout);
    else if (epi == 1) hgemm_kernel<1><<<grid, block, HSMEM>>>(A, WT, bias, C, N, K, lng, lnb, lnout);
    else if (epi == 2) hgemm_kernel<2><<<grid, block, HSMEM>>>(A, WT, bias, C, N, K, lng, lnb, lnout);
    else               hgemm_kernel<3><<<grid, block, HSMEM>>>(A, WT, bias, C, N, K, lng, lnb, lnout);
}

extern "C" void kernel_launch(void* const* d_in, const int* in_sizes, int n_in,
                              void* d_out, int out_size) {
    cudaFuncSetAttribute(hgemm_kernel<0>, cudaFuncAttributeMaxDynamicSharedMemorySize, HSMEM);
    cudaFuncSetAttribute(hgemm_kernel<1>, cudaFuncAttributeMaxDynamicSharedMemorySize, HSMEM);
    cudaFuncSetAttribute(hgemm_kernel<2>, cudaFuncAttributeMaxDynamicSharedMemorySize, HSMEM);
    cudaFuncSetAttribute(hgemm_kernel<3>, cudaFuncAttributeMaxDynamicSharedMemorySize, HSMEM);

    const float* x       = (const float*)d_in[0];
    const float* w_proj[2] = { (const float*)d_in[1], (const float*)d_in[3] };
    const float* b_proj[2] = { (const float*)d_in[2], (const float*)d_in[4] };
    const float* pos[2]    = { (const float*)d_in[5], (const float*)d_in[6] };
    const float* ln1_g = (const float*)d_in[7];
    const float* ln1_b = (const float*)d_in[8];
    const float* wq = (const float*)d_in[9];
    const float* bq = (const float*)d_in[10];
    const float* wk = (const float*)d_in[11];
    const float* bk = (const float*)d_in[12];
    const float* wv = (const float*)d_in[13];
    const float* bv = (const float*)d_in[14];
    const float* wo = (const float*)d_in[15];
    const float* bo = (const float*)d_in[16];
    const float* ln2_g = (const float*)d_in[17];
    const float* ln2_b = (const float*)d_in[18];
    const float* w_ff1 = (const float*)d_in[19];
    const float* b_ff1 = (const float*)d_in[20];
    const float* w_ff2 = (const float*)d_in[21];
    const float* b_ff2 = (const float*)d_in[22];
    const float* ln_g = (const float*)d_in[23];
    const float* ln_b = (const float*)d_in[24];
    const float* w_fus1 = (const float*)d_in[25];
    const float* b_fus1 = (const float*)d_in[26];
    const float* w_fus2 = (const float*)d_in[27];
    const float* b_fus2 = (const float*)d_in[28];

    __half *winh, *s2h, *ffh, *combh, *wth;
    float *tokens, *seq, *qkv, *bqkv;
    cudaGetSymbolAddress((void**)&winh,   g_winh);
    cudaGetSymbolAddress((void**)&tokens, g_tokens);
    cudaGetSymbolAddress((void**)&seq,    g_seq);
    cudaGetSymbolAddress((void**)&qkv,    g_qkv);
    cudaGetSymbolAddress((void**)&s2h,    g_s2h);
    cudaGetSymbolAddress((void**)&ffh,    g_ffh);
    cudaGetSymbolAddress((void**)&combh,  g_combh);
    cudaGetSymbolAddress((void**)&wth,    g_wth);
    cudaGetSymbolAddress((void**)&bqkv,   g_bqkv);

    __half* wt_proj0 = wth;
    __half* wt_proj1 = wth + 16384;
    __half* wt_qkv   = wth + 49152;
    __half* wt_o     = wth + 442368;
    __half* wt_ff1   = wth + 573440;
    __half* wt_ff2   = wth + 1097728;
    __half* wt_fus1  = wth + 1622016;
    __half* wt_fus2  = wth + 1753088;

    // fused weight prep: build job table
    WtJobs jobs;
    int nt = 0, nj = 0;
    auto addjob = [&](const float* src, __half* dst, int K, int N) {
        jobs.src[nj] = src; jobs.dst[nj] = dst; jobs.K[nj] = K; jobs.N[nj] = N;
        jobs.t0[nj] = nt; nt += (N / 32) * (K / 32); nj++;
    };
    addjob(w_proj[0], wt_proj0, 64, 256);
    addjob(w_proj[1], wt_proj1, 128, 256);
    for (int li = 0; li < 2; li++) {
        addjob(wq + li * 65536, wt_qkv + li * 196608,          256, 256);
        addjob(wk + li * 65536, wt_qkv + li * 196608 + 65536,  256, 256);
        addjob(wv + li * 65536, wt_qkv + li * 196608 + 131072, 256, 256);
        addjob(wo + li * 65536, wt_o + li * 65536, 256, 256);
        addjob(w_ff1 + li * 262144, wt_ff1 + li * 262144, 256, 1024);
        addjob(w_ff2 + li * 262144, wt_ff2 + li * 262144, 1024, 256);
    }
    addjob(w_fus1, wt_fus1, 512, 256);
    addjob(w_fus2, wt_fus2, 256, 256);
    wt_fused<<<nt, 256>>>(jobs, nj);
    for (int li = 0; li < 2; li++) {
        cudaMemcpyAsync(bqkv + li * 768,       bq + li * 256, 1024, cudaMemcpyDeviceToDevice);
        cudaMemcpyAsync(bqkv + li * 768 + 256, bk + li * 256, 1024, cudaMemcpyDeviceToDevice);
        cudaMemcpyAsync(bqkv + li * 768 + 512, bv + li * 256, 1024, cudaMemcpyDeviceToDevice);
    }

    const int PL[2] = {8, 16}, ST[2] = {4, 8}, EE[2] = {136, 128}, NMX[2] = {34, 16};
    const int MP[2] = {1152, 1024};
    const int MCC[2] = {MC0, MC1}, MBB[2] = {MB0, MB1};

    for (int s = 0; s < 2; s++) {
        int pl = PL[s], st = ST[s], E = EE[s], NMAX = NMX[s];
        int plc = pl * CH;
        int BE = BATCH * E;
        int M = MCC[s], MBc = MBB[s];

        { int tot = BE * plc;
          win_kernel<<<(tot + 255) / 256, 256>>>(x, winh, E, pl); }
        gemm(winh, s == 0 ? wt_proj0 : wt_proj1, b_proj[s], tokens, MP[s], HID, plc, 0);
        { int nwarp = NSEQ * NMAX;
          int blocks = (nwarp + 7) / 8;
          if (s == 0) build_seq_ln<0><<<blocks, 256>>>(tokens, pos[s], ln1_g, ln1_b,
                                                       seq, s2h, NMAX, E, pl, st, MBc);
          else        build_seq_ln<1><<<blocks, 256>>>(tokens, pos[s], ln1_g, ln1_b,
                                                       seq, s2h, NMAX, E, pl, st, MBc);
        }

        for (int li = 0; li < 2; li++) {
            gemm(s2h, wt_qkv + li * 196608, bqkv + li * 768, qkv, M, 768, HID, 0);
            dim3 ag(NSEQ, NHEAD);
            if (s == 0) attn_kernel<0, 34><<<ag, 64>>>(qkv, s2h, MBc);
            else        attn_kernel<1, 16><<<ag, 64>>>(qkv, s2h, MBc);
            // O-proj + residual + fused LN2 -> s2h
            gemm(s2h, wt_o + li * 65536, bo + li * HID, seq, M, HID, HID, 3,
                 ln2_g + li * HID, ln2_b + li * HID, s2h);
            gemm(s2h, wt_ff1 + li * 262144, b_ff1 + li * FFD, ffh, M, FFD, HID, 1);
            if (li == 0)   // FF2 + residual + fused LN1(layer1) -> s2h
                gemm(ffh, wt_ff2 + li * 262144, b_ff2 + li * HID, seq, M, HID, FFD, 3,
                     ln1_g + HID, ln1_b + HID, s2h);
            else
                gemm(ffh, wt_ff2 + li * 262144, b_ff2 + li * HID, seq, M, HID, FFD, 2);
        }
        { int tot = NSEQ * HID;
          int blocks = (tot + 255) / 256;
          if (s == 0) gather_kernel<0><<<blocks, 256>>>(seq, combh, 0, MBc);
          else        gather_kernel<1><<<blocks, 256>>>(seq, combh, 256, MBc);
        }
    }

    gemm(combh, wt_fus1, b_fus1, s2h, NSEQ, HID, 2 * HID, 1);
    gemm(s2h, wt_fus2, b_fus2, seq, NSEQ, HID, HID, 0);
    ln_final<<<NSEQ / 8, 256>>>(seq, ln_g, ln_b, (float*)d_out);
}

// round 10
// speedup vs baseline: 6.7242x; 1.0408x over previous
#include <cuda_runtime.h>
#include <cuda_fp16.h>
#include <math.h>
#include <stdint.h>

// ---------------- problem constants ----------------
#define LSEQ   128
#define BATCH  8
#define CH     8
#define HID    256
#define NHEAD  8
#define DHEAD  32
#define FFD    1024
#define MAXPADC 15
#define NSEQ   1024          // BATCH * LSEQ

// compacted row counts
#define MB0 2368
#define MB1 1088
#define MC0 18944            // 148 * 128
#define MC1 8704             // 68 * 128
#define MTOT 27648           // 216 * 128 (both scales concatenated)

// ---------------- scratch (allocation-free) ----------------
__device__ __half  g_winh[147456];
__device__ float   g_tokens[294912];
__device__ float   g_seq[MTOT * 256];
__device__ __half  g_qkvh[MTOT * 768];
__device__ __half  g_s2h[MTOT * 256];
__device__ __half  g_ffh[MTOT * 1024];
__device__ __half  g_combh[1024 * 512];
__device__ __half  g_wth[1818624];
__device__ float   g_bqkv[1536];

// ---------------- helpers ----------------
__device__ __forceinline__ float gelu_exact(float x) {
    return 0.5f * x * (1.0f + erff(x * 0.7071067811865476f));
}
__device__ __forceinline__ uint32_t smem_u32(const void* p) {
    uint32_t a;
    asm("{ .reg .u64 t; cvta.to.shared.u64 t, %1; cvt.u32.u64 %0, t; }" : "=r"(a) : "l"(p));
    return a;
}
__device__ __forceinline__ void cp16(uint32_t dst, const void* src) {
    asm volatile("cp.async.cg.shared.global [%0], [%1], 16;" :: "r"(dst), "l"(src));
}
__device__ __forceinline__ void cp_commit() {
    asm volatile("cp.async.commit_group;" ::: "memory");
}
template<int N>
__device__ __forceinline__ void cp_wait() {
    asm volatile("cp.async.wait_group %0;" :: "n"(N) : "memory");
}
__device__ __forceinline__ void mma_f16(float* c, const uint32_t* a,
                                        uint32_t b0, uint32_t b1) {
    asm volatile(
        "mma.sync.aligned.m16n8k16.row.col.f32.f16.f16.f32 "
        "{%0,%1,%2,%3}, {%4,%5,%6,%7}, {%8,%9}, {%0,%1,%2,%3};\n"
        : "+f"(c[0]), "+f"(c[1]), "+f"(c[2]), "+f"(c[3])
        : "r"(a[0]), "r"(a[1]), "r"(a[2]), "r"(a[3]), "r"(b0), "r"(b1));
}
__device__ __forceinline__ void ldsm4(uint32_t& r0, uint32_t& r1, uint32_t& r2,
                                      uint32_t& r3, uint32_t addr) {
    asm volatile("ldmatrix.sync.aligned.m8n8.x4.shared.b16 {%0,%1,%2,%3}, [%4];"
                 : "=r"(r0), "=r"(r1), "=r"(r2), "=r"(r3) : "r"(addr));
}
template<int SCALE>
__device__ __forceinline__ int nfun(int t) {
    return SCALE == 0 ? ((t + 8) >> 2) + 1 : (t >> 3) + 1;
}
template<int SCALE>
__device__ __forceinline__ int Sfun(int t) {
    if (SCALE == 0) {
        int m = t + 8, q = m >> 2, r = m & 3;
        return t + 2 * q * (q - 1) + r * q - 4;
    } else {
        int q = t >> 3, r = t & 7;
        return t + 4 * q * (q - 1) + r * q;
    }
}

// ---------------- fused weight transpose + half convert ----------------
#define NJOBS 16
struct WtJobs {
    const float* src[NJOBS];
    __half*      dst[NJOBS];
    int K[NJOBS], N[NJOBS], t0[NJOBS];
};
__global__ void wt_fused(WtJobs jobs, int njobs) {
    __shared__ float t[32][33];
    int tile = blockIdx.x;
    int ji = 0;
    #pragma unroll 1
    while (ji + 1 < njobs && tile >= jobs.t0[ji + 1]) ji++;
    int lt = tile - jobs.t0[ji];
    int K = jobs.K[ji], N = jobs.N[ji];
    int tn = N >> 5;
    int nb = (lt % tn) * 32, kb = (lt / tn) * 32;
    const float* W = jobs.src[ji];
    __half* WT = jobs.dst[ji];
    int tx = threadIdx.x & 31, ty = threadIdx.x >> 5;
    #pragma unroll
    for (int i = 0; i < 32; i += 8)
        t[ty + i][tx] = W[(size_t)(kb + ty + i) * N + nb + tx];
    __syncthreads();
    #pragma unroll
    for (int i = 0; i < 32; i += 8)
        WT[(size_t)(nb + ty + i) * K + kb + tx] = __float2half_rn(t[tx][ty + i]);
}

// ---------------- window gather (half) ----------------
__global__ void win_kernel(const float* __restrict__ x, __half* __restrict__ win,
                           int E, int pl) {
    int plc = pl * CH;
    int tot = BATCH * E * plc;
    int idx = blockIdx.x * blockDim.x + threadIdx.x;
    if (idx >= tot) return;
    int r = idx % plc;
    int e = (idx / plc) % E;
    int b = idx / (plc * E);
    int p = r >> 3, c = r & 7;
    int i = e + p;
    win[idx] = __float2half_rn((i < MAXPADC) ? 0.0f : x[(b * LSEQ + (i - MAXPADC)) * CH + c]);
}

// ---------------- seq build + fused LN1: one warp per valid row ----------------
template<int SCALE>
__global__ void build_seq_ln(const float* __restrict__ tokens,
                             const float* __restrict__ pos,
                             const float* __restrict__ lg, const float* __restrict__ lb,
                             float* __restrict__ seq, __half* __restrict__ s2h,
                             int NMAX, int E, int pl, int st, int MBc, int rowoff) {
    int wid = threadIdx.x >> 5, lane = threadIdx.x & 31;
    int wg = blockIdx.x * 8 + wid;
    if (wg >= NSEQ * NMAX) return;
    int k = wg % NMAX, bt = wg / NMAX;
    int t = bt & (LSEQ - 1), b = bt >> 7;
    int n = nfun<SCALE>(t);
    if (k >= n) return;
    int ends = t + MAXPADC - (n - 1) * st + k * st;
    int j = ends - (pl - 1);
    j = j < 0 ? 0 : (j > E - 1 ? E - 1 : j);
    int m = rowoff + b * MBc + Sfun<SCALE>(t) + k;

    const float4* tp = (const float4*)(tokens + (size_t)(b * E + j) * 256) + lane * 2;
    const float4* pp = (const float4*)(pos + k * 256) + lane * 2;
    float4 t0 = tp[0], t1 = tp[1], p0 = pp[0], p1 = pp[1];
    float v[8] = { t0.x + p0.x, t0.y + p0.y, t0.z + p0.z, t0.w + p0.w,
                   t1.x + p1.x, t1.y + p1.y, t1.z + p1.z, t1.w + p1.w };
    float s = 0.0f, q = 0.0f;
    #pragma unroll
    for (int i = 0; i < 8; i++) { s += v[i]; q += v[i] * v[i]; }
    #pragma unroll
    for (int o = 16; o > 0; o >>= 1) {
        s += __shfl_xor_sync(0xffffffffu, s, o);
        q += __shfl_xor_sync(0xffffffffu, q, o);
    }
    float mu = s * (1.0f / 256.0f);
    float var = q * (1.0f / 256.0f) - mu * mu;
    float rinv = rsqrtf(var + 1e-5f);

    float4* sp = (float4*)(seq + (size_t)m * 256) + lane * 2;
    sp[0] = make_float4(v[0], v[1], v[2], v[3]);
    sp[1] = make_float4(v[4], v[5], v[6], v[7]);

    const float4* gp = (const float4*)(lg) + lane * 2;
    const float4* bp = (const float4*)(lb) + lane * 2;
    float4 g0 = gp[0], g1 = gp[1], bb0 = bp[0], bb1 = bp[1];
    __half2 h[4];
    h[0] = __floats2half2_rn((v[0]-mu)*rinv*g0.x+bb0.x, (v[1]-mu)*rinv*g0.y+bb0.y);
    h[1] = __floats2half2_rn((v[2]-mu)*rinv*g0.z+bb0.z, (v[3]-mu)*rinv*g0.w+bb0.w);
    h[2] = __floats2half2_rn((v[4]-mu)*rinv*g1.x+bb1.x, (v[5]-mu)*rinv*g1.y+bb1.y);
    h[3] = __floats2half2_rn((v[6]-mu)*rinv*g1.z+bb1.z, (v[7]-mu)*rinv*g1.w+bb1.w);
    *(uint4*)(s2h + (size_t)m * 256 + lane * 8) = *(uint4*)h;
}

// ---------------- gather last valid patch (half, compacted) ----------------
template<int SCALE>
__global__ void gather_kernel(const float* __restrict__ seq, __half* __restrict__ comb,
                              int off, int MBc, int rowoff) {
    int idx = blockIdx.x * blockDim.x + threadIdx.x;
    if (idx >= NSEQ * HID) return;
    int h = idx & 255;
    int bt = idx >> 8;
    int t = bt & (LSEQ - 1);
    int b = bt >> 7;
    int n = nfun<SCALE>(t);
    int m = rowoff + b * MBc + Sfun<SCALE>(t) + n - 1;
    comb[bt * 512 + off + h] = __float2half_rn(seq[(size_t)m * HID + h]);
}

// ---------------- final layernorm: warp per row, fp32 out ----------------
__global__ void ln_final(const float* __restrict__ in, const float* __restrict__ g,
                         const float* __restrict__ b, float* __restrict__ out) {
    int warp = threadIdx.x >> 5, lane = threadIdx.x & 31;
    size_t row = (size_t)blockIdx.x * 8 + warp;
    const float4* p = (const float4*)(in + row * 256);
    float4 v0 = p[lane], v1 = p[lane + 32];
    float s = v0.x + v0.y + v0.z + v0.w + v1.x + v1.y + v1.z + v1.w;
    #pragma unroll
    for (int o = 16; o > 0; o >>= 1) s += __shfl_xor_sync(0xffffffffu, s, o);
    float mu = s * (1.0f / 256.0f);
    float d0x = v0.x - mu, d0y = v0.y - mu, d0z = v0.z - mu, d0w = v0.w - mu;
    float d1x = v1.x - mu, d1y = v1.y - mu, d1z = v1.z - mu, d1w = v1.w - mu;
    float q = d0x*d0x + d0y*d0y + d0z*d0z + d0w*d0w
            + d1x*d1x + d1y*d1y + d1z*d1z + d1w*d1w;
    #pragma unroll
    for (int o = 16; o > 0; o >>= 1) q += __shfl_xor_sync(0xffffffffu, q, o);
    float r = rsqrtf(q * (1.0f / 256.0f) + 1e-5f);
    const float4* gp = (const float4*)g;
    const float4* bp = (const float4*)b;
    float4 g0 = gp[lane], g1 = gp[lane + 32];
    float4 b0 = bp[lane], b1 = bp[lane + 32];
    float4* po = (float4*)(out + row * 256);
    po[lane]      = make_float4(d0x*r*g0.x+b0.x, d0y*r*g0.y+b0.y, d0z*r*g0.z+b0.z, d0w*r*g0.w+b0.w);
    po[lane + 32] = make_float4(d1x*r*g1.x+b1.x, d1y*r*g1.y+b1.y, d1z*r*g1.z+b1.z, d1w*r*g1.w+b1.w);
}

// ---------------- fp16 mma.sync GEMM, cp.async 3-stage, ldmatrix ----------------
// EPI: 0 bias->fp32; 1 bias+gelu->half; 2 bias+residual->fp32;
//      3 bias+residual->fp32 + fused LN -> half (N==256, grid.x==1); 4 bias->half
#define HSTAGE 12288
#define HSMEM  (3 * HSTAGE * 2)
template<int EPI>
__global__ void __launch_bounds__(256, 1) hgemm_kernel(
        const __half* __restrict__ A, const __half* __restrict__ BT,
        const float* __restrict__ bias, void* __restrict__ Cv,
        int N, int K,
        const float* __restrict__ lng, const float* __restrict__ lnb,
        __half* __restrict__ lnout) {
    extern __shared__ __half sm[];
    const uint32_t sb = smem_u32(sm);
    const int tid = threadIdx.x, lane = tid & 31, warp = tid >> 5;
    const int bm = blockIdx.y << 7, bn = blockIdx.x << 8;
    const int wm = (warp & 1) << 6, wn = (warp >> 1) << 6;
    const int nc = K >> 5;

    float acc[4][8][4];
    #pragma unroll
    for (int mi = 0; mi < 4; mi++)
        #pragma unroll
        for (int j = 0; j < 8; j++)
            #pragma unroll
            for (int q = 0; q < 4; q++) acc[mi][j][q] = 0.0f;

    const int sA0 = tid, sA1 = tid + 256;
    auto issue = [&](int c) {
        const int koff = c << 5;
        const uint32_t stg = sb + (uint32_t)((c % 3) * HSTAGE) * 2u;
        #pragma unroll
        for (int i = 0; i < 2; i++) {
            int seg = (i == 0) ? sA0 : sA1;
            int row = seg >> 2, sc = seg & 3;
            uint32_t dst = stg + (uint32_t)(row * 32 + ((sc ^ ((row >> 1) & 3)) << 3)) * 2u;
            cp16(dst, A + (size_t)(bm + row) * K + koff + sc * 8);
        }
        #pragma unroll
        for (int i = 0; i < 4; i++) {
            int seg = tid + i * 256;
            int row = seg >> 2, sc = seg & 3;
            uint32_t dst = stg + (uint32_t)(4096 + row * 32 + ((sc ^ ((row >> 1) & 3)) << 3)) * 2u;
            cp16(dst, BT + (size_t)(bn + row) * K + koff + sc * 8);
        }
    };

    #pragma unroll
    for (int s = 0; s < 2; s++) {
        if (s < nc) issue(s);
        cp_commit();
    }

    const int r_lo = lane >> 2, wv = lane & 3;
    const int arow = wm + (lane & 15);
    const int asel = (lane >> 4) & 1;
    int brow[4], bsel[4];
    {
        int i = lane >> 3;
        #pragma unroll
        for (int g = 0; g < 4; g++) {
            brow[g] = wn + ((g << 1) + (i >> 1)) * 8 + (lane & 7);
            bsel[g] = i & 1;
        }
    }

    for (int c = 0; c < nc; c++) {
        cp_wait<1>();
        __syncthreads();
        if (c + 2 < nc) issue(c + 2);
        cp_commit();

        const uint32_t stA = sb + (uint32_t)((c % 3) * HSTAGE) * 2u;
        const uint32_t stB = stA + 8192u;
        #pragma unroll
        for (int kk = 0; kk < 2; kk++) {
            uint32_t a[4][4];
            #pragma unroll
            for (int mi = 0; mi < 4; mi++) {
                int r = arow + mi * 16;
                uint32_t ad = stA + (uint32_t)(r * 64 + ((((kk << 1) | asel) ^ ((r >> 1) & 3)) << 4));
                ldsm4(a[mi][0], a[mi][1], a[mi][2], a[mi][3], ad);
            }
            uint32_t bf[8][2];
            #pragma unroll
            for (int g = 0; g < 4; g++) {
                int r = brow[g];
                uint32_t bd = stB + (uint32_t)(r * 64 + ((((kk << 1) | bsel[g]) ^ ((r >> 1) & 3)) << 4));
                ldsm4(bf[2*g][0], bf[2*g][1], bf[2*g+1][0], bf[2*g+1][1], bd);
            }
            #pragma unroll
            for (int j = 0; j < 8; j++)
                #pragma unroll
                for (int mi = 0; mi < 4; mi++)
                    mma_f16(acc[mi][j], a[mi], bf[j][0], bf[j][1]);
        }
    }

    if (EPI == 3) {
        float* C = (float*)Cv;
        #pragma unroll
        for (int mi = 0; mi < 4; mi++) {
            const int r = bm + wm + mi * 16 + r_lo;
            #pragma unroll
            for (int j = 0; j < 8; j++) {
                const int cl = wn + j * 8 + wv * 2;
                float bf0 = bias[cl], bf1 = bias[cl + 1];
                float2* p0 = (float2*)(C + (size_t)r * 256 + cl);
                float2* p1 = (float2*)(C + (size_t)(r + 8) * 256 + cl);
                float2 o0 = *p0, o1 = *p1;
                acc[mi][j][0] += bf0 + o0.x; acc[mi][j][1] += bf1 + o0.y;
                acc[mi][j][2] += bf0 + o1.x; acc[mi][j][3] += bf1 + o1.y;
                *p0 = make_float2(acc[mi][j][0], acc[mi][j][1]);
                *p1 = make_float2(acc[mi][j][2], acc[mi][j][3]);
            }
        }
        float2* red = (float2*)sm;
        float sums[8], sqs[8];
        #pragma unroll
        for (int mi = 0; mi < 4; mi++) {
            #pragma unroll
            for (int rr = 0; rr < 2; rr++) {
                float s = 0.0f, q = 0.0f;
                #pragma unroll
                for (int j = 0; j < 8; j++) {
                    float v0 = acc[mi][j][rr * 2], v1 = acc[mi][j][rr * 2 + 1];
                    s += v0 + v1; q += v0 * v0 + v1 * v1;
                }
                s += __shfl_xor_sync(0xffffffffu, s, 1);
                s += __shfl_xor_sync(0xffffffffu, s, 2);
                q += __shfl_xor_sync(0xffffffffu, q, 1);
                q += __shfl_xor_sync(0xffffffffu, q, 2);
                sums[mi * 2 + rr] = s; sqs[mi * 2 + rr] = q;
            }
        }
        const int wn_i = warp >> 1;
        __syncthreads();      // all warps done with last stage smem before red overwrite
        if (wv == 0) {
            #pragma unroll
            for (int idx = 0; idx < 8; idx++) {
                int rl = wm + (idx >> 1) * 16 + r_lo + (idx & 1) * 8;
                red[rl * 4 + wn_i] = make_float2(sums[idx], sqs[idx]);
            }
        }
        __syncthreads();
        float mus[8], rinvs[8];
        #pragma unroll
        for (int idx = 0; idx < 8; idx++) {
            int rl = wm + (idx >> 1) * 16 + r_lo + (idx & 1) * 8;
            float S = 0.0f, Q = 0.0f;
            #pragma unroll
            for (int w = 0; w < 4; w++) {
                float2 e = red[rl * 4 + w];
                S += e.x; Q += e.y;
            }
            float mu = S * (1.0f / 256.0f);
            mus[idx] = mu;
            rinvs[idx] = rsqrtf(Q * (1.0f / 256.0f) - mu * mu + 1e-5f);
        }
        #pragma unroll
        for (int mi = 0; mi < 4; mi++) {
            const int r = bm + wm + mi * 16 + r_lo;
            #pragma unroll
            for (int j = 0; j < 8; j++) {
                const int cl = wn + j * 8 + wv * 2;
                float gg0 = lng[cl], gg1 = lng[cl + 1];
                float bb0 = lnb[cl], bb1 = lnb[cl + 1];
                float mu0 = mus[mi * 2], ri0 = rinvs[mi * 2];
                float mu1 = mus[mi * 2 + 1], ri1 = rinvs[mi * 2 + 1];
                *(__half2*)(lnout + (size_t)r * 256 + cl) =
                    __floats2half2_rn((acc[mi][j][0] - mu0) * ri0 * gg0 + bb0,
                                      (acc[mi][j][1] - mu0) * ri0 * gg1 + bb1);
                *(__half2*)(lnout + (size_t)(r + 8) * 256 + cl) =
                    __floats2half2_rn((acc[mi][j][2] - mu1) * ri1 * gg0 + bb0,
                                      (acc[mi][j][3] - mu1) * ri1 * gg1 + bb1);
            }
        }
        return;
    }

    #pragma unroll
    for (int mi = 0; mi < 4; mi++) {
        const int r = bm + wm + mi * 16 + r_lo;
        #pragma unroll
        for (int j = 0; j < 8; j++) {
            const int cl = bn + wn + j * 8 + wv * 2;
            float bf0 = bias[cl], bf1 = bias[cl + 1];
            float v0 = acc[mi][j][0] + bf0, v1 = acc[mi][j][1] + bf1;
            float v2 = acc[mi][j][2] + bf0, v3 = acc[mi][j][3] + bf1;
            if (EPI == 0) {
                float* C = (float*)Cv;
                *(float2*)(C + (size_t)r * N + cl)       = make_float2(v0, v1);
                *(float2*)(C + (size_t)(r + 8) * N + cl) = make_float2(v2, v3);
            } else if (EPI == 1) {
                __half* C = (__half*)Cv;
                *(__half2*)(C + (size_t)r * N + cl) =
                    __floats2half2_rn(gelu_exact(v0), gelu_exact(v1));
                *(__half2*)(C + (size_t)(r + 8) * N + cl) =
                    __floats2half2_rn(gelu_exact(v2), gelu_exact(v3));
            } else if (EPI == 4) {
                __half* C = (__half*)Cv;
                *(__half2*)(C + (size_t)r * N + cl)       = __floats2half2_rn(v0, v1);
                *(__half2*)(C + (size_t)(r + 8) * N + cl) = __floats2half2_rn(v2, v3);
            } else {
                float* C = (float*)Cv;
                float2* p0 = (float2*)(C + (size_t)r * N + cl);
                float2* p1 = (float2*)(C + (size_t)(r + 8) * N + cl);
                float2 o0 = *p0, o1 = *p1;
                *p0 = make_float2(o0.x + v0, o0.y + v1);
                *p1 = make_float2(o1.x + v2, o1.y + v3);
            }
        }
    }
}

// ---------------- attention (compacted, half qkv) ----------------
template<int SCALE, int NMAX>
__global__ void attn_kernel(const __half* __restrict__ QKV, __half* __restrict__ O,
                            int MBc, int rowoff) {
    __shared__ float Ks[NMAX][32];
    __shared__ float Vs[NMAX][32];
    int bt = blockIdx.x, head = blockIdx.y;
    int t = bt & (LSEQ - 1);
    int b = bt >> 7;
    int n = nfun<SCALE>(t);
    int rb = rowoff + b * MBc + Sfun<SCALE>(t);
    size_t base = (size_t)rb * 768 + head * DHEAD;

    for (int i = threadIdx.x; i < NMAX * 16; i += blockDim.x) {
        int kk = i >> 4, d = (i & 15) << 1;
        float2 kv = make_float2(0.f, 0.f), vv = make_float2(0.f, 0.f);
        if (kk < n) {
            kv = __half22float2(*(const __half2*)(QKV + base + (size_t)kk * 768 + 256 + d));
            vv = __half22float2(*(const __half2*)(QKV + base + (size_t)kk * 768 + 512 + d));
        }
        Ks[kk][d] = kv.x; Ks[kk][d + 1] = kv.y;
        Vs[kk][d] = vv.x; Vs[kk][d + 1] = vv.y;
    }
    __syncthreads();

    int tq = threadIdx.x;
    if (tq < n) {
        float qr[32];
        #pragma unroll
        for (int d = 0; d < 32; d += 2) {
            float2 qv = __half22float2(*(const __half2*)(QKV + base + (size_t)tq * 768 + d));
            qr[d] = qv.x; qr[d + 1] = qv.y;
        }
        float sc[NMAX];
        float mx = -1e30f;
        #pragma unroll
        for (int kk = 0; kk < NMAX; kk++) {
            float s = 0.0f;
            #pragma unroll
            for (int d = 0; d < 32; d++) s += qr[d] * Ks[kk][d];
            s *= 0.17677669529663687f;
            sc[kk] = (kk < n) ? s : -1e30f;
            mx = fmaxf(mx, sc[kk]);
        }
        float ssum = 0.0f;
        #pragma unroll
        for (int kk = 0; kk < NMAX; kk++) {
            float e = (kk < n) ? expf(sc[kk] - mx) : 0.0f;
            sc[kk] = e;
            ssum += e;
        }
        float inv = 1.0f / ssum;
        __half* op = O + (size_t)(rb + tq) * HID + head * DHEAD;
        #pragma unroll
        for (int d = 0; d < 32; d += 2) {
            float o0 = 0.0f, o1 = 0.0f;
            #pragma unroll
            for (int kk = 0; kk < NMAX; kk++) {
                o0 += sc[kk] * Vs[kk][d];
                o1 += sc[kk] * Vs[kk][d + 1];
            }
            *(__half2*)(op + d) = __floats2half2_rn(o0 * inv, o1 * inv);
        }
    }
}

// ---------------- host side ----------------
static inline void gemm(const __half* A, const __half* WT, const float* bias, void* C,
                        int Mp, int N, int K, int epi,
                        const float* lng = nullptr, const float* lnb = nullptr,
                        __half* lnout = nullptr) {
    dim3 grid(N >> 8, Mp >> 7), block(256);
    if (epi == 0)      hgemm_kernel<0><<<grid, block, HSMEM>>>(A, WT, bias, C, N, K, lng, lnb, lnout);
    else if (epi == 1) hgemm_kernel<1><<<grid, block, HSMEM>>>(A, WT, bias, C, N, K, lng, lnb, lnout);
    else if (epi == 2) hgemm_kernel<2><<<grid, block, HSMEM>>>(A, WT, bias, C, N, K, lng, lnb, lnout);
    else if (epi == 3) hgemm_kernel<3><<<grid, block, HSMEM>>>(A, WT, bias, C, N, K, lng, lnb, lnout);
    else               hgemm_kernel<4><<<grid, block, HSMEM>>>(A, WT, bias, C, N, K, lng, lnb, lnout);
}

extern "C" void kernel_launch(void* const* d_in, const int* in_sizes, int n_in,
                              void* d_out, int out_size) {
    cudaFuncSetAttribute(hgemm_kernel<0>, cudaFuncAttributeMaxDynamicSharedMemorySize, HSMEM);
    cudaFuncSetAttribute(hgemm_kernel<1>, cudaFuncAttributeMaxDynamicSharedMemorySize, HSMEM);
    cudaFuncSetAttribute(hgemm_kernel<2>, cudaFuncAttributeMaxDynamicSharedMemorySize, HSMEM);
    cudaFuncSetAttribute(hgemm_kernel<3>, cudaFuncAttributeMaxDynamicSharedMemorySize, HSMEM);
    cudaFuncSetAttribute(hgemm_kernel<4>, cudaFuncAttributeMaxDynamicSharedMemorySize, HSMEM);

    const float* x       = (const float*)d_in[0];
    const float* w_proj[2] = { (const float*)d_in[1], (const float*)d_in[3] };
    const float* b_proj[2] = { (const float*)d_in[2], (const float*)d_in[4] };
    const float* pos[2]    = { (const float*)d_in[5], (const float*)d_in[6] };
    const float* ln1_g = (const float*)d_in[7];
    const float* ln1_b = (const float*)d_in[8];
    const float* wq = (const float*)d_in[9];
    const float* bq = (const float*)d_in[10];
    const float* wk = (const float*)d_in[11];
    const float* bk = (const float*)d_in[12];
    const float* wv = (const float*)d_in[13];
    const float* bv = (const float*)d_in[14];
    const float* wo = (const float*)d_in[15];
    const float* bo = (const float*)d_in[16];
    const float* ln2_g = (const float*)d_in[17];
    const float* ln2_b = (const float*)d_in[18];
    const float* w_ff1 = (const float*)d_in[19];
    const float* b_ff1 = (const float*)d_in[20];
    const float* w_ff2 = (const float*)d_in[21];
    const float* b_ff2 = (const float*)d_in[22];
    const float* ln_g = (const float*)d_in[23];
    const float* ln_b = (const float*)d_in[24];
    const float* w_fus1 = (const float*)d_in[25];
    const float* b_fus1 = (const float*)d_in[26];
    const float* w_fus2 = (const float*)d_in[27];
    const float* b_fus2 = (const float*)d_in[28];

    __half *winh, *qkvh, *s2h, *ffh, *combh, *wth;
    float *tokens, *seq, *bqkv;
    cudaGetSymbolAddress((void**)&winh,   g_winh);
    cudaGetSymbolAddress((void**)&tokens, g_tokens);
    cudaGetSymbolAddress((void**)&seq,    g_seq);
    cudaGetSymbolAddress((void**)&qkvh,   g_qkvh);
    cudaGetSymbolAddress((void**)&s2h,    g_s2h);
    cudaGetSymbolAddress((void**)&ffh,    g_ffh);
    cudaGetSymbolAddress((void**)&combh,  g_combh);
    cudaGetSymbolAddress((void**)&wth,    g_wth);
    cudaGetSymbolAddress((void**)&bqkv,   g_bqkv);

    __half* wt_proj0 = wth;
    __half* wt_proj1 = wth + 16384;
    __half* wt_qkv   = wth + 49152;
    __half* wt_o     = wth + 442368;
    __half* wt_ff1   = wth + 573440;
    __half* wt_ff2   = wth + 1097728;
    __half* wt_fus1  = wth + 1622016;
    __half* wt_fus2  = wth + 1753088;

    WtJobs jobs;
    int nt = 0, nj = 0;
    auto addjob = [&](const float* src, __half* dst, int K, int N) {
        jobs.src[nj] = src; jobs.dst[nj] = dst; jobs.K[nj] = K; jobs.N[nj] = N;
        jobs.t0[nj] = nt; nt += (N / 32) * (K / 32); nj++;
    };
    addjob(w_proj[0], wt_proj0, 64, 256);
    addjob(w_proj[1], wt_proj1, 128, 256);
    for (int li = 0; li < 2; li++) {
        addjob(wq + li * 65536, wt_qkv + li * 196608,          256, 256);
        addjob(wk + li * 65536, wt_qkv + li * 196608 + 65536,  256, 256);
        addjob(wv + li * 65536, wt_qkv + li * 196608 + 131072, 256, 256);
        addjob(wo + li * 65536, wt_o + li * 65536, 256, 256);
        addjob(w_ff1 + li * 262144, wt_ff1 + li * 262144, 256, 1024);
        addjob(w_ff2 + li * 262144, wt_ff2 + li * 262144, 1024, 256);
    }
    addjob(w_fus1, wt_fus1, 512, 256);
    addjob(w_fus2, wt_fus2, 256, 256);
    wt_fused<<<nt, 256>>>(jobs, nj);
    for (int li = 0; li < 2; li++) {
        cudaMemcpyAsync(bqkv + li * 768,       bq + li * 256, 1024, cudaMemcpyDeviceToDevice);
        cudaMemcpyAsync(bqkv + li * 768 + 256, bk + li * 256, 1024, cudaMemcpyDeviceToDevice);
        cudaMemcpyAsync(bqkv + li * 768 + 512, bv + li * 256, 1024, cudaMemcpyDeviceToDevice);
    }

    const int PL[2] = {8, 16}, ST[2] = {4, 8}, EE[2] = {136, 128}, NMX[2] = {34, 16};
    const int MP[2] = {1152, 1024};
    const int MBB[2] = {MB0, MB1}, ROFF[2] = {0, MC0};

    // ---- build both scales into combined buffer ----
    for (int s = 0; s < 2; s++) {
        int pl = PL[s], st = ST[s], E = EE[s], NMAX = NMX[s];
        int plc = pl * CH;
        int BE = BATCH * E;
        { int tot = BE * plc;
          win_kernel<<<(tot + 255) / 256, 256>>>(x, winh, E, pl); }
        gemm(winh, s == 0 ? wt_proj0 : wt_proj1, b_proj[s], tokens, MP[s], HID, plc, 0);
        { int nwarp = NSEQ * NMAX;
          int blocks = (nwarp + 7) / 8;
          if (s == 0) build_seq_ln<0><<<blocks, 256>>>(tokens, pos[s], ln1_g, ln1_b,
                                                       seq, s2h, NMAX, E, pl, st, MBB[s], ROFF[s]);
          else        build_seq_ln<1><<<blocks, 256>>>(tokens, pos[s], ln1_g, ln1_b,
                                                       seq, s2h, NMAX, E, pl, st, MBB[s], ROFF[s]);
        }
    }

    // ---- transformer over combined M (weights shared across scales) ----
    for (int li = 0; li < 2; li++) {
        gemm(s2h, wt_qkv + li * 196608, bqkv + li * 768, qkvh, MTOT, 768, HID, 4);
        dim3 ag(NSEQ, NHEAD);
        attn_kernel<0, 34><<<ag, 64>>>(qkvh, s2h, MB0, 0);
        attn_kernel<1, 16><<<ag, 64>>>(qkvh, s2h, MB1, MC0);
        gemm(s2h, wt_o + li * 65536, bo + li * HID, seq, MTOT, HID, HID, 3,
             ln2_g + li * HID, ln2_b + li * HID, s2h);
        gemm(s2h, wt_ff1 + li * 262144, b_ff1 + li * FFD, ffh, MTOT, FFD, HID, 1);
        if (li == 0)
            gemm(ffh, wt_ff2 + li * 262144, b_ff2 + li * HID, seq, MTOT, HID, FFD, 3,
                 ln1_g + HID, ln1_b + HID, s2h);
        else
            gemm(ffh, wt_ff2 + li * 262144, b_ff2 + li * HID, seq, MTOT, HID, FFD, 2);
    }

    // ---- gather + fusion head ----
    { int tot = NSEQ * HID;
      int blocks = (tot + 255) / 256;
      gather_kernel<0><<<blocks, 256>>>(seq, combh, 0, MB0, 0);
      gather_kernel<1><<<blocks, 256>>>(seq, combh, 256, MB1, MC0);
    }
    gemm(combh, wt_fus1, b_fus1, s2h, NSEQ, HID, 2 * HID, 1);
    gemm(s2h, wt_fus2, b_fus2, seq, NSEQ, HID, HID, 0);
    ln_final<<<NSEQ / 8, 256>>>(seq, ln_g, ln_b, (float*)d_out);
}

// round 11
// speedup vs baseline: 6.8186x; 1.0140x over previous
#include <cuda_runtime.h>
#include <cuda_fp16.h>
#include <math.h>
#include <stdint.h>

// ---------------- problem constants ----------------
#define LSEQ   128
#define BATCH  8
#define CH     8
#define HID    256
#define NHEAD  8
#define DHEAD  32
#define FFD    1024
#define MAXPADC 15
#define NSEQ   1024          // BATCH * LSEQ

// compacted row counts
#define MB0 2368
#define MB1 1088
#define MC0 18944            // 148 * 128
#define MC1 8704             // 68 * 128
#define MTOT 27648           // 216 * 128

// ---------------- scratch (allocation-free) ----------------
__device__ __half  g_winh[147456];
__device__ float   g_tokens[294912];
__device__ float   g_seq[MTOT * 256];
__device__ __half  g_qkvh[MTOT * 768];
__device__ __half  g_s2h[MTOT * 256];
__device__ __half  g_ffh[MTOT * 1024];
__device__ __half  g_combh[1024 * 512];
__device__ __half  g_wth[1818624];
__device__ float   g_bqkv[1536];

// ---------------- helpers ----------------
__device__ __forceinline__ float gelu_exact(float x) {
    return 0.5f * x * (1.0f + erff(x * 0.7071067811865476f));
}
__device__ __forceinline__ uint32_t smem_u32(const void* p) {
    uint32_t a;
    asm("{ .reg .u64 t; cvta.to.shared.u64 t, %1; cvt.u32.u64 %0, t; }" : "=r"(a) : "l"(p));
    return a;
}
__device__ __forceinline__ void cp16(uint32_t dst, const void* src) {
    asm volatile("cp.async.cg.shared.global [%0], [%1], 16;" :: "r"(dst), "l"(src));
}
__device__ __forceinline__ void cp_commit() {
    asm volatile("cp.async.commit_group;" ::: "memory");
}
template<int N>
__device__ __forceinline__ void cp_wait() {
    asm volatile("cp.async.wait_group %0;" :: "n"(N) : "memory");
}
__device__ __forceinline__ void mma_f16(float* c, const uint32_t* a,
                                        uint32_t b0, uint32_t b1) {
    asm volatile(
        "mma.sync.aligned.m16n8k16.row.col.f32.f16.f16.f32 "
        "{%0,%1,%2,%3}, {%4,%5,%6,%7}, {%8,%9}, {%0,%1,%2,%3};\n"
        : "+f"(c[0]), "+f"(c[1]), "+f"(c[2]), "+f"(c[3])
        : "r"(a[0]), "r"(a[1]), "r"(a[2]), "r"(a[3]), "r"(b0), "r"(b1));
}
__device__ __forceinline__ void ldsm4(uint32_t& r0, uint32_t& r1, uint32_t& r2,
                                      uint32_t& r3, uint32_t addr) {
    asm volatile("ldmatrix.sync.aligned.m8n8.x4.shared.b16 {%0,%1,%2,%3}, [%4];"
                 : "=r"(r0), "=r"(r1), "=r"(r2), "=r"(r3) : "r"(addr));
}
template<int SCALE>
__device__ __forceinline__ int nfun(int t) {
    return SCALE == 0 ? ((t + 8) >> 2) + 1 : (t >> 3) + 1;
}
template<int SCALE>
__device__ __forceinline__ int Sfun(int t) {
    if (SCALE == 0) {
        int m = t + 8, q = m >> 2, r = m & 3;
        return t + 2 * q * (q - 1) + r * q - 4;
    } else {
        int q = t >> 3, r = t & 7;
        return t + 4 * q * (q - 1) + r * q;
    }
}

// ---------------- fused weight transpose + half convert ----------------
#define NJOBS 16
struct WtJobs {
    const float* src[NJOBS];
    __half*      dst[NJOBS];
    int K[NJOBS], N[NJOBS], t0[NJOBS];
};
__global__ void wt_fused(WtJobs jobs, int njobs) {
    __shared__ float t[32][33];
    int tile = blockIdx.x;
    int ji = 0;
    #pragma unroll 1
    while (ji + 1 < njobs && tile >= jobs.t0[ji + 1]) ji++;
    int lt = tile - jobs.t0[ji];
    int K = jobs.K[ji], N = jobs.N[ji];
    int tn = N >> 5;
    int nb = (lt % tn) * 32, kb = (lt / tn) * 32;
    const float* W = jobs.src[ji];
    __half* WT = jobs.dst[ji];
    int tx = threadIdx.x & 31, ty = threadIdx.x >> 5;
    #pragma unroll
    for (int i = 0; i < 32; i += 8)
        t[ty + i][tx] = W[(size_t)(kb + ty + i) * N + nb + tx];
    __syncthreads();
    #pragma unroll
    for (int i = 0; i < 32; i += 8)
        WT[(size_t)(nb + ty + i) * K + kb + tx] = __float2half_rn(t[tx][ty + i]);
}

// ---------------- window gather (half) ----------------
__global__ void win_kernel(const float* __restrict__ x, __half* __restrict__ win,
                           int E, int pl) {
    int plc = pl * CH;
    int tot = BATCH * E * plc;
    int idx = blockIdx.x * blockDim.x + threadIdx.x;
    if (idx >= tot) return;
    int r = idx % plc;
    int e = (idx / plc) % E;
    int b = idx / (plc * E);
    int p = r >> 3, c = r & 7;
    int i = e + p;
    win[idx] = __float2half_rn((i < MAXPADC) ? 0.0f : x[(b * LSEQ + (i - MAXPADC)) * CH + c]);
}

// ---------------- seq build + fused LN1: one warp per valid row ----------------
template<int SCALE>
__global__ void build_seq_ln(const float* __restrict__ tokens,
                             const float* __restrict__ pos,
                             const float* __restrict__ lg, const float* __restrict__ lb,
                             float* __restrict__ seq, __half* __restrict__ s2h,
                             int NMAX, int E, int pl, int st, int MBc, int rowoff) {
    int wid = threadIdx.x >> 5, lane = threadIdx.x & 31;
    int wg = blockIdx.x * 8 + wid;
    if (wg >= NSEQ * NMAX) return;
    int k = wg % NMAX, bt = wg / NMAX;
    int t = bt & (LSEQ - 1), b = bt >> 7;
    int n = nfun<SCALE>(t);
    if (k >= n) return;
    int ends = t + MAXPADC - (n - 1) * st + k * st;
    int j = ends - (pl - 1);
    j = j < 0 ? 0 : (j > E - 1 ? E - 1 : j);
    int m = rowoff + b * MBc + Sfun<SCALE>(t) + k;

    const float4* tp = (const float4*)(tokens + (size_t)(b * E + j) * 256) + lane * 2;
    const float4* pp = (const float4*)(pos + k * 256) + lane * 2;
    float4 t0 = tp[0], t1 = tp[1], p0 = pp[0], p1 = pp[1];
    float v[8] = { t0.x + p0.x, t0.y + p0.y, t0.z + p0.z, t0.w + p0.w,
                   t1.x + p1.x, t1.y + p1.y, t1.z + p1.z, t1.w + p1.w };
    float s = 0.0f, q = 0.0f;
    #pragma unroll
    for (int i = 0; i < 8; i++) { s += v[i]; q += v[i] * v[i]; }
    #pragma unroll
    for (int o = 16; o > 0; o >>= 1) {
        s += __shfl_xor_sync(0xffffffffu, s, o);
        q += __shfl_xor_sync(0xffffffffu, q, o);
    }
    float mu = s * (1.0f / 256.0f);
    float var = q * (1.0f / 256.0f) - mu * mu;
    float rinv = rsqrtf(var + 1e-5f);

    float4* sp = (float4*)(seq + (size_t)m * 256) + lane * 2;
    sp[0] = make_float4(v[0], v[1], v[2], v[3]);
    sp[1] = make_float4(v[4], v[5], v[6], v[7]);

    const float4* gp = (const float4*)(lg) + lane * 2;
    const float4* bp = (const float4*)(lb) + lane * 2;
    float4 g0 = gp[0], g1 = gp[1], bb0 = bp[0], bb1 = bp[1];
    __half2 h[4];
    h[0] = __floats2half2_rn((v[0]-mu)*rinv*g0.x+bb0.x, (v[1]-mu)*rinv*g0.y+bb0.y);
    h[1] = __floats2half2_rn((v[2]-mu)*rinv*g0.z+bb0.z, (v[3]-mu)*rinv*g0.w+bb0.w);
    h[2] = __floats2half2_rn((v[4]-mu)*rinv*g1.x+bb1.x, (v[5]-mu)*rinv*g1.y+bb1.y);
    h[3] = __floats2half2_rn((v[6]-mu)*rinv*g1.z+bb1.z, (v[7]-mu)*rinv*g1.w+bb1.w);
    *(uint4*)(s2h + (size_t)m * 256 + lane * 8) = *(uint4*)h;
}

// ---------------- gather last valid patch (half, compacted) ----------------
template<int SCALE>
__global__ void gather_kernel(const float* __restrict__ seq, __half* __restrict__ comb,
                              int off, int MBc, int rowoff) {
    int idx = blockIdx.x * blockDim.x + threadIdx.x;
    if (idx >= NSEQ * HID) return;
    int h = idx & 255;
    int bt = idx >> 8;
    int t = bt & (LSEQ - 1);
    int b = bt >> 7;
    int n = nfun<SCALE>(t);
    int m = rowoff + b * MBc + Sfun<SCALE>(t) + n - 1;
    comb[bt * 512 + off + h] = __float2half_rn(seq[(size_t)m * HID + h]);
}

// ---------------- final layernorm: warp per row, fp32 out ----------------
__global__ void ln_final(const float* __restrict__ in, const float* __restrict__ g,
                         const float* __restrict__ b, float* __restrict__ out) {
    int warp = threadIdx.x >> 5, lane = threadIdx.x & 31;
    size_t row = (size_t)blockIdx.x * 8 + warp;
    const float4* p = (const float4*)(in + row * 256);
    float4 v0 = p[lane], v1 = p[lane + 32];
    float s = v0.x + v0.y + v0.z + v0.w + v1.x + v1.y + v1.z + v1.w;
    #pragma unroll
    for (int o = 16; o > 0; o >>= 1) s += __shfl_xor_sync(0xffffffffu, s, o);
    float mu = s * (1.0f / 256.0f);
    float d0x = v0.x - mu, d0y = v0.y - mu, d0z = v0.z - mu, d0w = v0.w - mu;
    float d1x = v1.x - mu, d1y = v1.y - mu, d1z = v1.z - mu, d1w = v1.w - mu;
    float q = d0x*d0x + d0y*d0y + d0z*d0z + d0w*d0w
            + d1x*d1x + d1y*d1y + d1z*d1z + d1w*d1w;
    #pragma unroll
    for (int o = 16; o > 0; o >>= 1) q += __shfl_xor_sync(0xffffffffu, q, o);
    float r = rsqrtf(q * (1.0f / 256.0f) + 1e-5f);
    const float4* gp = (const float4*)g;
    const float4* bp = (const float4*)b;
    float4 g0 = gp[lane], g1 = gp[lane + 32];
    float4 b0 = bp[lane], b1 = bp[lane + 32];
    float4* po = (float4*)(out + row * 256);
    po[lane]      = make_float4(d0x*r*g0.x+b0.x, d0y*r*g0.y+b0.y, d0z*r*g0.z+b0.z, d0w*r*g0.w+b0.w);
    po[lane + 32] = make_float4(d1x*r*g1.x+b1.x, d1y*r*g1.y+b1.y, d1z*r*g1.z+b1.z, d1w*r*g1.w+b1.w);
}

// ---------------- fp16 mma.sync GEMM: 512 threads, 16 warps (32x64 tiles) ----------------
// EPI: 0 bias->fp32; 1 bias+gelu->half; 2 bias+residual->fp32;
//      3 bias+residual->fp32 + fused LN -> half (N==256, grid.x==1); 4 bias->half
#define HSTAGE 12288
#define HSMEM  (3 * HSTAGE * 2)
template<int EPI>
__global__ void __launch_bounds__(512, 1) hgemm_kernel(
        const __half* __restrict__ A, const __half* __restrict__ BT,
        const float* __restrict__ bias, void* __restrict__ Cv,
        int N, int K,
        const float* __restrict__ lng, const float* __restrict__ lnb,
        __half* __restrict__ lnout) {
    extern __shared__ __half sm[];
    const uint32_t sb = smem_u32(sm);
    const int tid = threadIdx.x, lane = tid & 31, warp = tid >> 5;     // 0..15
    const int bm = blockIdx.y << 7, bn = blockIdx.x << 8;
    const int wm = (warp & 3) << 5;        // 0,32,64,96
    const int wn = (warp >> 2) << 6;       // 0,64,128,192
    const int nc = K >> 5;

    float acc[2][8][4];
    #pragma unroll
    for (int mi = 0; mi < 2; mi++)
        #pragma unroll
        for (int j = 0; j < 8; j++)
            #pragma unroll
            for (int q = 0; q < 4; q++) acc[mi][j][q] = 0.0f;

    auto issue = [&](int c) {
        const int koff = c << 5;
        const uint32_t stg = sb + (uint32_t)((c % 3) * HSTAGE) * 2u;
        {   // A: 512 segs, 1 per thread
            int row = tid >> 2, sc = tid & 3;
            uint32_t dst = stg + (uint32_t)(row * 32 + ((sc ^ ((row >> 1) & 3)) << 3)) * 2u;
            cp16(dst, A + (size_t)(bm + row) * K + koff + sc * 8);
        }
        #pragma unroll
        for (int i = 0; i < 2; i++) {  // B: 1024 segs, 2 per thread
            int seg = tid + i * 512;
            int row = seg >> 2, sc = seg & 3;
            uint32_t dst = stg + (uint32_t)(4096 + row * 32 + ((sc ^ ((row >> 1) & 3)) << 3)) * 2u;
            cp16(dst, BT + (size_t)(bn + row) * K + koff + sc * 8);
        }
    };

    #pragma unroll
    for (int s = 0; s < 2; s++) {
        if (s < nc) issue(s);
        cp_commit();
    }

    const int r_lo = lane >> 2, wv = lane & 3;
    const int arow = wm + (lane & 15);
    const int asel = (lane >> 4) & 1;
    int brow[4], bsel[4];
    {
        int i = lane >> 3;
        #pragma unroll
        for (int g = 0; g < 4; g++) {
            brow[g] = wn + ((g << 1) + (i >> 1)) * 8 + (lane & 7);
            bsel[g] = i & 1;
        }
    }

    for (int c = 0; c < nc; c++) {
        cp_wait<1>();
        __syncthreads();
        if (c + 2 < nc) issue(c + 2);
        cp_commit();

        const uint32_t stA = sb + (uint32_t)((c % 3) * HSTAGE) * 2u;
        const uint32_t stB = stA + 8192u;
        #pragma unroll
        for (int kk = 0; kk < 2; kk++) {
            uint32_t a[2][4];
            #pragma unroll
            for (int mi = 0; mi < 2; mi++) {
                int r = arow + mi * 16;
                uint32_t ad = stA + (uint32_t)(r * 64 + ((((kk << 1) | asel) ^ ((r >> 1) & 3)) << 4));
                ldsm4(a[mi][0], a[mi][1], a[mi][2], a[mi][3], ad);
            }
            uint32_t bf[8][2];
            #pragma unroll
            for (int g = 0; g < 4; g++) {
                int r = brow[g];
                uint32_t bd = stB + (uint32_t)(r * 64 + ((((kk << 1) | bsel[g]) ^ ((r >> 1) & 3)) << 4));
                ldsm4(bf[2*g][0], bf[2*g][1], bf[2*g+1][0], bf[2*g+1][1], bd);
            }
            #pragma unroll
            for (int j = 0; j < 8; j++)
                #pragma unroll
                for (int mi = 0; mi < 2; mi++)
                    mma_f16(acc[mi][j], a[mi], bf[j][0], bf[j][1]);
        }
    }

    if (EPI == 3) {
        float* C = (float*)Cv;
        #pragma unroll
        for (int mi = 0; mi < 2; mi++) {
            const int r = bm + wm + mi * 16 + r_lo;
            #pragma unroll
            for (int j = 0; j < 8; j++) {
                const int cl = wn + j * 8 + wv * 2;
                float bf0 = bias[cl], bf1 = bias[cl + 1];
                float2* p0 = (float2*)(C + (size_t)r * 256 + cl);
                float2* p1 = (float2*)(C + (size_t)(r + 8) * 256 + cl);
                float2 o0 = *p0, o1 = *p1;
                acc[mi][j][0] += bf0 + o0.x; acc[mi][j][1] += bf1 + o0.y;
                acc[mi][j][2] += bf0 + o1.x; acc[mi][j][3] += bf1 + o1.y;
                *p0 = make_float2(acc[mi][j][0], acc[mi][j][1]);
                *p1 = make_float2(acc[mi][j][2], acc[mi][j][3]);
            }
        }
        float2* red = (float2*)sm;   // [128][4]
        float sums[4], sqs[4];
        #pragma unroll
        for (int mi = 0; mi < 2; mi++) {
            #pragma unroll
            for (int rr = 0; rr < 2; rr++) {
                float s = 0.0f, q = 0.0f;
                #pragma unroll
                for (int j = 0; j < 8; j++) {
                    float v0 = acc[mi][j][rr * 2], v1 = acc[mi][j][rr * 2 + 1];
                    s += v0 + v1; q += v0 * v0 + v1 * v1;
                }
                s += __shfl_xor_sync(0xffffffffu, s, 1);
                s += __shfl_xor_sync(0xffffffffu, s, 2);
                q += __shfl_xor_sync(0xffffffffu, q, 1);
                q += __shfl_xor_sync(0xffffffffu, q, 2);
                sums[mi * 2 + rr] = s; sqs[mi * 2 + rr] = q;
            }
        }
        const int wn_i = warp >> 2;
        __syncthreads();
        if (wv == 0) {
            #pragma unroll
            for (int idx = 0; idx < 4; idx++) {
                int rl = wm + (idx >> 1) * 16 + r_lo + (idx & 1) * 8;
                red[rl * 4 + wn_i] = make_float2(sums[idx], sqs[idx]);
            }
        }
        __syncthreads();
        float mus[4], rinvs[4];
        #pragma unroll
        for (int idx = 0; idx < 4; idx++) {
            int rl = wm + (idx >> 1) * 16 + r_lo + (idx & 1) * 8;
            float S = 0.0f, Q = 0.0f;
            #pragma unroll
            for (int w = 0; w < 4; w++) {
                float2 e = red[rl * 4 + w];
                S += e.x; Q += e.y;
            }
            float mu = S * (1.0f / 256.0f);
            mus[idx] = mu;
            rinvs[idx] = rsqrtf(Q * (1.0f / 256.0f) - mu * mu + 1e-5f);
        }
        #pragma unroll
        for (int mi = 0; mi < 2; mi++) {
            const int r = bm + wm + mi * 16 + r_lo;
            #pragma unroll
            for (int j = 0; j < 8; j++) {
                const int cl = wn + j * 8 + wv * 2;
                float gg0 = lng[cl], gg1 = lng[cl + 1];
                float bb0 = lnb[cl], bb1 = lnb[cl + 1];
                float mu0 = mus[mi * 2], ri0 = rinvs[mi * 2];
                float mu1 = mus[mi * 2 + 1], ri1 = rinvs[mi * 2 + 1];
                *(__half2*)(lnout + (size_t)r * 256 + cl) =
                    __floats2half2_rn((acc[mi][j][0] - mu0) * ri0 * gg0 + bb0,
                                      (acc[mi][j][1] - mu0) * ri0 * gg1 + bb1);
                *(__half2*)(lnout + (size_t)(r + 8) * 256 + cl) =
                    __floats2half2_rn((acc[mi][j][2] - mu1) * ri1 * gg0 + bb0,
                                      (acc[mi][j][3] - mu1) * ri1 * gg1 + bb1);
            }
        }
        return;
    }

    #pragma unroll
    for (int mi = 0; mi < 2; mi++) {
        const int r = bm + wm + mi * 16 + r_lo;
        #pragma unroll
        for (int j = 0; j < 8; j++) {
            const int cl = bn + wn + j * 8 + wv * 2;
            float bf0 = bias[cl], bf1 = bias[cl + 1];
            float v0 = acc[mi][j][0] + bf0, v1 = acc[mi][j][1] + bf1;
            float v2 = acc[mi][j][2] + bf0, v3 = acc[mi][j][3] + bf1;
            if (EPI == 0) {
                float* C = (float*)Cv;
                *(float2*)(C + (size_t)r * N + cl)       = make_float2(v0, v1);
                *(float2*)(C + (size_t)(r + 8) * N + cl) = make_float2(v2, v3);
            } else if (EPI == 1) {
                __half* C = (__half*)Cv;
                *(__half2*)(C + (size_t)r * N + cl) =
                    __floats2half2_rn(gelu_exact(v0), gelu_exact(v1));
                *(__half2*)(C + (size_t)(r + 8) * N + cl) =
                    __floats2half2_rn(gelu_exact(v2), gelu_exact(v3));
            } else if (EPI == 4) {
                __half* C = (__half*)Cv;
                *(__half2*)(C + (size_t)r * N + cl)       = __floats2half2_rn(v0, v1);
                *(__half2*)(C + (size_t)(r + 8) * N + cl) = __floats2half2_rn(v2, v3);
            } else {
                float* C = (float*)Cv;
                float2* p0 = (float2*)(C + (size_t)r * N + cl);
                float2* p1 = (float2*)(C + (size_t)(r + 8) * N + cl);
                float2 o0 = *p0, o1 = *p1;
                *p0 = make_float2(o0.x + v0, o0.y + v1);
                *p1 = make_float2(o1.x + v2, o1.y + v3);
            }
        }
    }
}

// ---------------- attention (compacted, half qkv) ----------------
template<int SCALE, int NMAX>
__global__ void attn_kernel(const __half* __restrict__ QKV, __half* __restrict__ O,
                            int MBc, int rowoff) {
    __shared__ float Ks[NMAX][32];
    __shared__ float Vs[NMAX][32];
    int bt = blockIdx.x, head = blockIdx.y;
    int t = bt & (LSEQ - 1);
    int b = bt >> 7;
    int n = nfun<SCALE>(t);
    int rb = rowoff + b * MBc + Sfun<SCALE>(t);
    size_t base = (size_t)rb * 768 + head * DHEAD;

    for (int i = threadIdx.x; i < NMAX * 16; i += blockDim.x) {
        int kk = i >> 4, d = (i & 15) << 1;
        float2 kv = make_float2(0.f, 0.f), vv = make_float2(0.f, 0.f);
        if (kk < n) {
            kv = __half22float2(*(const __half2*)(QKV + base + (size_t)kk * 768 + 256 + d));
            vv = __half22float2(*(const __half2*)(QKV + base + (size_t)kk * 768 + 512 + d));
        }
        Ks[kk][d] = kv.x; Ks[kk][d + 1] = kv.y;
        Vs[kk][d] = vv.x; Vs[kk][d + 1] = vv.y;
    }
    __syncthreads();

    int tq = threadIdx.x;
    if (tq < n) {
        float qr[32];
        #pragma unroll
        for (int d = 0; d < 32; d += 2) {
            float2 qv = __half22float2(*(const __half2*)(QKV + base + (size_t)tq * 768 + d));
            qr[d] = qv.x; qr[d + 1] = qv.y;
        }
        float sc[NMAX];
        float mx = -1e30f;
        #pragma unroll
        for (int kk = 0; kk < NMAX; kk++) {
            float s = 0.0f;
            #pragma unroll
            for (int d = 0; d < 32; d++) s += qr[d] * Ks[kk][d];
            s *= 0.17677669529663687f;
            sc[kk] = (kk < n) ? s : -1e30f;
            mx = fmaxf(mx, sc[kk]);
        }
        float ssum = 0.0f;
        #pragma unroll
        for (int kk = 0; kk < NMAX; kk++) {
            float e = (kk < n) ? expf(sc[kk] - mx) : 0.0f;
            sc[kk] = e;
            ssum += e;
        }
        float inv = 1.0f / ssum;
        __half* op = O + (size_t)(rb + tq) * HID + head * DHEAD;
        #pragma unroll
        for (int d = 0; d < 32; d += 2) {
            float o0 = 0.0f, o1 = 0.0f;
            #pragma unroll
            for (int kk = 0; kk < NMAX; kk++) {
                o0 += sc[kk] * Vs[kk][d];
                o1 += sc[kk] * Vs[kk][d + 1];
            }
            *(__half2*)(op + d) = __floats2half2_rn(o0 * inv, o1 * inv);
        }
    }
}

// ---------------- host side ----------------
static inline void gemm(const __half* A, const __half* WT, const float* bias, void* C,
                        int Mp, int N, int K, int epi,
                        const float* lng = nullptr, const float* lnb = nullptr,
                        __half* lnout = nullptr) {
    dim3 grid(N >> 8, Mp >> 7), block(512);
    if (epi == 0)      hgemm_kernel<0><<<grid, block, HSMEM>>>(A, WT, bias, C, N, K, lng, lnb, lnout);
    else if (epi == 1) hgemm_kernel<1><<<grid, block, HSMEM>>>(A, WT, bias, C, N, K, lng, lnb, lnout);
    else if (epi == 2) hgemm_kernel<2><<<grid, block, HSMEM>>>(A, WT, bias, C, N, K, lng, lnb, lnout);
    else if (epi == 3) hgemm_kernel<3><<<grid, block, HSMEM>>>(A, WT, bias, C, N, K, lng, lnb, lnout);
    else               hgemm_kernel<4><<<grid, block, HSMEM>>>(A, WT, bias, C, N, K, lng, lnb, lnout);
}

extern "C" void kernel_launch(void* const* d_in, const int* in_sizes, int n_in,
                              void* d_out, int out_size) {
    cudaFuncSetAttribute(hgemm_kernel<0>, cudaFuncAttributeMaxDynamicSharedMemorySize, HSMEM);
    cudaFuncSetAttribute(hgemm_kernel<1>, cudaFuncAttributeMaxDynamicSharedMemorySize, HSMEM);
    cudaFuncSetAttribute(hgemm_kernel<2>, cudaFuncAttributeMaxDynamicSharedMemorySize, HSMEM);
    cudaFuncSetAttribute(hgemm_kernel<3>, cudaFuncAttributeMaxDynamicSharedMemorySize, HSMEM);
    cudaFuncSetAttribute(hgemm_kernel<4>, cudaFuncAttributeMaxDynamicSharedMemorySize, HSMEM);

    const float* x       = (const float*)d_in[0];
    const float* w_proj[2] = { (const float*)d_in[1], (const float*)d_in[3] };
    const float* b_proj[2] = { (const float*)d_in[2], (const float*)d_in[4] };
    const float* pos[2]    = { (const float*)d_in[5], (const float*)d_in[6] };
    const float* ln1_g = (const float*)d_in[7];
    const float* ln1_b = (const float*)d_in[8];
    const float* wq = (const float*)d_in[9];
    const float* bq = (const float*)d_in[10];
    const float* wk = (const float*)d_in[11];
    const float* bk = (const float*)d_in[12];
    const float* wv = (const float*)d_in[13];
    const float* bv = (const float*)d_in[14];
    const float* wo = (const float*)d_in[15];
    const float* bo = (const float*)d_in[16];
    const float* ln2_g = (const float*)d_in[17];
    const float* ln2_b = (const float*)d_in[18];
    const float* w_ff1 = (const float*)d_in[19];
    const float* b_ff1 = (const float*)d_in[20];
    const float* w_ff2 = (const float*)d_in[21];
    const float* b_ff2 = (const float*)d_in[22];
    const float* ln_g = (const float*)d_in[23];
    const float* ln_b = (const float*)d_in[24];
    const float* w_fus1 = (const float*)d_in[25];
    const float* b_fus1 = (const float*)d_in[26];
    const float* w_fus2 = (const float*)d_in[27];
    const float* b_fus2 = (const float*)d_in[28];

    __half *winh, *qkvh, *s2h, *ffh, *combh, *wth;
    float *tokens, *seq, *bqkv;
    cudaGetSymbolAddress((void**)&winh,   g_winh);
    cudaGetSymbolAddress((void**)&tokens, g_tokens);
    cudaGetSymbolAddress((void**)&seq,    g_seq);
    cudaGetSymbolAddress((void**)&qkvh,   g_qkvh);
    cudaGetSymbolAddress((void**)&s2h,    g_s2h);
    cudaGetSymbolAddress((void**)&ffh,    g_ffh);
    cudaGetSymbolAddress((void**)&combh,  g_combh);
    cudaGetSymbolAddress((void**)&wth,    g_wth);
    cudaGetSymbolAddress((void**)&bqkv,   g_bqkv);

    __half* wt_proj0 = wth;
    __half* wt_proj1 = wth + 16384;
    __half* wt_qkv   = wth + 49152;
    __half* wt_o     = wth + 442368;
    __half* wt_ff1   = wth + 573440;
    __half* wt_ff2   = wth + 1097728;
    __half* wt_fus1  = wth + 1622016;
    __half* wt_fus2  = wth + 1753088;

    WtJobs jobs;
    int nt = 0, nj = 0;
    auto addjob = [&](const float* src, __half* dst, int K, int N) {
        jobs.src[nj] = src; jobs.dst[nj] = dst; jobs.K[nj] = K; jobs.N[nj] = N;
        jobs.t0[nj] = nt; nt += (N / 32) * (K / 32); nj++;
    };
    addjob(w_proj[0], wt_proj0, 64, 256);
    addjob(w_proj[1], wt_proj1, 128, 256);
    for (int li = 0; li < 2; li++) {
        addjob(wq + li * 65536, wt_qkv + li * 196608,          256, 256);
        addjob(wk + li * 65536, wt_qkv + li * 196608 + 65536,  256, 256);
        addjob(wv + li * 65536, wt_qkv + li * 196608 + 131072, 256, 256);
        addjob(wo + li * 65536, wt_o + li * 65536, 256, 256);
        addjob(w_ff1 + li * 262144, wt_ff1 + li * 262144, 256, 1024);
        addjob(w_ff2 + li * 262144, wt_ff2 + li * 262144, 1024, 256);
    }
    addjob(w_fus1, wt_fus1, 512, 256);
    addjob(w_fus2, wt_fus2, 256, 256);
    wt_fused<<<nt, 256>>>(jobs, nj);
    for (int li = 0; li < 2; li++) {
        cudaMemcpyAsync(bqkv + li * 768,       bq + li * 256, 1024, cudaMemcpyDeviceToDevice);
        cudaMemcpyAsync(bqkv + li * 768 + 256, bk + li * 256, 1024, cudaMemcpyDeviceToDevice);
        cudaMemcpyAsync(bqkv + li * 768 + 512, bv + li * 256, 1024, cudaMemcpyDeviceToDevice);
    }

    const int PL[2] = {8, 16}, ST[2] = {4, 8}, EE[2] = {136, 128}, NMX[2] = {34, 16};
    const int MP[2] = {1152, 1024};
    const int MBB[2] = {MB0, MB1}, ROFF[2] = {0, MC0};

    for (int s = 0; s < 2; s++) {
        int pl = PL[s], st = ST[s], E = EE[s], NMAX = NMX[s];
        int plc = pl * CH;
        int BE = BATCH * E;
        { int tot = BE * plc;
          win_kernel<<<(tot + 255) / 256, 256>>>(x, winh, E, pl); }
        gemm(winh, s == 0 ? wt_proj0 : wt_proj1, b_proj[s], tokens, MP[s], HID, plc, 0);
        { int nwarp = NSEQ * NMAX;
          int blocks = (nwarp + 7) / 8;
          if (s == 0) build_seq_ln<0><<<blocks, 256>>>(tokens, pos[s], ln1_g, ln1_b,
                                                       seq, s2h, NMAX, E, pl, st, MBB[s], ROFF[s]);
          else        build_seq_ln<1><<<blocks, 256>>>(tokens, pos[s], ln1_g, ln1_b,
                                                       seq, s2h, NMAX, E, pl, st, MBB[s], ROFF[s]);
        }
    }

    for (int li = 0; li < 2; li++) {
        gemm(s2h, wt_qkv + li * 196608, bqkv + li * 768, qkvh, MTOT, 768, HID, 4);
        dim3 ag(NSEQ, NHEAD);
        attn_kernel<0, 34><<<ag, 64>>>(qkvh, s2h, MB0, 0);
        attn_kernel<1, 16><<<ag, 64>>>(qkvh, s2h, MB1, MC0);
        gemm(s2h, wt_o + li * 65536, bo + li * HID, seq, MTOT, HID, HID, 3,
             ln2_g + li * HID, ln2_b + li * HID, s2h);
        gemm(s2h, wt_ff1 + li * 262144, b_ff1 + li * FFD, ffh, MTOT, FFD, HID, 1);
        if (li == 0)
            gemm(ffh, wt_ff2 + li * 262144, b_ff2 + li * HID, seq, MTOT, HID, FFD, 3,
                 ln1_g + HID, ln1_b + HID, s2h);
        else
            gemm(ffh, wt_ff2 + li * 262144, b_ff2 + li * HID, seq, MTOT, HID, FFD, 2);
    }

    { int tot = NSEQ * HID;
      int blocks = (tot + 255) / 256;
      gather_kernel<0><<<blocks, 256>>>(seq, combh, 0, MB0, 0);
      gather_kernel<1><<<blocks, 256>>>(seq, combh, 256, MB1, MC0);
    }
    gemm(combh, wt_fus1, b_fus1, s2h, NSEQ, HID, 2 * HID, 1);
    gemm(s2h, wt_fus2, b_fus2, seq, NSEQ, HID, HID, 0);
    ln_final<<<NSEQ / 8, 256>>>(seq, ln_g, ln_b, (float*)d_out);
}

// round 15
// speedup vs baseline: 7.2797x; 1.0676x over previous
#include <cuda_runtime.h>
#include <cuda_fp16.h>
#include <math.h>
#include <stdint.h>

#define LSEQ   128
#define BATCH  8
#define CH     8
#define HID    256
#define NHEAD  8
#define DHEAD  32
#define FFD    1024
#define MAXPADC 15
#define NSEQ   1024

#define MB0 2368
#define MB1 1088
#define MC0 18944
#define MC1 8704
#define MTOT 27648

__device__ __half  g_winh[147456];
__device__ float   g_tokens[294912];
__device__ float   g_seq[MTOT * 256];
__device__ __half  g_qkvh[MTOT * 768];
__device__ __half  g_s2h[MTOT * 256];
__device__ __half  g_ffh[MTOT * 1024];
__device__ __half  g_combh[1024 * 512];
__device__ __half  g_wth[1818624];
__device__ float   g_bqkv[1536];

__device__ __forceinline__ float gelu_exact(float x) {
    return 0.5f * x * (1.0f + erff(x * 0.7071067811865476f));
}
__device__ __forceinline__ uint32_t smem_u32(const void* p) {
    uint32_t a;
    asm("{ .reg .u64 t; cvta.to.shared.u64 t, %1; cvt.u32.u64 %0, t; }" : "=r"(a) : "l"(p));
    return a;
}
__device__ __forceinline__ void cp16(uint32_t dst, const void* src) {
    asm volatile("cp.async.cg.shared.global [%0], [%1], 16;" :: "r"(dst), "l"(src));
}
__device__ __forceinline__ void cp_commit() {
    asm volatile("cp.async.commit_group;" ::: "memory");
}
template<int N>
__device__ __forceinline__ void cp_wait() {
    asm volatile("cp.async.wait_group %0;" :: "n"(N) : "memory");
}
__device__ __forceinline__ void mma_f16(float* c, const uint32_t* a,
                                        uint32_t b0, uint32_t b1) {
    asm volatile(
        "mma.sync.aligned.m16n8k16.row.col.f32.f16.f16.f32 "
        "{%0,%1,%2,%3}, {%4,%5,%6,%7}, {%8,%9}, {%0,%1,%2,%3};\n"
        : "+f"(c[0]), "+f"(c[1]), "+f"(c[2]), "+f"(c[3])
        : "r"(a[0]), "r"(a[1]), "r"(a[2]), "r"(a[3]), "r"(b0), "r"(b1));
}
__device__ __forceinline__ void ldsm4(uint32_t& r0, uint32_t& r1, uint32_t& r2,
                                      uint32_t& r3, uint32_t addr) {
    asm volatile("ldmatrix.sync.aligned.m8n8.x4.shared.b16 {%0,%1,%2,%3}, [%4];"
                 : "=r"(r0), "=r"(r1), "=r"(r2), "=r"(r3) : "r"(addr));
}
template<int SCALE>
__device__ __forceinline__ int nfun(int t) {
    return SCALE == 0 ? ((t + 8) >> 2) + 1 : (t >> 3) + 1;
}
template<int SCALE>
__device__ __forceinline__ int Sfun(int t) {
    if (SCALE == 0) {
        int m = t + 8, q = m >> 2, r = m & 3;
        return t + 2 * q * (q - 1) + r * q - 4;
    } else {
        int q = t >> 3, r = t & 7;
        return t + 4 * q * (q - 1) + r * q;
    }
}

#define NJOBS 16
struct WtJobs {
    const float* src[NJOBS];
    __half*      dst[NJOBS];
    int K[NJOBS], N[NJOBS], t0[NJOBS];
};
__global__ void wt_fused(WtJobs jobs, int njobs) {
    __shared__ float t[32][33];
    int tile = blockIdx.x;
    int ji = 0;
    #pragma unroll 1
    while (ji + 1 < njobs && tile >= jobs.t0[ji + 1]) ji++;
    int lt = tile - jobs.t0[ji];
    int K = jobs.K[ji], N = jobs.N[ji];
    int tn = N >> 5;
    int nb = (lt % tn) * 32, kb = (lt / tn) * 32;
    const float* W = jobs.src[ji];
    __half* WT = jobs.dst[ji];
    int tx = threadIdx.x & 31, ty = threadIdx.x >> 5;
    #pragma unroll
    for (int i = 0; i < 32; i += 8)
        t[ty + i][tx] = W[(size_t)(kb + ty + i) * N + nb + tx];
    __syncthreads();
    #pragma unroll
    for (int i = 0; i < 32; i += 8)
        WT[(size_t)(nb + ty + i) * K + kb + tx] = __float2half_rn(t[tx][ty + i]);
}

__global__ void win_kernel(const float* __restrict__ x, __half* __restrict__ win,
                           int E, int pl) {
    int plc = pl * CH;
    int tot = BATCH * E * plc;
    int idx = blockIdx.x * blockDim.x + threadIdx.x;
    if (idx >= tot) return;
    int r = idx % plc;
    int e = (idx / plc) % E;
    int b = idx / (plc * E);
    int p = r >> 3, c = r & 7;
    int i = e + p;
    win[idx] = __float2half_rn((i < MAXPADC) ? 0.0f : x[(b * LSEQ + (i - MAXPADC)) * CH + c]);
}

template<int SCALE>
__global__ void build_seq_ln(const float* __restrict__ tokens,
                             const float* __restrict__ pos,
                             const float* __restrict__ lg, const float* __restrict__ lb,
                             float* __restrict__ seq, __half* __restrict__ s2h,
                             int NMAX, int E, int pl, int st, int MBc, int rowoff) {
    int wid = threadIdx.x >> 5, lane = threadIdx.x & 31;
    int wg = blockIdx.x * 8 + wid;
    if (wg >= NSEQ * NMAX) return;
    int k = wg % NMAX, bt = wg / NMAX;
    int t = bt & (LSEQ - 1), b = bt >> 7;
    int n = nfun<SCALE>(t);
    if (k >= n) return;
    int ends = t + MAXPADC - (n - 1) * st + k * st;
    int j = ends - (pl - 1);
    j = j < 0 ? 0 : (j > E - 1 ? E - 1 : j);
    int m = rowoff + b * MBc + Sfun<SCALE>(t) + k;

    const float4* tp = (const float4*)(tokens + (size_t)(b * E + j) * 256) + lane * 2;
    const float4* pp = (const float4*)(pos + k * 256) + lane * 2;
    float4 t0 = tp[0], t1 = tp[1], p0 = pp[0], p1 = pp[1];
    float v[8] = { t0.x + p0.x, t0.y + p0.y, t0.z + p0.z, t0.w + p0.w,
                   t1.x + p1.x, t1.y + p1.y, t1.z + p1.z, t1.w + p1.w };
    float s = 0.0f, q = 0.0f;
    #pragma unroll
    for (int i = 0; i < 8; i++) { s += v[i]; q += v[i] * v[i]; }
    #pragma unroll
    for (int o = 16; o > 0; o >>= 1) {
        s += __shfl_xor_sync(0xffffffffu, s, o);
        q += __shfl_xor_sync(0xffffffffu, q, o);
    }
    float mu = s * (1.0f / 256.0f);
    float var = q * (1.0f / 256.0f) - mu * mu;
    float rinv = rsqrtf(var + 1e-5f);

    float4* sp = (float4*)(seq + (size_t)m * 256) + lane * 2;
    sp[0] = make_float4(v[0], v[1], v[2], v[3]);
    sp[1] = make_float4(v[4], v[5], v[6], v[7]);

    const float4* gp = (const float4*)(lg) + lane * 2;
    const float4* bp = (const float4*)(lb) + lane * 2;
    float4 g0 = gp[0], g1 = gp[1], bb0 = bp[0], bb1 = bp[1];
    __half2 h[4];
    h[0] = __floats2half2_rn((v[0]-mu)*rinv*g0.x+bb0.x, (v[1]-mu)*rinv*g0.y+bb0.y);
    h[1] = __floats2half2_rn((v[2]-mu)*rinv*g0.z+bb0.z, (v[3]-mu)*rinv*g0.w+bb0.w);
    h[2] = __floats2half2_rn((v[4]-mu)*rinv*g1.x+bb1.x, (v[5]-mu)*rinv*g1.y+bb1.y);
    h[3] = __floats2half2_rn((v[6]-mu)*rinv*g1.z+bb1.z, (v[7]-mu)*rinv*g1.w+bb1.w);
    *(uint4*)(s2h + (size_t)m * 256 + lane * 8) = *(uint4*)h;
}

template<int SCALE>
__global__ void gather_kernel(const float* __restrict__ seq, __half* __restrict__ comb,
                              int off, int MBc, int rowoff) {
    int idx = blockIdx.x * blockDim.x + threadIdx.x;
    if (idx >= NSEQ * HID) return;
    int h = idx & 255;
    int bt = idx >> 8;
    int t = bt & (LSEQ - 1);
    int b = bt >> 7;
    int n = nfun<SCALE>(t);
    int m = rowoff + b * MBc + Sfun<SCALE>(t) + n - 1;
    comb[bt * 512 + off + h] = __float2half_rn(seq[(size_t)m * HID + h]);
}

__global__ void ln_final(const float* __restrict__ in, const float* __restrict__ g,
                         const float* __restrict__ b, float* __restrict__ out) {
    int warp = threadIdx.x >> 5, lane = threadIdx.x & 31;
    size_t row = (size_t)blockIdx.x * 8 + warp;
    const float4* p = (const float4*)(in + row * 256);
    float4 v0 = p[lane], v1 = p[lane + 32];
    float s = v0.x + v0.y + v0.z + v0.w + v1.x + v1.y + v1.z + v1.w;
    #pragma unroll
    for (int o = 16; o > 0; o >>= 1) s += __shfl_xor_sync(0xffffffffu, s, o);
    float mu = s * (1.0f / 256.0f);
    float d0x = v0.x - mu, d0y = v0.y - mu, d0z = v0.z - mu, d0w = v0.w - mu;
    float d1x = v1.x - mu, d1y = v1.y - mu, d1z = v1.z - mu, d1w = v1.w - mu;
    float q = d0x*d0x + d0y*d0y + d0z*d0z + d0w*d0w
            + d1x*d1x + d1y*d1y + d1z*d1z + d1w*d1w;
    #pragma unroll
    for (int o = 16; o > 0; o >>= 1) q += __shfl_xor_sync(0xffffffffu, q, o);
    float r = rsqrtf(q * (1.0f / 256.0f) + 1e-5f);
    const float4* gp = (const float4*)g;
    const float4* bp = (const float4*)b;
    float4 g0 = gp[lane], g1 = gp[lane + 32];
    float4 b0 = bp[lane], b1 = bp[lane + 32];
    float4* po = (float4*)(out + row * 256);
    po[lane]      = make_float4(d0x*r*g0.x+b0.x, d0y*r*g0.y+b0.y, d0z*r*g0.z+b0.z, d0w*r*g0.w+b0.w);
    po[lane + 32] = make_float4(d1x*r*g1.x+b1.x, d1y*r*g1.y+b1.y, d1z*r*g1.z+b1.z, d1w*r*g1.w+b1.w);
}

#define HSTAGE 12288
#define HSMEM  (3 * HSTAGE * 2)
template<int EPI>
__global__ void __launch_bounds__(512, 1) hgemm_kernel(
        const __half* __restrict__ A, const __half* __restrict__ BT,
        const float* __restrict__ bias, void* __restrict__ Cv,
        int N, int K) {
    extern __shared__ __half sm[];
    const uint32_t sb = smem_u32(sm);
    const int tid = threadIdx.x, lane = tid & 31, warp = tid >> 5;
    const int bm = blockIdx.y << 7, bn = blockIdx.x << 8;
    const int wm = (warp & 3) << 5;
    const int wn = (warp >> 2) << 6;
    const int nc = K >> 5;

    float acc[2][8][4];
    #pragma unroll
    for (int mi = 0; mi < 2; mi++)
        #pragma unroll
        for (int j = 0; j < 8; j++)
            #pragma unroll
            for (int q = 0; q < 4; q++) acc[mi][j][q] = 0.0f;

    auto issue = [&](int c) {
        const int koff = c << 5;
        const uint32_t stg = sb + (uint32_t)((c % 3) * HSTAGE) * 2u;
        {
            int row = tid >> 2, sc = tid & 3;
            uint32_t dst = stg + (uint32_t)(row * 32 + ((sc ^ ((row >> 1) & 3)) << 3)) * 2u;
            cp16(dst, A + (size_t)(bm + row) * K + koff + sc * 8);
        }
        #pragma unroll
        for (int i = 0; i < 2; i++) {
            int seg = tid + i * 512;
            int row = seg >> 2, sc = seg & 3;
            uint32_t dst = stg + (uint32_t)(4096 + row * 32 + ((sc ^ ((row >> 1) & 3)) << 3)) * 2u;
            cp16(dst, BT + (size_t)(bn + row) * K + koff + sc * 8);
        }
    };

    #pragma unroll
    for (int s = 0; s < 2; s++) {
        if (s < nc) issue(s);
        cp_commit();
    }

    const int r_lo = lane >> 2, wv = lane & 3;
    const int arow = wm + (lane & 15);
    const int asel = (lane >> 4) & 1;
    int brow[4], bsel[4];
    {
        int i = lane >> 3;
        #pragma unroll
        for (int g = 0; g < 4; g++) {
            brow[g] = wn + ((g << 1) + (i >> 1)) * 8 + (lane & 7);
            bsel[g] = i & 1;
        }
    }

    for (int c = 0; c < nc; c++) {
        cp_wait<1>();
        __syncthreads();
        if (c + 2 < nc) issue(c + 2);
        cp_commit();

        const uint32_t stA = sb + (uint32_t)((c % 3) * HSTAGE) * 2u;
        const uint32_t stB = stA + 8192u;
        #pragma unroll
        for (int kk = 0; kk < 2; kk++) {
            uint32_t a[2][4];
            #pragma unroll
            for (int mi = 0; mi < 2; mi++) {
                int r = arow + mi * 16;
                uint32_t ad = stA + (uint32_t)(r * 64 + ((((kk << 1) | asel) ^ ((r >> 1) & 3)) << 4));
                ldsm4(a[mi][0], a[mi][1], a[mi][2], a[mi][3], ad);
            }
            uint32_t bf[8][2];
            #pragma unroll
            for (int g = 0; g < 4; g++) {
                int r = brow[g];
                uint32_t bd = stB + (uint32_t)(r * 64 + ((((kk << 1) | bsel[g]) ^ ((r >> 1) & 3)) << 4));
                ldsm4(bf[2*g][0], bf[2*g][1], bf[2*g+1][0], bf[2*g+1][1], bd);
            }
            #pragma unroll
            for (int j = 0; j < 8; j++)
                #pragma unroll
                for (int mi = 0; mi < 2; mi++)
                    mma_f16(acc[mi][j], a[mi], bf[j][0], bf[j][1]);
        }
    }

    #pragma unroll
    for (int mi = 0; mi < 2; mi++) {
        const int r = bm + wm + mi * 16 + r_lo;
        #pragma unroll
        for (int j = 0; j < 8; j++) {
            const int cl = bn + wn + j * 8 + wv * 2;
            float bf0 = bias[cl], bf1 = bias[cl + 1];
            float v0 = acc[mi][j][0] + bf0, v1 = acc[mi][j][1] + bf1;
            float v2 = acc[mi][j][2] + bf0, v3 = acc[mi][j][3] + bf1;
            if (EPI == 0) {
                float* C = (float*)Cv;
                *(float2*)(C + (size_t)r * N + cl)       = make_float2(v0, v1);
                *(float2*)(C + (size_t)(r + 8) * N + cl) = make_float2(v2, v3);
            } else if (EPI == 1) {
                __half* C = (__half*)Cv;
                *(__half2*)(C + (size_t)r * N + cl) =
                    __floats2half2_rn(gelu_exact(v0), gelu_exact(v1));
                *(__half2*)(C + (size_t)(r + 8) * N + cl) =
                    __floats2half2_rn(gelu_exact(v2), gelu_exact(v3));
            } else {
                __half* C = (__half*)Cv;
                *(__half2*)(C + (size_t)r * N + cl)       = __floats2half2_rn(v0, v1);
                *(__half2*)(C + (size_t)(r + 8) * N + cl) = __floats2half2_rn(v2, v3);
            }
        }
    }
}

#define H64STAGE 10240
#define H64SMEM  (3 * H64STAGE * 2)
template<int EPI>
__global__ void __launch_bounds__(512, 1) hgemm64_kernel(
        const __half* __restrict__ A, const __half* __restrict__ BT,
        const float* __restrict__ bias, float* __restrict__ C,
        int K,
        const float* __restrict__ lng, const float* __restrict__ lnb,
        __half* __restrict__ lnout) {
    extern __shared__ __half sm[];
    const uint32_t sb = smem_u32(sm);
    const int tid = threadIdx.x, lane = tid & 31, warp = tid >> 5;
    const int bm = blockIdx.y << 6;
    const int wm = (warp & 1) << 5;
    const int wn = (warp >> 1) << 5;
    const int nc = K >> 5;

    float acc[2][4][4];
    #pragma unroll
    for (int mi = 0; mi < 2; mi++)
        #pragma unroll
        for (int j = 0; j < 4; j++)
            #pragma unroll
            for (int q = 0; q < 4; q++) acc[mi][j][q] = 0.0f;

    auto issue = [&](int c) {
        const int koff = c << 5;
        const uint32_t stg = sb + (uint32_t)((c % 3) * H64STAGE) * 2u;
        if (tid < 256) {
            int row = tid >> 2, sc = tid & 3;
            uint32_t dst = stg + (uint32_t)(row * 32 + ((sc ^ ((row >> 1) & 3)) << 3)) * 2u;
            cp16(dst, A + (size_t)(bm + row) * K + koff + sc * 8);
        }
        #pragma unroll
        for (int i = 0; i < 2; i++) {
            int seg = tid + i * 512;
            int row = seg >> 2, sc = seg & 3;
            uint32_t dst = stg + (uint32_t)(2048 + row * 32 + ((sc ^ ((row >> 1) & 3)) << 3)) * 2u;
            cp16(dst, BT + (size_t)row * K + koff + sc * 8);
        }
    };

    #pragma unroll
    for (int s = 0; s < 2; s++) {
        if (s < nc) issue(s);
        cp_commit();
    }

    const int r_lo = lane >> 2, wv = lane & 3;
    const int arow = wm + (lane & 15);
    const int asel = (lane >> 4) & 1;
    int brow[2], bsel2;
    {
        int i = lane >> 3;
        bsel2 = i & 1;
        #pragma unroll
        for (int g = 0; g < 2; g++)
            brow[g] = wn + ((g << 1) + (i >> 1)) * 8 + (lane & 7);
    }

    for (int c = 0; c < nc; c++) {
        cp_wait<1>();
        __syncthreads();
        if (c + 2 < nc) issue(c + 2);
        cp_commit();

        const uint32_t stA = sb + (uint32_t)((c % 3) * H64STAGE) * 2u;
        const uint32_t stB = stA + 4096u;
        #pragma unroll
        for (int kk = 0; kk < 2; kk++) {
            uint32_t a[2][4];
            #pragma unroll
            for (int mi = 0; mi < 2; mi++) {
                int r = arow + mi * 16;
                uint32_t ad = stA + (uint32_t)(r * 64 + ((((kk << 1) | asel) ^ ((r >> 1) & 3)) << 4));
                ldsm4(a[mi][0], a[mi][1], a[mi][2], a[mi][3], ad);
            }
            uint32_t bf[4][2];
            #pragma unroll
            for (int g = 0; g < 2; g++) {
                int r = brow[g];
                uint32_t bd = stB + (uint32_t)(r * 64 + ((((kk << 1) | bsel2) ^ ((r >> 1) & 3)) << 4));
                ldsm4(bf[2*g][0], bf[2*g][1], bf[2*g+1][0], bf[2*g+1][1], bd);
            }
            #pragma unroll
            for (int j = 0; j < 4; j++)
                #pragma unroll
                for (int mi = 0; mi < 2; mi++)
                    mma_f16(acc[mi][j], a[mi], bf[j][0], bf[j][1]);
        }
    }

    #pragma unroll
    for (int mi = 0; mi < 2; mi++) {
        const int r = bm + wm + mi * 16 + r_lo;
        #pragma unroll
        for (int j = 0; j < 4; j++) {
            const int cl = wn + j * 8 + wv * 2;
            float bf0 = bias[cl], bf1 = bias[cl + 1];
            float2* p0 = (float2*)(C + (size_t)r * 256 + cl);
            float2* p1 = (float2*)(C + (size_t)(r + 8) * 256 + cl);
            float2 o0 = *p0, o1 = *p1;
            acc[mi][j][0] += bf0 + o0.x; acc[mi][j][1] += bf1 + o0.y;
            acc[mi][j][2] += bf0 + o1.x; acc[mi][j][3] += bf1 + o1.y;
            *p0 = make_float2(acc[mi][j][0], acc[mi][j][1]);
            *p1 = make_float2(acc[mi][j][2], acc[mi][j][3]);
        }
    }
    if (EPI == 2) return;

    float2* red = (float2*)sm;
    float sums[4], sqs[4];
    #pragma unroll
    for (int mi = 0; mi < 2; mi++) {
        #pragma unroll
        for (int rr = 0; rr < 2; rr++) {
            float s = 0.0f, q = 0.0f;
            #pragma unroll
            for (int j = 0; j < 4; j++) {
                float v0 = acc[mi][j][rr * 2], v1 = acc[mi][j][rr * 2 + 1];
                s += v0 + v1; q += v0 * v0 + v1 * v1;
            }
            s += __shfl_xor_sync(0xffffffffu, s, 1);
            s += __shfl_xor_sync(0xffffffffu, s, 2);
            q += __shfl_xor_sync(0xffffffffu, q, 1);
            q += __shfl_xor_sync(0xffffffffu, q, 2);
            sums[mi * 2 + rr] = s; sqs[mi * 2 + rr] = q;
        }
    }
    const int wn_i = warp >> 1;
    __syncthreads();
    if (wv == 0) {
        #pragma unroll
        for (int idx = 0; idx < 4; idx++) {
            int rl = wm + (idx >> 1) * 16 + r_lo + (idx & 1) * 8;
            red[rl * 8 + wn_i] = make_float2(sums[idx], sqs[idx]);
        }
    }
    __syncthreads();
    float mus[4], rinvs[4];
    #pragma unroll
    for (int idx = 0; idx < 4; idx++) {
        int rl = wm + (idx >> 1) * 16 + r_lo + (idx & 1) * 8;
        float S = 0.0f, Q = 0.0f;
        #pragma unroll
        for (int w = 0; w < 8; w++) {
            float2 e = red[rl * 8 + w];
            S += e.x; Q += e.y;
        }
        float mu = S * (1.0f / 256.0f);
        mus[idx] = mu;
        rinvs[idx] = rsqrtf(Q * (1.0f / 256.0f) - mu * mu + 1e-5f);
    }
    #pragma unroll
    for (int mi = 0; mi < 2; mi++) {
        const int r = bm + wm + mi * 16 + r_lo;
        #pragma unroll
        for (int j = 0; j < 4; j++) {
            const int cl = wn + j * 8 + wv * 2;
            float gg0 = lng[cl], gg1 = lng[cl + 1];
            float bb0 = lnb[cl], bb1 = lnb[cl + 1];
            float mu0 = mus[mi * 2], ri0 = rinvs[mi * 2];
            float mu1 = mus[mi * 2 + 1], ri1 = rinvs[mi * 2 + 1];
            *(__half2*)(lnout + (size_t)r * 256 + cl) =
                __floats2half2_rn((acc[mi][j][0] - mu0) * ri0 * gg0 + bb0,
                                  (acc[mi][j][1] - mu0) * ri0 * gg1 + bb1);
            *(__half2*)(lnout + (size_t)(r + 8) * 256 + cl) =
                __floats2half2_rn((acc[mi][j][2] - mu1) * ri1 * gg0 + bb0,
                                  (acc[mi][j][3] - mu1) * ri1 * gg1 + bb1);
        }
    }
}

template<int SCALE, int NMAX>
__global__ void attn_kernel(const __half* __restrict__ QKV, __half* __restrict__ O,
                            int MBc, int rowoff) {
    __shared__ float Ks[NMAX][32];
    __shared__ float Vs[NMAX][32];
    int bt = blockIdx.x, head = blockIdx.y;
    int t = bt & (LSEQ - 1);
    int b = bt >> 7;
    int n = nfun<SCALE>(t);
    int rb = rowoff + b * MBc + Sfun<SCALE>(t);
    size_t base = (size_t)rb * 768 + head * DHEAD;

    for (int i = threadIdx.x; i < NMAX * 16; i += blockDim.x) {
        int kk = i >> 4, d = (i & 15) << 1;
        float2 kv = make_float2(0.f, 0.f), vv = make_float2(0.f, 0.f);
        if (kk < n) {
            kv = __half22float2(*(const __half2*)(QKV + base + (size_t)kk * 768 + 256 + d));
            vv = __half22float2(*(const __half2*)(QKV + base + (size_t)kk * 768 + 512 + d));
        }
        Ks[kk][d] = kv.x; Ks[kk][d + 1] = kv.y;
        Vs[kk][d] = vv.x; Vs[kk][d + 1] = vv.y;
    }
    __syncthreads();

    int tq = threadIdx.x;
    if (tq < n) {
        float qr[32];
        #pragma unroll
        for (int d = 0; d < 32; d += 2) {
            float2 qv = __half22float2(*(const __half2*)(QKV + base + (size_t)tq * 768 + d));
            qr[d] = qv.x; qr[d + 1] = qv.y;
        }
        float sc[NMAX];
        float mx = -1e30f;
        #pragma unroll
        for (int kk = 0; kk < NMAX; kk++) {
            float s = 0.0f;
            #pragma unroll
            for (int d = 0; d < 32; d++) s += qr[d] * Ks[kk][d];
            s *= 0.17677669529663687f;
            sc[kk] = (kk < n) ? s : -1e30f;
            mx = fmaxf(mx, sc[kk]);
        }
        float ssum = 0.0f;
        #pragma unroll
        for (int kk = 0; kk < NMAX; kk++) {
            float e = (kk < n) ? expf(sc[kk] - mx) : 0.0f;
            sc[kk] = e;
            ssum += e;
        }
        float inv = 1.0f / ssum;
        __half* op = O + (size_t)(rb + tq) * HID + head * DHEAD;
        #pragma unroll
        for (int d = 0; d < 32; d += 2) {
            float o0 = 0.0f, o1 = 0.0f;
            #pragma unroll
            for (int kk = 0; kk < NMAX; kk++) {
                o0 += sc[kk] * Vs[kk][d];
                o1 += sc[kk] * Vs[kk][d + 1];
            }
            *(__half2*)(op + d) = __floats2half2_rn(o0 * inv, o1 * inv);
        }
    }
}

static inline void gemm(const __half* A, const __half* WT, const float* bias, void* C,
                        int Mp, int N, int K, int epi) {
    dim3 grid(N >> 8, Mp >> 7), block(512);
    if (epi == 0)      hgemm_kernel<0><<<grid, block, HSMEM>>>(A, WT, bias, C, N, K);
    else if (epi == 1) hgemm_kernel<1><<<grid, block, HSMEM>>>(A, WT, bias, C, N, K);
    else               hgemm_kernel<4><<<grid, block, HSMEM>>>(A, WT, bias, C, N, K);
}
static inline void gemm64(const __half* A, const __half* WT, const float* bias, float* C,
                          int Mp, int K, int epi,
                          const float* lng = nullptr, const float* lnb = nullptr,
                          __half* lnout = nullptr) {
    dim3 grid(1, Mp >> 6), block(512);
    if (epi == 2) hgemm64_kernel<2><<<grid, block, H64SMEM>>>(A, WT, bias, C, K, lng, lnb, lnout);
    else          hgemm64_kernel<3><<<grid, block, H64SMEM>>>(A, WT, bias, C, K, lng, lnb, lnout);
}

extern "C" void kernel_launch(void* const* d_in, const int* in_sizes, int n_in,
                              void* d_out, int out_size) {
    cudaFuncSetAttribute(hgemm_kernel<0>, cudaFuncAttributeMaxDynamicSharedMemorySize, HSMEM);
    cudaFuncSetAttribute(hgemm_kernel<1>, cudaFuncAttributeMaxDynamicSharedMemorySize, HSMEM);
    cudaFuncSetAttribute(hgemm_kernel<4>, cudaFuncAttributeMaxDynamicSharedMemorySize, HSMEM);
    cudaFuncSetAttribute(hgemm64_kernel<2>, cudaFuncAttributeMaxDynamicSharedMemorySize, H64SMEM);
    cudaFuncSetAttribute(hgemm64_kernel<3>, cudaFuncAttributeMaxDynamicSharedMemorySize, H64SMEM);

    const float* x       = (const float*)d_in[0];
    const float* w_proj[2] = { (const float*)d_in[1], (const float*)d_in[3] };
    const float* b_proj[2] = { (const float*)d_in[2], (const float*)d_in[4] };
    const float* pos[2]    = { (const float*)d_in[5], (const float*)d_in[6] };
    const float* ln1_g = (const float*)d_in[7];
    const float* ln1_b = (const float*)d_in[8];
    const float* wq = (const float*)d_in[9];
    const float* bq = (const float*)d_in[10];
    const float* wk = (const float*)d_in[11];
    const float* bk = (const float*)d_in[12];
    const float* wv = (const float*)d_in[13];
    const float* bv = (const float*)d_in[14];
    const float* wo = (const float*)d_in[15];
    const float* bo = (const float*)d_in[16];
    const float* ln2_g = (const float*)d_in[17];
    const float* ln2_b = (const float*)d_in[18];
    const float* w_ff1 = (const float*)d_in[19];
    const float* b_ff1 = (const float*)d_in[20];
    const float* w_ff2 = (const float*)d_in[21];
    const float* b_ff2 = (const float*)d_in[22];
    const float* ln_g = (const float*)d_in[23];
    const float* ln_b = (const float*)d_in[24];
    const float* w_fus1 = (const float*)d_in[25];
    const float* b_fus1 = (const float*)d_in[26];
    const float* w_fus2 = (const float*)d_in[27];
    const float* b_fus2 = (const float*)d_in[28];

    __half *winh, *qkvh, *s2h, *ffh, *combh, *wth;
    float *tokens, *seq, *bqkv;
    cudaGetSymbolAddress((void**)&winh,   g_winh);
    cudaGetSymbolAddress((void**)&tokens, g_tokens);
    cudaGetSymbolAddress((void**)&seq,    g_seq);
    cudaGetSymbolAddress((void**)&qkvh,   g_qkvh);
    cudaGetSymbolAddress((void**)&s2h,    g_s2h);
    cudaGetSymbolAddress((void**)&ffh,    g_ffh);
    cudaGetSymbolAddress((void**)&combh,  g_combh);
    cudaGetSymbolAddress((void**)&wth,    g_wth);
    cudaGetSymbolAddress((void**)&bqkv,   g_bqkv);

    __half* wt_proj0 = wth;
    __half* wt_proj1 = wth + 16384;
    __half* wt_qkv   = wth + 49152;
    __half* wt_o     = wth + 442368;
    __half* wt_ff1   = wth + 573440;
    __half* wt_ff2   = wth + 1097728;
    __half* wt_fus1  = wth + 1622016;
    __half* wt_fus2  = wth + 1753088;

    WtJobs jobs;
    int nt = 0, nj = 0;
    auto addjob = [&](const float* src, __half* dst, int K, int N) {
        jobs.src[nj] = src; jobs.dst[nj] = dst; jobs.K[nj] = K; jobs.N[nj] = N;
        jobs.t0[nj] = nt; nt += (N / 32) * (K / 32); nj++;
    };
    addjob(w_proj[0], wt_proj0, 64, 256);
    addjob(w_proj[1], wt_proj1, 128, 256);
    for (int li = 0; li < 2; li++) {
        addjob(wq + li * 65536, wt_qkv + li * 196608,          256, 256);
        addjob(wk + li * 65536, wt_qkv + li * 196608 + 65536,  256, 256);
        addjob(wv + li * 65536, wt_qkv + li * 196608 + 131072, 256, 256);
        addjob(wo + li * 65536, wt_o + li * 65536, 256, 256);
        addjob(w_ff1 + li * 262144, wt_ff1 + li * 262144, 256, 1024);
        addjob(w_ff2 + li * 262144, wt_ff2 + li * 262144, 1024, 256);
    }
    addjob(w_fus1, wt_fus1, 512, 256);
    addjob(w_fus2, wt_fus2, 256, 256);
    wt_fused<<<nt, 256>>>(jobs, nj);
    for (int li = 0; li < 2; li++) {
        cudaMemcpyAsync(bqkv + li * 768,       bq + li * 256, 1024, cudaMemcpyDeviceToDevice);
        cudaMemcpyAsync(bqkv + li * 768 + 256, bk + li * 256, 1024, cudaMemcpyDeviceToDevice);
        cudaMemcpyAsync(bqkv + li * 768 + 512, bv + li * 256, 1024, cudaMemcpyDeviceToDevice);
    }

    const int PL[2] = {8, 16}, ST[2] = {4, 8}, EE[2] = {136, 128}, NMX[2] = {34, 16};
    const int MP[2] = {1152, 1024};
    const int MBB[2] = {MB0, MB1}, ROFF[2] = {0, MC0};

    for (int s = 0; s < 2; s++) {
        int pl = PL[s], st = ST[s], E = EE[s], NMAX = NMX[s];
        int plc = pl * CH;
        int BE = BATCH * E;
        { int tot = BE * plc;
          win_kernel<<<(tot + 255) / 256, 256>>>(x, winh, E, pl); }
        gemm(winh, s == 0 ? wt_proj0 : wt_proj1, b_proj[s], tokens, MP[s], HID, plc, 0);
        { int nwarp = NSEQ * NMAX;
          int blocks = (nwarp + 7) / 8;
          if (s == 0) build_seq_ln<0><<<blocks, 256>>>(tokens, pos[s], ln1_g, ln1_b,
                                                       seq, s2h, NMAX, E, pl, st, MBB[s], ROFF[s]);
          else        build_seq_ln<1><<<blocks, 256>>>(tokens, pos[s], ln1_g, ln1_b,
                                                       seq, s2h, NMAX, E, pl, st, MBB[s], ROFF[s]);
        }
    }

    for (int li = 0; li < 2; li++) {
        gemm(s2h, wt_qkv + li * 196608, bqkv + li * 768, qkvh, MTOT, 768, HID, 4);
        dim3 ag(NSEQ, NHEAD);
        attn_kernel<0, 34><<<ag, 64>>>(qkvh, s2h, MB0, 0);
        attn_kernel<1, 16><<<ag, 64>>>(qkvh, s2h, MB1, MC0);
        gemm64(s2h, wt_o + li * 65536, bo + li * HID, seq, MTOT, HID, 3,
               ln2_g + li * HID, ln2_b + li * HID, s2h);
        gemm(s2h, wt_ff1 + li * 262144, b_ff1 + li * FFD, ffh, MTOT, FFD, HID, 1);
        if (li == 0)
            gemm64(ffh, wt_ff2 + li * 262144, b_ff2 + li * HID, seq, MTOT, FFD, 3,
                   ln1_g + HID, ln1_b + HID, s2h);
        else
            gemm64(ffh, wt_ff2 + li * 262144, b_ff2 + li * HID, seq, MTOT, FFD, 2);
    }

    { int tot = NSEQ * HID;
      int blocks = (tot + 255) / 256;
      gather_kernel<0><<<blocks, 256>>>(seq, combh, 0, MB0, 0);
      gather_kernel<1><<<blocks, 256>>>(seq, combh, 256, MB1, MC0);
    }
    gemm(combh, wt_fus1, b_fus1, s2h, NSEQ, HID, 2 * HID, 1);
    gemm(s2h, wt_fus2, b_fus2, seq, NSEQ, HID, HID, 0);
    ln_final<<<NSEQ / 8, 256>>>(seq, ln_g, ln_b, (float*)d_out);
}